// round 7
// baseline (speedup 1.0000x reference)
#include <cuda_runtime.h>
#include <math.h>

// Problem constants
#define Bq   4
#define Nq   1024
#define Cq   512
#define Hq   8
#define HDq  64
#define BHq  32
#define Mq   4096
#define SCALEq 0.125f
#define LN_EPSq 1e-5f

typedef unsigned long long u64;
typedef ulonglong2 u64x2;

// packed fp32x2 FMA (sm_103a). ptxas never emits this from C++.
__device__ __forceinline__ u64 f2fma(u64 a, u64 b, u64 c) {
    u64 d;
    asm("fma.rn.f32x2 %0, %1, %2, %3;" : "=l"(d) : "l"(a), "l"(b), "l"(c));
    return d;
}
__device__ __forceinline__ float2 upk(u64 v) {
    float2 r;
    asm("mov.b64 {%0, %1}, %2;" : "=f"(r.x), "=f"(r.y) : "l"(v));
    return r;
}
__device__ __forceinline__ u64 dup2(float x) {
    u64 r;
    asm("mov.b64 %0, {%1, %1};" : "=l"(r) : "f"(x));
    return r;
}

// Scratch (device globals — allocation-free)
__device__ float g_q  [BHq * Nq * HDq];     // [bh][n][d]
__device__ float g_k  [BHq * Nq * HDq];
__device__ float g_v  [BHq * Nq * HDq];
__device__ float g_aoP[4 * Mq * Cq];        // 4 k-split partials of attn-out
__device__ float g_yp [Mq * Cq];            // pre-layernorm y

// ---------------------------------------------------------------------------
// Kernel 1: QKV GEMM. x[4096,512] @ Wqkv[512,1536] + bqkv -> scatter q/k/v
// 64x128 tiles, K-slab 16, 256 threads, 4x8/thread, double-buffered, FFMA2.
// Grid (12, 64) = 768 blocks for high occupancy.
// ---------------------------------------------------------------------------
__global__ __launch_bounds__(256) void k_qkv(const float* __restrict__ A,
                                             const float* __restrict__ Bm,
                                             const float* __restrict__ bias) {
    const int K = 512, Nn = 1536;
    __shared__ float As[2][16][68];    // transposed [k][row]
    __shared__ float Bs[2][16][128];   // natural [k][col]
    int tid = threadIdx.x;
    int bx = blockIdx.x, by = blockIdx.y;
    int aRow = tid >> 2, aCol = (tid & 3) << 2;
    int bRow = tid >> 4, bCol = (tid & 15) << 3;
    int ty = tid >> 4, tx = tid & 15;   // rows ty*4..+3, cols tx*8..+7

    u64 acc[4][4];
#pragma unroll
    for (int i = 0; i < 4; i++)
#pragma unroll
        for (int j = 0; j < 4; j++) acc[i][j] = 0ULL;

    const float* Ap = A + (size_t)(by * 64 + aRow) * K + aCol;
    const float* Bp = Bm + (size_t)bRow * Nn + bx * 128 + bCol;

    {
        float4 av = *(const float4*)(Ap);
        As[0][aCol + 0][aRow] = av.x;
        As[0][aCol + 1][aRow] = av.y;
        As[0][aCol + 2][aRow] = av.z;
        As[0][aCol + 3][aRow] = av.w;
        *(float4*)&Bs[0][bRow][bCol] = *(const float4*)(Bp);
        *(float4*)&Bs[0][bRow][bCol + 4] = *(const float4*)(Bp + 4);
    }
    __syncthreads();

    for (int k0 = 0; k0 < K; k0 += 16) {
        int buf = (k0 >> 4) & 1;
        float4 av, bv0, bv1;
        bool more = (k0 + 16) < K;
        if (more) {
            av  = *(const float4*)(Ap + k0 + 16);
            bv0 = *(const float4*)(Bp + (size_t)(k0 + 16) * Nn);
            bv1 = *(const float4*)(Bp + (size_t)(k0 + 16) * Nn + 4);
        }
#pragma unroll
        for (int k = 0; k < 16; k++) {
            float4 a = *(const float4*)&As[buf][k][ty * 4];
            u64x2 b0 = *(const u64x2*)&Bs[buf][k][tx * 8];
            u64x2 b1 = *(const u64x2*)&Bs[buf][k][tx * 8 + 4];
            u64 ad[4] = {dup2(a.x), dup2(a.y), dup2(a.z), dup2(a.w)};
            u64 bp[4] = {b0.x, b0.y, b1.x, b1.y};
#pragma unroll
            for (int i = 0; i < 4; i++)
#pragma unroll
                for (int j = 0; j < 4; j++) acc[i][j] = f2fma(ad[i], bp[j], acc[i][j]);
        }
        if (more) {
            int nb = buf ^ 1;
            As[nb][aCol + 0][aRow] = av.x;
            As[nb][aCol + 1][aRow] = av.y;
            As[nb][aCol + 2][aRow] = av.z;
            As[nb][aCol + 3][aRow] = av.w;
            *(float4*)&Bs[nb][bRow][bCol] = bv0;
            *(float4*)&Bs[nb][bRow][bCol + 4] = bv1;
        }
        __syncthreads();
    }

    // epilogue: scatter into q/k/v [bh][n][d]
#pragma unroll
    for (int i = 0; i < 4; i++) {
        int r = by * 64 + ty * 4 + i;
        int bb = r >> 10, n = r & 1023;
#pragma unroll
        for (int jp = 0; jp < 4; jp++) {
            float2 v2 = upk(acc[i][jp]);
            float vv[2] = {v2.x, v2.y};
#pragma unroll
            for (int l = 0; l < 2; l++) {
                int c = bx * 128 + tx * 8 + jp * 2 + l;
                float v = vv[l] + bias[c];
                int sel = c >> 9;
                int rem = c & 511;
                int h = rem >> 6, d = rem & 63;
                float* dst = (sel == 0) ? g_q : ((sel == 1) ? g_k : g_v);
                dst[((bb * 8 + h) * 1024 + n) * 64 + d] = v;
            }
        }
    }
}

// ---------------------------------------------------------------------------
// Kernel 2: scores. S = poly(ow; q·k^T*SCALE) pre-softmax into attn.
// 128x128 tile per block per bh, 256 threads, 8x8/thread, FFMA2 inner.
// ---------------------------------------------------------------------------
#define QKSTR 132
__global__ __launch_bounds__(256) void k_scores(const float* __restrict__ ow_in,
                                                float* __restrict__ attn) {
    extern __shared__ float sm[];
    float* Qt = sm;                // [d][row]
    float* Kt = sm + 64 * QKSTR;   // [d][col]
    int bh = blockIdx.z;
    int mb = blockIdx.y * 128;
    int nb = blockIdx.x * 128;
    int tid = threadIdx.x;

    {
        int row = tid >> 1;
        int d0 = (tid & 1) << 5;
        const float* qp = g_q + (size_t)(bh * 1024 + mb + row) * 64 + d0;
        const float* kp = g_k + (size_t)(bh * 1024 + nb + row) * 64 + d0;
#pragma unroll
        for (int m = 0; m < 8; m++) {
            int d = d0 + m * 4;
            float4 qv = *(const float4*)(qp + m * 4);
            Qt[(d + 0) * QKSTR + row] = qv.x;
            Qt[(d + 1) * QKSTR + row] = qv.y;
            Qt[(d + 2) * QKSTR + row] = qv.z;
            Qt[(d + 3) * QKSTR + row] = qv.w;
            float4 kv = *(const float4*)(kp + m * 4);
            Kt[(d + 0) * QKSTR + row] = kv.x;
            Kt[(d + 1) * QKSTR + row] = kv.y;
            Kt[(d + 2) * QKSTR + row] = kv.z;
            Kt[(d + 3) * QKSTR + row] = kv.w;
        }
    }
    __syncthreads();

    int ty = tid >> 4, tx = tid & 15;
    u64 acc[8][4];
#pragma unroll
    for (int i = 0; i < 8; i++)
#pragma unroll
        for (int j = 0; j < 4; j++) acc[i][j] = 0ULL;

#pragma unroll 8
    for (int d = 0; d < 64; d++) {
        float a[8];
        *(float4*)&a[0] = *(const float4*)(Qt + d * QKSTR + ty * 8);
        *(float4*)&a[4] = *(const float4*)(Qt + d * QKSTR + ty * 8 + 4);
        u64x2 b0 = *(const u64x2*)(Kt + d * QKSTR + tx * 8);
        u64x2 b1 = *(const u64x2*)(Kt + d * QKSTR + tx * 8 + 4);
        u64 bp[4] = {b0.x, b0.y, b1.x, b1.y};
#pragma unroll
        for (int i = 0; i < 8; i++) {
            u64 ad = dup2(a[i]);
#pragma unroll
            for (int j = 0; j < 4; j++) acc[i][j] = f2fma(ad, bp[j], acc[i][j]);
        }
    }

    float w0 = ow_in[0], w1 = ow_in[1], w2 = ow_in[2];
    float mw = fmaxf(w0, fmaxf(w1, w2));
    float e0 = __expf(w0 - mw), e1 = __expf(w1 - mw), e2 = __expf(w2 - mw);
    float inv = 1.f / (e0 + e1 + e2);
    w0 = e0 * inv; w1 = e1 * inv; w2 = e2 * inv;

#pragma unroll
    for (int i = 0; i < 8; i++) {
        int row = bh * 1024 + mb + ty * 8 + i;
        float o[8];
#pragma unroll
        for (int jp = 0; jp < 4; jp++) {
            float2 v2 = upk(acc[i][jp]);
            float s;
            s = v2.x * SCALEq; o[jp * 2 + 0] = s * (w0 + s * (w1 + s * w2));
            s = v2.y * SCALEq; o[jp * 2 + 1] = s * (w0 + s * (w1 + s * w2));
        }
        float* dst = attn + (size_t)row * 1024 + nb + tx * 8;
        *(float4*)dst = *(float4*)&o[0];
        *(float4*)(dst + 4) = *(float4*)&o[4];
    }
}

// ---------------------------------------------------------------------------
// Kernel 3: row softmax in place on attn [32768 rows x 1024].
// ---------------------------------------------------------------------------
__global__ __launch_bounds__(256) void k_softmax(float* __restrict__ attn) {
    __shared__ float red[8];
    int row = blockIdx.x;
    int tid = threadIdx.x;
    float* p = attn + (size_t)row * 1024;
    float4 v = *(const float4*)(p + tid * 4);

    float m = fmaxf(fmaxf(v.x, v.y), fmaxf(v.z, v.w));
#pragma unroll
    for (int o = 16; o; o >>= 1) m = fmaxf(m, __shfl_xor_sync(0xffffffffu, m, o));
    int wid = tid >> 5, lane = tid & 31;
    if (lane == 0) red[wid] = m;
    __syncthreads();
    if (tid == 0) {
        float mm = red[0];
#pragma unroll
        for (int i = 1; i < 8; i++) mm = fmaxf(mm, red[i]);
        red[0] = mm;
    }
    __syncthreads();
    m = red[0];
    __syncthreads();

    float4 e;
    e.x = __expf(v.x - m); e.y = __expf(v.y - m);
    e.z = __expf(v.z - m); e.w = __expf(v.w - m);
    float s = e.x + e.y + e.z + e.w;
#pragma unroll
    for (int o = 16; o; o >>= 1) s += __shfl_xor_sync(0xffffffffu, s, o);
    if (lane == 0) red[wid] = s;
    __syncthreads();
    if (tid == 0) {
        float ss = 0.f;
#pragma unroll
        for (int i = 0; i < 8; i++) ss += red[i];
        red[0] = ss;
    }
    __syncthreads();
    float invs = 1.f / red[0];

    e.x *= invs; e.y *= invs; e.z *= invs; e.w *= invs;
    *(float4*)(p + tid * 4) = e;
}

// ---------------------------------------------------------------------------
// Kernel 4: partial AV. Per (b,h,z): [128,256]@[256,64] -> g_aoP[z].
// 256 threads, 128x64 tile, FFMA2 with free row-pairs from transposed tile.
// ---------------------------------------------------------------------------
#define ATSTR 132
#define VSTR2 68
__global__ __launch_bounds__(256) void k_av(const float* __restrict__ attn) {
    extern __shared__ float sm[];
    float* At = sm;                 // [k 0..63][row 0..127] transposed
    float* Vs = sm + 64 * ATSTR;    // [k][d]
    int mb = blockIdx.x * 128;
    int bh = blockIdx.y;
    int kz = blockIdx.z << 8;       // z * 256
    int tid = threadIdx.x;
    int ty = tid >> 4, tx = tid & 15;

    u64 acc[4][4];
#pragma unroll
    for (int i = 0; i < 4; i++)
#pragma unroll
        for (int j = 0; j < 4; j++) acc[i][j] = 0ULL;

    for (int k0 = 0; k0 < 256; k0 += 64) {
        {   // fill At transposed: At[k][row]
            int row = tid >> 1;
            int c0 = (tid & 1) << 5;
            const float* ap = attn + (size_t)(bh * 1024 + mb + row) * 1024 + kz + k0 + c0;
#pragma unroll
            for (int m = 0; m < 8; m++) {
                float4 av = *(const float4*)(ap + m * 4);
                int kk = c0 + m * 4;
                At[(kk + 0) * ATSTR + row] = av.x;
                At[(kk + 1) * ATSTR + row] = av.y;
                At[(kk + 2) * ATSTR + row] = av.z;
                At[(kk + 3) * ATSTR + row] = av.w;
            }
        }
        {   // fill Vs natural: Vs[k][d]
            int vr = tid >> 2;
            int d0 = (tid & 3) << 4;
            const float* vp = g_v + (size_t)(bh * 1024 + kz + k0 + vr) * 64 + d0;
            float* vd = Vs + vr * VSTR2 + d0;
#pragma unroll
            for (int m = 0; m < 4; m++)
                *(float4*)(vd + m * 4) = *(const float4*)(vp + m * 4);
        }
        __syncthreads();

#pragma unroll 8
        for (int kk = 0; kk < 64; kk++) {
            u64x2 a01 = *(const u64x2*)(At + kk * ATSTR + ty * 8);      // rows 0-3
            u64x2 a23 = *(const u64x2*)(At + kk * ATSTR + ty * 8 + 4);  // rows 4-7
            float4 bf = *(const float4*)(Vs + kk * VSTR2 + tx * 4);
            u64 ap4[4] = {a01.x, a01.y, a23.x, a23.y};
            u64 bp4[4] = {dup2(bf.x), dup2(bf.y), dup2(bf.z), dup2(bf.w)};
#pragma unroll
            for (int i = 0; i < 4; i++)
#pragma unroll
                for (int j = 0; j < 4; j++) acc[i][j] = f2fma(ap4[i], bp4[j], acc[i][j]);
        }
        __syncthreads();
    }

    int b = bh >> 3, h = bh & 7;
    float* base = g_aoP + (size_t)blockIdx.z * (Mq * Cq);
#pragma unroll
    for (int p = 0; p < 4; p++) {
        float2 v0 = upk(acc[p][0]);
        float2 v1 = upk(acc[p][1]);
        float2 v2 = upk(acc[p][2]);
        float2 v3 = upk(acc[p][3]);
        float4 lo = {v0.x, v1.x, v2.x, v3.x};   // row 2p
        float4 hi = {v0.y, v1.y, v2.y, v3.y};   // row 2p+1
        int n0 = mb + ty * 8 + 2 * p;
        *(float4*)(base + (size_t)(b * 1024 + n0) * 512 + h * 64 + tx * 4) = lo;
        *(float4*)(base + (size_t)(b * 1024 + n0 + 1) * 512 + h * 64 + tx * 4) = hi;
    }
}

// ---------------------------------------------------------------------------
// Kernel 5: proj GEMM + bias + residual. A = sum of 4 g_aoP partials.
// 64x128 tiles, K-slab 16, 256 threads, 4x8/thread, double-buffered, FFMA2.
// Grid (4, 64) = 256 blocks.
// ---------------------------------------------------------------------------
__global__ __launch_bounds__(256) void k_proj(const float* __restrict__ x,
                                              const float* __restrict__ Bm,
                                              const float* __restrict__ bias) {
    const int K = 512, Nn = 512;
    const int P = Mq * Cq;
    __shared__ float As[2][16][68];
    __shared__ float Bs[2][16][128];
    int tid = threadIdx.x;
    int bx = blockIdx.x, by = blockIdx.y;
    int aRow = tid >> 2, aCol = (tid & 3) << 2;
    int bRow = tid >> 4, bCol = (tid & 15) << 3;
    int ty = tid >> 4, tx = tid & 15;

    u64 acc[4][4];
#pragma unroll
    for (int i = 0; i < 4; i++)
#pragma unroll
        for (int j = 0; j < 4; j++) acc[i][j] = 0ULL;

    const float* Ap = g_aoP + (size_t)(by * 64 + aRow) * K + aCol;
    const float* Bp = Bm + (size_t)bRow * Nn + bx * 128 + bCol;

    {
        float4 a0 = *(const float4*)(Ap);
        float4 a1 = *(const float4*)(Ap + P);
        float4 a2 = *(const float4*)(Ap + 2 * P);
        float4 a3 = *(const float4*)(Ap + 3 * P);
        As[0][aCol + 0][aRow] = a0.x + a1.x + a2.x + a3.x;
        As[0][aCol + 1][aRow] = a0.y + a1.y + a2.y + a3.y;
        As[0][aCol + 2][aRow] = a0.z + a1.z + a2.z + a3.z;
        As[0][aCol + 3][aRow] = a0.w + a1.w + a2.w + a3.w;
        *(float4*)&Bs[0][bRow][bCol] = *(const float4*)(Bp);
        *(float4*)&Bs[0][bRow][bCol + 4] = *(const float4*)(Bp + 4);
    }
    __syncthreads();

    for (int k0 = 0; k0 < K; k0 += 16) {
        int buf = (k0 >> 4) & 1;
        float4 av, bv0, bv1;
        bool more = (k0 + 16) < K;
        if (more) {
            float4 a0 = *(const float4*)(Ap + k0 + 16);
            float4 a1 = *(const float4*)(Ap + P + k0 + 16);
            float4 a2 = *(const float4*)(Ap + 2 * P + k0 + 16);
            float4 a3 = *(const float4*)(Ap + 3 * P + k0 + 16);
            av.x = a0.x + a1.x + a2.x + a3.x;
            av.y = a0.y + a1.y + a2.y + a3.y;
            av.z = a0.z + a1.z + a2.z + a3.z;
            av.w = a0.w + a1.w + a2.w + a3.w;
            bv0 = *(const float4*)(Bp + (size_t)(k0 + 16) * Nn);
            bv1 = *(const float4*)(Bp + (size_t)(k0 + 16) * Nn + 4);
        }
#pragma unroll
        for (int k = 0; k < 16; k++) {
            float4 a = *(const float4*)&As[buf][k][ty * 4];
            u64x2 b0 = *(const u64x2*)&Bs[buf][k][tx * 8];
            u64x2 b1 = *(const u64x2*)&Bs[buf][k][tx * 8 + 4];
            u64 ad[4] = {dup2(a.x), dup2(a.y), dup2(a.z), dup2(a.w)};
            u64 bp[4] = {b0.x, b0.y, b1.x, b1.y};
#pragma unroll
            for (int i = 0; i < 4; i++)
#pragma unroll
                for (int j = 0; j < 4; j++) acc[i][j] = f2fma(ad[i], bp[j], acc[i][j]);
        }
        if (more) {
            int nb2 = buf ^ 1;
            As[nb2][aCol + 0][aRow] = av.x;
            As[nb2][aCol + 1][aRow] = av.y;
            As[nb2][aCol + 2][aRow] = av.z;
            As[nb2][aCol + 3][aRow] = av.w;
            *(float4*)&Bs[nb2][bRow][bCol] = bv0;
            *(float4*)&Bs[nb2][bRow][bCol + 4] = bv1;
        }
        __syncthreads();
    }

#pragma unroll
    for (int i = 0; i < 4; i++) {
        int r = by * 64 + ty * 4 + i;
#pragma unroll
        for (int jp = 0; jp < 4; jp++) {
            float2 v2 = upk(acc[i][jp]);
            int c = bx * 128 + tx * 8 + jp * 2;
            g_yp[(size_t)r * 512 + c]     = v2.x + bias[c]     + x[(size_t)r * 512 + c];
            g_yp[(size_t)r * 512 + c + 1] = v2.y + bias[c + 1] + x[(size_t)r * 512 + c + 1];
        }
    }
}

// ---------------------------------------------------------------------------
// Kernel 6: LayerNorm over last dim (512), write y to d_out.
// ---------------------------------------------------------------------------
__global__ __launch_bounds__(128) void k_ln(const float* __restrict__ gamma,
                                            const float* __restrict__ beta,
                                            float* __restrict__ y) {
    __shared__ float s1[4], s2[4];
    int row = blockIdx.x;
    int tid = threadIdx.x;
    const float* p = g_yp + (size_t)row * 512;
    float4 v = *(const float4*)(p + tid * 4);

    float s = v.x + v.y + v.z + v.w;
    float ss = v.x * v.x + v.y * v.y + v.z * v.z + v.w * v.w;
#pragma unroll
    for (int o = 16; o; o >>= 1) {
        s += __shfl_xor_sync(0xffffffffu, s, o);
        ss += __shfl_xor_sync(0xffffffffu, ss, o);
    }
    int wid = tid >> 5, lane = tid & 31;
    if (lane == 0) { s1[wid] = s; s2[wid] = ss; }
    __syncthreads();
    if (tid == 0) {
        s1[0] = s1[0] + s1[1] + s1[2] + s1[3];
        s2[0] = s2[0] + s2[1] + s2[2] + s2[3];
    }
    __syncthreads();
    float mu = s1[0] * (1.f / 512.f);
    float var = s2[0] * (1.f / 512.f) - mu * mu;
    float rstd = rsqrtf(var + LN_EPSq);

    int c = tid * 4;
    float4 g = *(const float4*)(gamma + c);
    float4 be = *(const float4*)(beta + c);
    float4 o;
    o.x = (v.x - mu) * rstd * g.x + be.x;
    o.y = (v.y - mu) * rstd * g.y + be.y;
    o.z = (v.z - mu) * rstd * g.z + be.z;
    o.w = (v.w - mu) * rstd * g.w + be.w;
    *(float4*)(y + (size_t)row * 512 + c) = o;
}

// ---------------------------------------------------------------------------
extern "C" void kernel_launch(void* const* d_in, const int* in_sizes, int n_in,
                              void* d_out, int out_size) {
    (void)in_sizes; (void)n_in; (void)out_size;
    const float* x     = (const float*)d_in[0];
    const float* Wqkv  = (const float*)d_in[1];
    const float* bqkv  = (const float*)d_in[2];
    const float* ow    = (const float*)d_in[3];
    const float* Wproj = (const float*)d_in[4];
    const float* bproj = (const float*)d_in[5];
    const float* gamma = (const float*)d_in[6];
    const float* beta  = (const float*)d_in[7];

    float* out      = (float*)d_out;
    float* y_out    = out;                         // [4,1024,512]
    float* attn_out = out + (size_t)Bq * Nq * Cq;  // [4,8,1024,1024]

    int scores_smem = 2 * 64 * QKSTR * (int)sizeof(float);            // 67584 B
    int av_smem     = (64 * ATSTR + 64 * VSTR2) * (int)sizeof(float); // 51200 B
    cudaFuncSetAttribute(k_scores, cudaFuncAttributeMaxDynamicSharedMemorySize,
                         scores_smem);
    cudaFuncSetAttribute(k_av, cudaFuncAttributeMaxDynamicSharedMemorySize,
                         av_smem);

    k_qkv    <<<dim3(12, 64), 256>>>(x, Wqkv, bqkv);
    k_scores <<<dim3(8, 8, 32), 256, scores_smem>>>(ow, attn_out);
    k_softmax<<<32768, 256>>>(attn_out);
    k_av     <<<dim3(8, 32, 4), 256, av_smem>>>(attn_out);
    k_proj   <<<dim3(4, 64), 256>>>(x, Wproj, bproj);
    k_ln     <<<4096, 128>>>(gamma, beta, y_out);
}

// round 9
// speedup vs baseline: 1.1342x; 1.1342x over previous
#include <cuda_runtime.h>
#include <math.h>

// Problem constants
#define Bq   4
#define Nq   1024
#define Cq   512
#define Hq   8
#define HDq  64
#define BHq  32
#define Mq   4096
#define SCALEq 0.125f
#define LN_EPSq 1e-5f

typedef unsigned long long u64;
typedef ulonglong2 u64x2;

// packed fp32x2 FMA (sm_103a). ptxas never emits this from C++.
__device__ __forceinline__ u64 f2fma(u64 a, u64 b, u64 c) {
    u64 d;
    asm("fma.rn.f32x2 %0, %1, %2, %3;" : "=l"(d) : "l"(a), "l"(b), "l"(c));
    return d;
}
__device__ __forceinline__ float2 upk(u64 v) {
    float2 r;
    asm("mov.b64 {%0, %1}, %2;" : "=f"(r.x), "=f"(r.y) : "l"(v));
    return r;
}
__device__ __forceinline__ u64 dup2(float x) {
    u64 r;
    asm("mov.b64 %0, {%1, %1};" : "=l"(r) : "f"(x));
    return r;
}

// Scratch (device globals — allocation-free)
__device__ float g_q  [BHq * Nq * HDq];     // [bh][n][d]
__device__ float g_k  [BHq * Nq * HDq];
__device__ float g_v  [BHq * Nq * HDq];
__device__ float g_aoP[4 * Mq * Cq];        // 4 k-split partials of attn-out
__device__ float g_yp [Mq * Cq];            // pre-layernorm y

// ---------------------------------------------------------------------------
// Kernel 1: QKV GEMM. x[4096,512] @ Wqkv[512,1536] + bqkv -> scatter q/k/v
// 128x128x8 tiles, 256 threads, 8x8/thread, double-buffered, FFMA2 inner.
// ---------------------------------------------------------------------------
__global__ __launch_bounds__(256) void k_qkv(const float* __restrict__ A,
                                             const float* __restrict__ Bm,
                                             const float* __restrict__ bias) {
    const int K = 512, Nn = 1536;
    __shared__ float As[2][8][128];
    __shared__ float Bs[2][8][128];
    int tid = threadIdx.x;
    int bx = blockIdx.x, by = blockIdx.y;
    int aRow = tid >> 1, aCol = (tid & 1) << 2;
    int bRow = tid >> 5, bCol = (tid & 31) << 2;
    int ty = tid >> 4, tx = tid & 15;

    u64 acc[8][4];
#pragma unroll
    for (int i = 0; i < 8; i++)
#pragma unroll
        for (int j = 0; j < 4; j++) acc[i][j] = 0ULL;

    const float* Ap = A + (size_t)(by * 128 + aRow) * K + aCol;
    const float* Bp = Bm + (size_t)bRow * Nn + bx * 128 + bCol;

    {
        float4 av = *(const float4*)(Ap);
        As[0][aCol + 0][aRow] = av.x;
        As[0][aCol + 1][aRow] = av.y;
        As[0][aCol + 2][aRow] = av.z;
        As[0][aCol + 3][aRow] = av.w;
        *(float4*)&Bs[0][bRow][bCol] = *(const float4*)(Bp);
    }
    __syncthreads();

    for (int k0 = 0; k0 < K; k0 += 8) {
        int buf = (k0 >> 3) & 1;
        float4 av, bv;
        bool more = (k0 + 8) < K;
        if (more) {
            av = *(const float4*)(Ap + k0 + 8);
            bv = *(const float4*)(Bp + (size_t)(k0 + 8) * Nn);
        }
#pragma unroll
        for (int k = 0; k < 8; k++) {
            float a[8];
            *(float4*)&a[0] = *(const float4*)&As[buf][k][ty * 8];
            *(float4*)&a[4] = *(const float4*)&As[buf][k][ty * 8 + 4];
            u64x2 b0 = *(const u64x2*)&Bs[buf][k][tx * 8];
            u64x2 b1 = *(const u64x2*)&Bs[buf][k][tx * 8 + 4];
            u64 bp[4] = {b0.x, b0.y, b1.x, b1.y};
#pragma unroll
            for (int i = 0; i < 8; i++) {
                u64 ad = dup2(a[i]);
#pragma unroll
                for (int j = 0; j < 4; j++) acc[i][j] = f2fma(ad, bp[j], acc[i][j]);
            }
        }
        if (more) {
            int nb = buf ^ 1;
            As[nb][aCol + 0][aRow] = av.x;
            As[nb][aCol + 1][aRow] = av.y;
            As[nb][aCol + 2][aRow] = av.z;
            As[nb][aCol + 3][aRow] = av.w;
            *(float4*)&Bs[nb][bRow][bCol] = bv;
        }
        __syncthreads();
    }

#pragma unroll
    for (int i = 0; i < 8; i++) {
        int r = by * 128 + ty * 8 + i;
        int bb = r >> 10, n = r & 1023;
#pragma unroll
        for (int jp = 0; jp < 4; jp++) {
            float2 v2 = upk(acc[i][jp]);
            float vv[2] = {v2.x, v2.y};
#pragma unroll
            for (int l = 0; l < 2; l++) {
                int c = bx * 128 + tx * 8 + jp * 2 + l;
                float v = vv[l] + bias[c];
                int sel = c >> 9;
                int rem = c & 511;
                int h = rem >> 6, d = rem & 63;
                float* dst = (sel == 0) ? g_q : ((sel == 1) ? g_k : g_v);
                dst[((bb * 8 + h) * 1024 + n) * 64 + d] = v;
            }
        }
    }
}

// ---------------------------------------------------------------------------
// Kernel 2: scores. S = poly(ow; q·k^T*SCALE) pre-softmax into attn.
// 128x128 tile per block per bh, 256 threads, 8x8/thread, FFMA2 inner.
// ---------------------------------------------------------------------------
#define QKSTR 132
__global__ __launch_bounds__(256) void k_scores(const float* __restrict__ ow_in,
                                                float* __restrict__ attn) {
    extern __shared__ float sm[];
    float* Qt = sm;                // [d][row]
    float* Kt = sm + 64 * QKSTR;   // [d][col]
    int bh = blockIdx.z;
    int mb = blockIdx.y * 128;
    int nb = blockIdx.x * 128;
    int tid = threadIdx.x;

    {
        int row = tid >> 1;
        int d0 = (tid & 1) << 5;
        const float* qp = g_q + (size_t)(bh * 1024 + mb + row) * 64 + d0;
        const float* kp = g_k + (size_t)(bh * 1024 + nb + row) * 64 + d0;
#pragma unroll
        for (int m = 0; m < 8; m++) {
            int d = d0 + m * 4;
            float4 qv = *(const float4*)(qp + m * 4);
            Qt[(d + 0) * QKSTR + row] = qv.x;
            Qt[(d + 1) * QKSTR + row] = qv.y;
            Qt[(d + 2) * QKSTR + row] = qv.z;
            Qt[(d + 3) * QKSTR + row] = qv.w;
            float4 kv = *(const float4*)(kp + m * 4);
            Kt[(d + 0) * QKSTR + row] = kv.x;
            Kt[(d + 1) * QKSTR + row] = kv.y;
            Kt[(d + 2) * QKSTR + row] = kv.z;
            Kt[(d + 3) * QKSTR + row] = kv.w;
        }
    }
    __syncthreads();

    int ty = tid >> 4, tx = tid & 15;
    u64 acc[8][4];
#pragma unroll
    for (int i = 0; i < 8; i++)
#pragma unroll
        for (int j = 0; j < 4; j++) acc[i][j] = 0ULL;

#pragma unroll 8
    for (int d = 0; d < 64; d++) {
        float a[8];
        *(float4*)&a[0] = *(const float4*)(Qt + d * QKSTR + ty * 8);
        *(float4*)&a[4] = *(const float4*)(Qt + d * QKSTR + ty * 8 + 4);
        u64x2 b0 = *(const u64x2*)(Kt + d * QKSTR + tx * 8);
        u64x2 b1 = *(const u64x2*)(Kt + d * QKSTR + tx * 8 + 4);
        u64 bp[4] = {b0.x, b0.y, b1.x, b1.y};
#pragma unroll
        for (int i = 0; i < 8; i++) {
            u64 ad = dup2(a[i]);
#pragma unroll
            for (int j = 0; j < 4; j++) acc[i][j] = f2fma(ad, bp[j], acc[i][j]);
        }
    }

    float w0 = ow_in[0], w1 = ow_in[1], w2 = ow_in[2];
    float mw = fmaxf(w0, fmaxf(w1, w2));
    float e0 = __expf(w0 - mw), e1 = __expf(w1 - mw), e2 = __expf(w2 - mw);
    float inv = 1.f / (e0 + e1 + e2);
    w0 = e0 * inv; w1 = e1 * inv; w2 = e2 * inv;

#pragma unroll
    for (int i = 0; i < 8; i++) {
        int row = bh * 1024 + mb + ty * 8 + i;
        float o[8];
#pragma unroll
        for (int jp = 0; jp < 4; jp++) {
            float2 v2 = upk(acc[i][jp]);
            float s;
            s = v2.x * SCALEq; o[jp * 2 + 0] = s * (w0 + s * (w1 + s * w2));
            s = v2.y * SCALEq; o[jp * 2 + 1] = s * (w0 + s * (w1 + s * w2));
        }
        float* dst = attn + (size_t)row * 1024 + nb + tx * 8;
        *(float4*)dst = *(float4*)&o[0];
        *(float4*)(dst + 4) = *(float4*)&o[4];
    }
}

// ---------------------------------------------------------------------------
// Kernel 3: row softmax in place on attn [32768 rows x 1024].
// ---------------------------------------------------------------------------
__global__ __launch_bounds__(256) void k_softmax(float* __restrict__ attn) {
    __shared__ float red[8];
    int row = blockIdx.x;
    int tid = threadIdx.x;
    float* p = attn + (size_t)row * 1024;
    float4 v = *(const float4*)(p + tid * 4);

    float m = fmaxf(fmaxf(v.x, v.y), fmaxf(v.z, v.w));
#pragma unroll
    for (int o = 16; o; o >>= 1) m = fmaxf(m, __shfl_xor_sync(0xffffffffu, m, o));
    int wid = tid >> 5, lane = tid & 31;
    if (lane == 0) red[wid] = m;
    __syncthreads();
    if (tid == 0) {
        float mm = red[0];
#pragma unroll
        for (int i = 1; i < 8; i++) mm = fmaxf(mm, red[i]);
        red[0] = mm;
    }
    __syncthreads();
    m = red[0];
    __syncthreads();

    float4 e;
    e.x = __expf(v.x - m); e.y = __expf(v.y - m);
    e.z = __expf(v.z - m); e.w = __expf(v.w - m);
    float s = e.x + e.y + e.z + e.w;
#pragma unroll
    for (int o = 16; o; o >>= 1) s += __shfl_xor_sync(0xffffffffu, s, o);
    if (lane == 0) red[wid] = s;
    __syncthreads();
    if (tid == 0) {
        float ss = 0.f;
#pragma unroll
        for (int i = 0; i < 8; i++) ss += red[i];
        red[0] = ss;
    }
    __syncthreads();
    float invs = 1.f / red[0];

    e.x *= invs; e.y *= invs; e.z *= invs; e.w *= invs;
    *(float4*)(p + tid * 4) = e;
}

// ---------------------------------------------------------------------------
// Kernel 4: partial AV. Per (b,h,z): [128,256]@[256,64] -> g_aoP[z].
// 128 threads, tile 128x64, 8 rows (4 FFMA2 pairs) x 8 cols per thread.
// LDS per kk: 16B a-pairs + 32B b = 48B per 64 MACs (0.75 B/MAC).
// ---------------------------------------------------------------------------
#define ATSTR 132
#define VSTR2 68
__global__ __launch_bounds__(128) void k_av(const float* __restrict__ attn) {
    extern __shared__ float sm[];
    float* At = sm;                 // [k 0..63][row 0..127] transposed
    float* Vs = sm + 64 * ATSTR;    // [k][d]
    int mb = blockIdx.x * 128;
    int bh = blockIdx.y;
    int kz = blockIdx.z << 8;       // z * 256
    int tid = threadIdx.x;
    int ty = tid >> 3;              // 0..15 -> rows ty*8..+7
    int tx = tid & 7;               // cols tx*8..+7

    u64 acc[4][8];
#pragma unroll
    for (int i = 0; i < 4; i++)
#pragma unroll
        for (int j = 0; j < 8; j++) acc[i][j] = 0ULL;

    for (int k0 = 0; k0 < 256; k0 += 64) {
        // fill At transposed: At[k][row] (two passes of 64 rows)
#pragma unroll
        for (int p = 0; p < 2; p++) {
            int row = (tid >> 1) + p * 64;
            int c0 = (tid & 1) << 5;
            const float* ap = attn + (size_t)(bh * 1024 + mb + row) * 1024 + kz + k0 + c0;
#pragma unroll
            for (int m = 0; m < 8; m++) {
                float4 av = *(const float4*)(ap + m * 4);
                int kk = c0 + m * 4;
                At[(kk + 0) * ATSTR + row] = av.x;
                At[(kk + 1) * ATSTR + row] = av.y;
                At[(kk + 2) * ATSTR + row] = av.z;
                At[(kk + 3) * ATSTR + row] = av.w;
            }
        }
        {   // fill Vs natural: Vs[k][d]  (64 rows, 2 threads/row)
            int vr = tid >> 1;
            int d0 = (tid & 1) << 5;
            const float* vp = g_v + (size_t)(bh * 1024 + kz + k0 + vr) * 64 + d0;
            float* vd = Vs + vr * VSTR2 + d0;
#pragma unroll
            for (int m = 0; m < 8; m++)
                *(float4*)(vd + m * 4) = *(const float4*)(vp + m * 4);
        }
        __syncthreads();

#pragma unroll 4
        for (int kk = 0; kk < 64; kk++) {
            u64x2 a01 = *(const u64x2*)(At + kk * ATSTR + ty * 8);      // rows 0-3
            u64x2 a23 = *(const u64x2*)(At + kk * ATSTR + ty * 8 + 4);  // rows 4-7
            float4 bf0 = *(const float4*)(Vs + kk * VSTR2 + tx * 8);
            float4 bf1 = *(const float4*)(Vs + kk * VSTR2 + tx * 8 + 4);
            u64 ap4[4] = {a01.x, a01.y, a23.x, a23.y};
            u64 bp8[8] = {dup2(bf0.x), dup2(bf0.y), dup2(bf0.z), dup2(bf0.w),
                          dup2(bf1.x), dup2(bf1.y), dup2(bf1.z), dup2(bf1.w)};
#pragma unroll
            for (int i = 0; i < 4; i++)
#pragma unroll
                for (int j = 0; j < 8; j++) acc[i][j] = f2fma(ap4[i], bp8[j], acc[i][j]);
        }
        __syncthreads();
    }

    int b = bh >> 3, h = bh & 7;
    float* base = g_aoP + (size_t)blockIdx.z * (Mq * Cq);
#pragma unroll
    for (int p = 0; p < 4; p++) {
        float lo[8], hi[8];
#pragma unroll
        for (int j = 0; j < 8; j++) {
            float2 v = upk(acc[p][j]);
            lo[j] = v.x;   // row ty*8 + 2p
            hi[j] = v.y;   // row ty*8 + 2p + 1
        }
        int n0 = mb + ty * 8 + 2 * p;
        float* d0 = base + (size_t)(b * 1024 + n0) * 512 + h * 64 + tx * 8;
        float* d1 = base + (size_t)(b * 1024 + n0 + 1) * 512 + h * 64 + tx * 8;
        *(float4*)d0 = *(float4*)&lo[0];
        *(float4*)(d0 + 4) = *(float4*)&lo[4];
        *(float4*)d1 = *(float4*)&hi[0];
        *(float4*)(d1 + 4) = *(float4*)&hi[4];
    }
}

// ---------------------------------------------------------------------------
// Kernel 5: proj GEMM + bias + residual. A = sum of 4 g_aoP partials.
// 128x128x8 tiles, double-buffered, FFMA2 inner.
// ---------------------------------------------------------------------------
__global__ __launch_bounds__(256) void k_proj(const float* __restrict__ x,
                                              const float* __restrict__ Bm,
                                              const float* __restrict__ bias) {
    const int K = 512, Nn = 512;
    const int P = Mq * Cq;
    __shared__ float As[2][8][128];
    __shared__ float Bs[2][8][128];
    int tid = threadIdx.x;
    int bx = blockIdx.x, by = blockIdx.y;
    int aRow = tid >> 1, aCol = (tid & 1) << 2;
    int bRow = tid >> 5, bCol = (tid & 31) << 2;
    int ty = tid >> 4, tx = tid & 15;

    u64 acc[8][4];
#pragma unroll
    for (int i = 0; i < 8; i++)
#pragma unroll
        for (int j = 0; j < 4; j++) acc[i][j] = 0ULL;

    const float* Ap = g_aoP + (size_t)(by * 128 + aRow) * K + aCol;
    const float* Bp = Bm + (size_t)bRow * Nn + bx * 128 + bCol;

    {
        float4 a0 = *(const float4*)(Ap);
        float4 a1 = *(const float4*)(Ap + P);
        float4 a2 = *(const float4*)(Ap + 2 * P);
        float4 a3 = *(const float4*)(Ap + 3 * P);
        float4 av = {a0.x + a1.x + a2.x + a3.x, a0.y + a1.y + a2.y + a3.y,
                     a0.z + a1.z + a2.z + a3.z, a0.w + a1.w + a2.w + a3.w};
        As[0][aCol + 0][aRow] = av.x;
        As[0][aCol + 1][aRow] = av.y;
        As[0][aCol + 2][aRow] = av.z;
        As[0][aCol + 3][aRow] = av.w;
        *(float4*)&Bs[0][bRow][bCol] = *(const float4*)(Bp);
    }
    __syncthreads();

    for (int k0 = 0; k0 < K; k0 += 8) {
        int buf = (k0 >> 3) & 1;
        float4 av, bv;
        bool more = (k0 + 8) < K;
        if (more) {
            float4 a0 = *(const float4*)(Ap + k0 + 8);
            float4 a1 = *(const float4*)(Ap + P + k0 + 8);
            float4 a2 = *(const float4*)(Ap + 2 * P + k0 + 8);
            float4 a3 = *(const float4*)(Ap + 3 * P + k0 + 8);
            av.x = a0.x + a1.x + a2.x + a3.x;
            av.y = a0.y + a1.y + a2.y + a3.y;
            av.z = a0.z + a1.z + a2.z + a3.z;
            av.w = a0.w + a1.w + a2.w + a3.w;
            bv = *(const float4*)(Bp + (size_t)(k0 + 8) * Nn);
        }
#pragma unroll
        for (int k = 0; k < 8; k++) {
            float a[8];
            *(float4*)&a[0] = *(const float4*)&As[buf][k][ty * 8];
            *(float4*)&a[4] = *(const float4*)&As[buf][k][ty * 8 + 4];
            u64x2 b0 = *(const u64x2*)&Bs[buf][k][tx * 8];
            u64x2 b1 = *(const u64x2*)&Bs[buf][k][tx * 8 + 4];
            u64 bp[4] = {b0.x, b0.y, b1.x, b1.y};
#pragma unroll
            for (int i = 0; i < 8; i++) {
                u64 ad = dup2(a[i]);
#pragma unroll
                for (int j = 0; j < 4; j++) acc[i][j] = f2fma(ad, bp[j], acc[i][j]);
            }
        }
        if (more) {
            int nb2 = buf ^ 1;
            As[nb2][aCol + 0][aRow] = av.x;
            As[nb2][aCol + 1][aRow] = av.y;
            As[nb2][aCol + 2][aRow] = av.z;
            As[nb2][aCol + 3][aRow] = av.w;
            *(float4*)&Bs[nb2][bRow][bCol] = bv;
        }
        __syncthreads();
    }

#pragma unroll
    for (int i = 0; i < 8; i++) {
        int r = by * 128 + ty * 8 + i;
#pragma unroll
        for (int jp = 0; jp < 4; jp++) {
            float2 v2 = upk(acc[i][jp]);
            int c = bx * 128 + tx * 8 + jp * 2;
            g_yp[(size_t)r * 512 + c]     = v2.x + bias[c]     + x[(size_t)r * 512 + c];
            g_yp[(size_t)r * 512 + c + 1] = v2.y + bias[c + 1] + x[(size_t)r * 512 + c + 1];
        }
    }
}

// ---------------------------------------------------------------------------
// Kernel 6: LayerNorm over last dim (512), write y to d_out.
// ---------------------------------------------------------------------------
__global__ __launch_bounds__(128) void k_ln(const float* __restrict__ gamma,
                                            const float* __restrict__ beta,
                                            float* __restrict__ y) {
    __shared__ float s1[4], s2[4];
    int row = blockIdx.x;
    int tid = threadIdx.x;
    const float* p = g_yp + (size_t)row * 512;
    float4 v = *(const float4*)(p + tid * 4);

    float s = v.x + v.y + v.z + v.w;
    float ss = v.x * v.x + v.y * v.y + v.z * v.z + v.w * v.w;
#pragma unroll
    for (int o = 16; o; o >>= 1) {
        s += __shfl_xor_sync(0xffffffffu, s, o);
        ss += __shfl_xor_sync(0xffffffffu, ss, o);
    }
    int wid = tid >> 5, lane = tid & 31;
    if (lane == 0) { s1[wid] = s; s2[wid] = ss; }
    __syncthreads();
    if (tid == 0) {
        s1[0] = s1[0] + s1[1] + s1[2] + s1[3];
        s2[0] = s2[0] + s2[1] + s2[2] + s2[3];
    }
    __syncthreads();
    float mu = s1[0] * (1.f / 512.f);
    float var = s2[0] * (1.f / 512.f) - mu * mu;
    float rstd = rsqrtf(var + LN_EPSq);

    int c = tid * 4;
    float4 g = *(const float4*)(gamma + c);
    float4 be = *(const float4*)(beta + c);
    float4 o;
    o.x = (v.x - mu) * rstd * g.x + be.x;
    o.y = (v.y - mu) * rstd * g.y + be.y;
    o.z = (v.z - mu) * rstd * g.z + be.z;
    o.w = (v.w - mu) * rstd * g.w + be.w;
    *(float4*)(y + (size_t)row * 512 + c) = o;
}

// ---------------------------------------------------------------------------
extern "C" void kernel_launch(void* const* d_in, const int* in_sizes, int n_in,
                              void* d_out, int out_size) {
    (void)in_sizes; (void)n_in; (void)out_size;
    const float* x     = (const float*)d_in[0];
    const float* Wqkv  = (const float*)d_in[1];
    const float* bqkv  = (const float*)d_in[2];
    const float* ow    = (const float*)d_in[3];
    const float* Wproj = (const float*)d_in[4];
    const float* bproj = (const float*)d_in[5];
    const float* gamma = (const float*)d_in[6];
    const float* beta  = (const float*)d_in[7];

    float* out      = (float*)d_out;
    float* y_out    = out;                         // [4,1024,512]
    float* attn_out = out + (size_t)Bq * Nq * Cq;  // [4,8,1024,1024]

    int scores_smem = 2 * 64 * QKSTR * (int)sizeof(float);            // 67584 B
    int av_smem     = (64 * ATSTR + 64 * VSTR2) * (int)sizeof(float); // 51200 B
    cudaFuncSetAttribute(k_scores, cudaFuncAttributeMaxDynamicSharedMemorySize,
                         scores_smem);
    cudaFuncSetAttribute(k_av, cudaFuncAttributeMaxDynamicSharedMemorySize,
                         av_smem);

    k_qkv    <<<dim3(12, 32), 256>>>(x, Wqkv, bqkv);
    k_scores <<<dim3(8, 8, 32), 256, scores_smem>>>(ow, attn_out);
    k_softmax<<<32768, 256>>>(attn_out);
    k_av     <<<dim3(8, 32, 4), 128, av_smem>>>(attn_out);
    k_proj   <<<dim3(4, 32), 256>>>(x, Wproj, bproj);
    k_ln     <<<4096, 128>>>(gamma, beta, y_out);
}

// round 10
// speedup vs baseline: 1.1682x; 1.0300x over previous
#include <cuda_runtime.h>
#include <math.h>

// Problem constants
#define Bq   4
#define Nq   1024
#define Cq   512
#define Hq   8
#define HDq  64
#define BHq  32
#define Mq   4096
#define SCALEq 0.125f
#define LN_EPSq 1e-5f

typedef unsigned long long u64;
typedef ulonglong2 u64x2;

// packed fp32x2 FMA (sm_103a). ptxas never emits this from C++.
__device__ __forceinline__ u64 f2fma(u64 a, u64 b, u64 c) {
    u64 d;
    asm("fma.rn.f32x2 %0, %1, %2, %3;" : "=l"(d) : "l"(a), "l"(b), "l"(c));
    return d;
}
__device__ __forceinline__ float2 upk(u64 v) {
    float2 r;
    asm("mov.b64 {%0, %1}, %2;" : "=f"(r.x), "=f"(r.y) : "l"(v));
    return r;
}
__device__ __forceinline__ u64 dup2(float x) {
    u64 r;
    asm("mov.b64 %0, {%1, %1};" : "=l"(r) : "f"(x));
    return r;
}

// Scratch (device globals — allocation-free)
__device__ float g_q  [BHq * Nq * HDq];     // [bh][n][d]
__device__ float g_k  [BHq * Nq * HDq];
__device__ float g_v  [BHq * Nq * HDq];
__device__ float g_aoP[4 * Mq * Cq];        // 4 k-split partials of attn-out
__device__ float g_ypP[4 * Mq * Cq];        // 4 k-split partials of proj-out

// ---------------------------------------------------------------------------
// Kernel 1: QKV GEMM. x[4096,512] @ Wqkv[512,1536] + bqkv -> scatter q/k/v
// 128x128x8 tiles, 256 threads, 8x8/thread, double-buffered, FFMA2 inner.
// ---------------------------------------------------------------------------
__global__ __launch_bounds__(256) void k_qkv(const float* __restrict__ A,
                                             const float* __restrict__ Bm,
                                             const float* __restrict__ bias) {
    const int K = 512, Nn = 1536;
    __shared__ float As[2][8][128];
    __shared__ float Bs[2][8][128];
    int tid = threadIdx.x;
    int bx = blockIdx.x, by = blockIdx.y;
    int aRow = tid >> 1, aCol = (tid & 1) << 2;
    int bRow = tid >> 5, bCol = (tid & 31) << 2;
    int ty = tid >> 4, tx = tid & 15;

    u64 acc[8][4];
#pragma unroll
    for (int i = 0; i < 8; i++)
#pragma unroll
        for (int j = 0; j < 4; j++) acc[i][j] = 0ULL;

    const float* Ap = A + (size_t)(by * 128 + aRow) * K + aCol;
    const float* Bp = Bm + (size_t)bRow * Nn + bx * 128 + bCol;

    {
        float4 av = *(const float4*)(Ap);
        As[0][aCol + 0][aRow] = av.x;
        As[0][aCol + 1][aRow] = av.y;
        As[0][aCol + 2][aRow] = av.z;
        As[0][aCol + 3][aRow] = av.w;
        *(float4*)&Bs[0][bRow][bCol] = *(const float4*)(Bp);
    }
    __syncthreads();

    for (int k0 = 0; k0 < K; k0 += 8) {
        int buf = (k0 >> 3) & 1;
        float4 av, bv;
        bool more = (k0 + 8) < K;
        if (more) {
            av = *(const float4*)(Ap + k0 + 8);
            bv = *(const float4*)(Bp + (size_t)(k0 + 8) * Nn);
        }
#pragma unroll
        for (int k = 0; k < 8; k++) {
            float a[8];
            *(float4*)&a[0] = *(const float4*)&As[buf][k][ty * 8];
            *(float4*)&a[4] = *(const float4*)&As[buf][k][ty * 8 + 4];
            u64x2 b0 = *(const u64x2*)&Bs[buf][k][tx * 8];
            u64x2 b1 = *(const u64x2*)&Bs[buf][k][tx * 8 + 4];
            u64 bp[4] = {b0.x, b0.y, b1.x, b1.y};
#pragma unroll
            for (int i = 0; i < 8; i++) {
                u64 ad = dup2(a[i]);
#pragma unroll
                for (int j = 0; j < 4; j++) acc[i][j] = f2fma(ad, bp[j], acc[i][j]);
            }
        }
        if (more) {
            int nb = buf ^ 1;
            As[nb][aCol + 0][aRow] = av.x;
            As[nb][aCol + 1][aRow] = av.y;
            As[nb][aCol + 2][aRow] = av.z;
            As[nb][aCol + 3][aRow] = av.w;
            *(float4*)&Bs[nb][bRow][bCol] = bv;
        }
        __syncthreads();
    }

#pragma unroll
    for (int i = 0; i < 8; i++) {
        int r = by * 128 + ty * 8 + i;
        int bb = r >> 10, n = r & 1023;
#pragma unroll
        for (int jp = 0; jp < 4; jp++) {
            float2 v2 = upk(acc[i][jp]);
            float vv[2] = {v2.x, v2.y};
#pragma unroll
            for (int l = 0; l < 2; l++) {
                int c = bx * 128 + tx * 8 + jp * 2 + l;
                float v = vv[l] + bias[c];
                int sel = c >> 9;
                int rem = c & 511;
                int h = rem >> 6, d = rem & 63;
                float* dst = (sel == 0) ? g_q : ((sel == 1) ? g_k : g_v);
                dst[((bb * 8 + h) * 1024 + n) * 64 + d] = v;
            }
        }
    }
}

// ---------------------------------------------------------------------------
// Kernel 2: scores. S = poly(ow; q·k^T*SCALE) pre-softmax into attn.
// 128x128 tile per block per bh, 256 threads, 8x8/thread, FFMA2 inner.
// ---------------------------------------------------------------------------
#define QKSTR 132
__global__ __launch_bounds__(256) void k_scores(const float* __restrict__ ow_in,
                                                float* __restrict__ attn) {
    extern __shared__ float sm[];
    float* Qt = sm;                // [d][row]
    float* Kt = sm + 64 * QKSTR;   // [d][col]
    int bh = blockIdx.z;
    int mb = blockIdx.y * 128;
    int nb = blockIdx.x * 128;
    int tid = threadIdx.x;

    {
        int row = tid >> 1;
        int d0 = (tid & 1) << 5;
        const float* qp = g_q + (size_t)(bh * 1024 + mb + row) * 64 + d0;
        const float* kp = g_k + (size_t)(bh * 1024 + nb + row) * 64 + d0;
#pragma unroll
        for (int m = 0; m < 8; m++) {
            int d = d0 + m * 4;
            float4 qv = *(const float4*)(qp + m * 4);
            Qt[(d + 0) * QKSTR + row] = qv.x;
            Qt[(d + 1) * QKSTR + row] = qv.y;
            Qt[(d + 2) * QKSTR + row] = qv.z;
            Qt[(d + 3) * QKSTR + row] = qv.w;
            float4 kv = *(const float4*)(kp + m * 4);
            Kt[(d + 0) * QKSTR + row] = kv.x;
            Kt[(d + 1) * QKSTR + row] = kv.y;
            Kt[(d + 2) * QKSTR + row] = kv.z;
            Kt[(d + 3) * QKSTR + row] = kv.w;
        }
    }
    __syncthreads();

    int ty = tid >> 4, tx = tid & 15;
    u64 acc[8][4];
#pragma unroll
    for (int i = 0; i < 8; i++)
#pragma unroll
        for (int j = 0; j < 4; j++) acc[i][j] = 0ULL;

#pragma unroll 8
    for (int d = 0; d < 64; d++) {
        float a[8];
        *(float4*)&a[0] = *(const float4*)(Qt + d * QKSTR + ty * 8);
        *(float4*)&a[4] = *(const float4*)(Qt + d * QKSTR + ty * 8 + 4);
        u64x2 b0 = *(const u64x2*)(Kt + d * QKSTR + tx * 8);
        u64x2 b1 = *(const u64x2*)(Kt + d * QKSTR + tx * 8 + 4);
        u64 bp[4] = {b0.x, b0.y, b1.x, b1.y};
#pragma unroll
        for (int i = 0; i < 8; i++) {
            u64 ad = dup2(a[i]);
#pragma unroll
            for (int j = 0; j < 4; j++) acc[i][j] = f2fma(ad, bp[j], acc[i][j]);
        }
    }

    float w0 = ow_in[0], w1 = ow_in[1], w2 = ow_in[2];
    float mw = fmaxf(w0, fmaxf(w1, w2));
    float e0 = __expf(w0 - mw), e1 = __expf(w1 - mw), e2 = __expf(w2 - mw);
    float inv = 1.f / (e0 + e1 + e2);
    w0 = e0 * inv; w1 = e1 * inv; w2 = e2 * inv;

#pragma unroll
    for (int i = 0; i < 8; i++) {
        int row = bh * 1024 + mb + ty * 8 + i;
        float o[8];
#pragma unroll
        for (int jp = 0; jp < 4; jp++) {
            float2 v2 = upk(acc[i][jp]);
            float s;
            s = v2.x * SCALEq; o[jp * 2 + 0] = s * (w0 + s * (w1 + s * w2));
            s = v2.y * SCALEq; o[jp * 2 + 1] = s * (w0 + s * (w1 + s * w2));
        }
        float* dst = attn + (size_t)row * 1024 + nb + tx * 8;
        *(float4*)dst = *(float4*)&o[0];
        *(float4*)(dst + 4) = *(float4*)&o[4];
    }
}

// ---------------------------------------------------------------------------
// Kernel 3: row softmax in place on attn [32768 rows x 1024].
// ---------------------------------------------------------------------------
__global__ __launch_bounds__(256) void k_softmax(float* __restrict__ attn) {
    __shared__ float red[8];
    int row = blockIdx.x;
    int tid = threadIdx.x;
    float* p = attn + (size_t)row * 1024;
    float4 v = *(const float4*)(p + tid * 4);

    float m = fmaxf(fmaxf(v.x, v.y), fmaxf(v.z, v.w));
#pragma unroll
    for (int o = 16; o; o >>= 1) m = fmaxf(m, __shfl_xor_sync(0xffffffffu, m, o));
    int wid = tid >> 5, lane = tid & 31;
    if (lane == 0) red[wid] = m;
    __syncthreads();
    if (tid == 0) {
        float mm = red[0];
#pragma unroll
        for (int i = 1; i < 8; i++) mm = fmaxf(mm, red[i]);
        red[0] = mm;
    }
    __syncthreads();
    m = red[0];
    __syncthreads();

    float4 e;
    e.x = __expf(v.x - m); e.y = __expf(v.y - m);
    e.z = __expf(v.z - m); e.w = __expf(v.w - m);
    float s = e.x + e.y + e.z + e.w;
#pragma unroll
    for (int o = 16; o; o >>= 1) s += __shfl_xor_sync(0xffffffffu, s, o);
    if (lane == 0) red[wid] = s;
    __syncthreads();
    if (tid == 0) {
        float ss = 0.f;
#pragma unroll
        for (int i = 0; i < 8; i++) ss += red[i];
        red[0] = ss;
    }
    __syncthreads();
    float invs = 1.f / red[0];

    e.x *= invs; e.y *= invs; e.z *= invs; e.w *= invs;
    *(float4*)(p + tid * 4) = e;
}

// ---------------------------------------------------------------------------
// Kernel 4: partial AV. Per (b,h,z): [128,256]@[256,64] -> g_aoP[z].
// 256 threads, 128x64 tile, FFMA2 with free row-pairs from transposed tile.
// (exact R4 version — best measured)
// ---------------------------------------------------------------------------
#define ATSTR 132
#define VSTR2 68
__global__ __launch_bounds__(256) void k_av(const float* __restrict__ attn) {
    extern __shared__ float sm[];
    float* At = sm;                 // [k 0..63][row 0..127] transposed
    float* Vs = sm + 64 * ATSTR;    // [k][d]
    int mb = blockIdx.x * 128;
    int bh = blockIdx.y;
    int kz = blockIdx.z << 8;       // z * 256
    int tid = threadIdx.x;
    int ty = tid >> 4, tx = tid & 15;

    u64 acc[4][4];
#pragma unroll
    for (int i = 0; i < 4; i++)
#pragma unroll
        for (int j = 0; j < 4; j++) acc[i][j] = 0ULL;

    for (int k0 = 0; k0 < 256; k0 += 64) {
        {   // fill At transposed: At[k][row]
            int row = tid >> 1;
            int c0 = (tid & 1) << 5;
            const float* ap = attn + (size_t)(bh * 1024 + mb + row) * 1024 + kz + k0 + c0;
#pragma unroll
            for (int m = 0; m < 8; m++) {
                float4 av = *(const float4*)(ap + m * 4);
                int kk = c0 + m * 4;
                At[(kk + 0) * ATSTR + row] = av.x;
                At[(kk + 1) * ATSTR + row] = av.y;
                At[(kk + 2) * ATSTR + row] = av.z;
                At[(kk + 3) * ATSTR + row] = av.w;
            }
        }
        {   // fill Vs natural: Vs[k][d]
            int vr = tid >> 2;
            int d0 = (tid & 3) << 4;
            const float* vp = g_v + (size_t)(bh * 1024 + kz + k0 + vr) * 64 + d0;
            float* vd = Vs + vr * VSTR2 + d0;
#pragma unroll
            for (int m = 0; m < 4; m++)
                *(float4*)(vd + m * 4) = *(const float4*)(vp + m * 4);
        }
        __syncthreads();

#pragma unroll 8
        for (int kk = 0; kk < 64; kk++) {
            u64x2 a01 = *(const u64x2*)(At + kk * ATSTR + ty * 8);      // rows 0-3
            u64x2 a23 = *(const u64x2*)(At + kk * ATSTR + ty * 8 + 4);  // rows 4-7
            float4 bf = *(const float4*)(Vs + kk * VSTR2 + tx * 4);
            u64 ap4[4] = {a01.x, a01.y, a23.x, a23.y};
            u64 bp4[4] = {dup2(bf.x), dup2(bf.y), dup2(bf.z), dup2(bf.w)};
#pragma unroll
            for (int i = 0; i < 4; i++)
#pragma unroll
                for (int j = 0; j < 4; j++) acc[i][j] = f2fma(ap4[i], bp4[j], acc[i][j]);
        }
        __syncthreads();
    }

    int b = bh >> 3, h = bh & 7;
    float* base = g_aoP + (size_t)blockIdx.z * (Mq * Cq);
#pragma unroll
    for (int p = 0; p < 4; p++) {
        float2 v0 = upk(acc[p][0]);
        float2 v1 = upk(acc[p][1]);
        float2 v2 = upk(acc[p][2]);
        float2 v3 = upk(acc[p][3]);
        float4 lo = {v0.x, v1.x, v2.x, v3.x};   // row 2p
        float4 hi = {v0.y, v1.y, v2.y, v3.y};   // row 2p+1
        int n0 = mb + ty * 8 + 2 * p;
        *(float4*)(base + (size_t)(b * 1024 + n0) * 512 + h * 64 + tx * 4) = lo;
        *(float4*)(base + (size_t)(b * 1024 + n0 + 1) * 512 + h * 64 + tx * 4) = hi;
    }
}

// ---------------------------------------------------------------------------
// Kernel 5: proj GEMM, K-split 4. A = sum of 4 g_aoP partials (disjoint K
// ranges per z). Each block: 128x128 tile over K=128 -> g_ypP[z] partial.
// Grid (4, 32, 4) = 512 blocks (vs 128) -> fixes grid-starved occupancy.
// ---------------------------------------------------------------------------
__global__ __launch_bounds__(256) void k_proj(const float* __restrict__ Bm) {
    const int K4 = 128, Nn = 512;
    const int P = Mq * Cq;
    __shared__ float As[2][8][128];
    __shared__ float Bs[2][8][128];
    int tid = threadIdx.x;
    int bx = blockIdx.x, by = blockIdx.y, bz = blockIdx.z;
    int aRow = tid >> 1, aCol = (tid & 1) << 2;
    int bRow = tid >> 5, bCol = (tid & 31) << 2;
    int ty = tid >> 4, tx = tid & 15;

    u64 acc[8][4];
#pragma unroll
    for (int i = 0; i < 8; i++)
#pragma unroll
        for (int j = 0; j < 4; j++) acc[i][j] = 0ULL;

    const float* Ap = g_aoP + (size_t)(by * 128 + aRow) * 512 + bz * 128 + aCol;
    const float* Bp = Bm + (size_t)(bz * 128 + bRow) * Nn + bx * 128 + bCol;

    {
        float4 a0 = *(const float4*)(Ap);
        float4 a1 = *(const float4*)(Ap + P);
        float4 a2 = *(const float4*)(Ap + 2 * P);
        float4 a3 = *(const float4*)(Ap + 3 * P);
        float4 av = {a0.x + a1.x + a2.x + a3.x, a0.y + a1.y + a2.y + a3.y,
                     a0.z + a1.z + a2.z + a3.z, a0.w + a1.w + a2.w + a3.w};
        As[0][aCol + 0][aRow] = av.x;
        As[0][aCol + 1][aRow] = av.y;
        As[0][aCol + 2][aRow] = av.z;
        As[0][aCol + 3][aRow] = av.w;
        *(float4*)&Bs[0][bRow][bCol] = *(const float4*)(Bp);
    }
    __syncthreads();

    for (int k0 = 0; k0 < K4; k0 += 8) {
        int buf = (k0 >> 3) & 1;
        float4 av, bv;
        bool more = (k0 + 8) < K4;
        if (more) {
            float4 a0 = *(const float4*)(Ap + k0 + 8);
            float4 a1 = *(const float4*)(Ap + P + k0 + 8);
            float4 a2 = *(const float4*)(Ap + 2 * P + k0 + 8);
            float4 a3 = *(const float4*)(Ap + 3 * P + k0 + 8);
            av.x = a0.x + a1.x + a2.x + a3.x;
            av.y = a0.y + a1.y + a2.y + a3.y;
            av.z = a0.z + a1.z + a2.z + a3.z;
            av.w = a0.w + a1.w + a2.w + a3.w;
            bv = *(const float4*)(Bp + (size_t)(k0 + 8) * Nn);
        }
#pragma unroll
        for (int k = 0; k < 8; k++) {
            float a[8];
            *(float4*)&a[0] = *(const float4*)&As[buf][k][ty * 8];
            *(float4*)&a[4] = *(const float4*)&As[buf][k][ty * 8 + 4];
            u64x2 b0 = *(const u64x2*)&Bs[buf][k][tx * 8];
            u64x2 b1 = *(const u64x2*)&Bs[buf][k][tx * 8 + 4];
            u64 bp[4] = {b0.x, b0.y, b1.x, b1.y};
#pragma unroll
            for (int i = 0; i < 8; i++) {
                u64 ad = dup2(a[i]);
#pragma unroll
                for (int j = 0; j < 4; j++) acc[i][j] = f2fma(ad, bp[j], acc[i][j]);
            }
        }
        if (more) {
            int nb2 = buf ^ 1;
            As[nb2][aCol + 0][aRow] = av.x;
            As[nb2][aCol + 1][aRow] = av.y;
            As[nb2][aCol + 2][aRow] = av.z;
            As[nb2][aCol + 3][aRow] = av.w;
            *(float4*)&Bs[nb2][bRow][bCol] = bv;
        }
        __syncthreads();
    }

    float* yp = g_ypP + (size_t)bz * P;
#pragma unroll
    for (int i = 0; i < 8; i++) {
        int r = by * 128 + ty * 8 + i;
#pragma unroll
        for (int jp = 0; jp < 4; jp++) {
            float2 v2 = upk(acc[i][jp]);
            int c = bx * 128 + tx * 8 + jp * 2;
            yp[(size_t)r * 512 + c]     = v2.x;
            yp[(size_t)r * 512 + c + 1] = v2.y;
        }
    }
}

// ---------------------------------------------------------------------------
// Kernel 6: LayerNorm. y_pre = sum of 4 proj partials + bias + x, then LN.
// ---------------------------------------------------------------------------
__global__ __launch_bounds__(128) void k_ln(const float* __restrict__ gamma,
                                            const float* __restrict__ beta,
                                            const float* __restrict__ bias,
                                            const float* __restrict__ x,
                                            float* __restrict__ y) {
    const int P = Mq * Cq;
    __shared__ float s1[4], s2[4];
    int row = blockIdx.x;
    int tid = threadIdx.x;
    int c = tid * 4;
    const float* p = g_ypP + (size_t)row * 512 + c;
    float4 v0 = *(const float4*)(p);
    float4 v1 = *(const float4*)(p + P);
    float4 v2 = *(const float4*)(p + 2 * P);
    float4 v3 = *(const float4*)(p + 3 * P);
    float4 bb = *(const float4*)(bias + c);
    float4 xx = *(const float4*)(x + (size_t)row * 512 + c);
    float4 v;
    v.x = v0.x + v1.x + v2.x + v3.x + bb.x + xx.x;
    v.y = v0.y + v1.y + v2.y + v3.y + bb.y + xx.y;
    v.z = v0.z + v1.z + v2.z + v3.z + bb.z + xx.z;
    v.w = v0.w + v1.w + v2.w + v3.w + bb.w + xx.w;

    float s = v.x + v.y + v.z + v.w;
    float ss = v.x * v.x + v.y * v.y + v.z * v.z + v.w * v.w;
#pragma unroll
    for (int o = 16; o; o >>= 1) {
        s += __shfl_xor_sync(0xffffffffu, s, o);
        ss += __shfl_xor_sync(0xffffffffu, ss, o);
    }
    int wid = tid >> 5, lane = tid & 31;
    if (lane == 0) { s1[wid] = s; s2[wid] = ss; }
    __syncthreads();
    if (tid == 0) {
        s1[0] = s1[0] + s1[1] + s1[2] + s1[3];
        s2[0] = s2[0] + s2[1] + s2[2] + s2[3];
    }
    __syncthreads();
    float mu = s1[0] * (1.f / 512.f);
    float var = s2[0] * (1.f / 512.f) - mu * mu;
    float rstd = rsqrtf(var + LN_EPSq);

    float4 g = *(const float4*)(gamma + c);
    float4 be = *(const float4*)(beta + c);
    float4 o;
    o.x = (v.x - mu) * rstd * g.x + be.x;
    o.y = (v.y - mu) * rstd * g.y + be.y;
    o.z = (v.z - mu) * rstd * g.z + be.z;
    o.w = (v.w - mu) * rstd * g.w + be.w;
    *(float4*)(y + (size_t)row * 512 + c) = o;
}

// ---------------------------------------------------------------------------
extern "C" void kernel_launch(void* const* d_in, const int* in_sizes, int n_in,
                              void* d_out, int out_size) {
    (void)in_sizes; (void)n_in; (void)out_size;
    const float* x     = (const float*)d_in[0];
    const float* Wqkv  = (const float*)d_in[1];
    const float* bqkv  = (const float*)d_in[2];
    const float* ow    = (const float*)d_in[3];
    const float* Wproj = (const float*)d_in[4];
    const float* bproj = (const float*)d_in[5];
    const float* gamma = (const float*)d_in[6];
    const float* beta  = (const float*)d_in[7];

    float* out      = (float*)d_out;
    float* y_out    = out;                         // [4,1024,512]
    float* attn_out = out + (size_t)Bq * Nq * Cq;  // [4,8,1024,1024]

    int scores_smem = 2 * 64 * QKSTR * (int)sizeof(float);            // 67584 B
    int av_smem     = (64 * ATSTR + 64 * VSTR2) * (int)sizeof(float); // 51200 B
    cudaFuncSetAttribute(k_scores, cudaFuncAttributeMaxDynamicSharedMemorySize,
                         scores_smem);
    cudaFuncSetAttribute(k_av, cudaFuncAttributeMaxDynamicSharedMemorySize,
                         av_smem);

    k_qkv    <<<dim3(12, 32), 256>>>(x, Wqkv, bqkv);
    k_scores <<<dim3(8, 8, 32), 256, scores_smem>>>(ow, attn_out);
    k_softmax<<<32768, 256>>>(attn_out);
    k_av     <<<dim3(8, 32, 4), 256, av_smem>>>(attn_out);
    k_proj   <<<dim3(4, 32, 4), 256>>>(Wproj);
    k_ln     <<<4096, 128>>>(gamma, beta, bproj, x, y_out);
}

// round 11
// speedup vs baseline: 1.3275x; 1.1363x over previous
#include <cuda_runtime.h>
#include <cuda_bf16.h>
#include <math.h>

// Problem constants
#define Bq   4
#define Nq   1024
#define Cq   512
#define Hq   8
#define HDq  64
#define BHq  32
#define Mq   4096
#define SCALEq 0.125f
#define LN_EPSq 1e-5f

typedef unsigned long long u64;
typedef ulonglong2 u64x2;

// packed fp32x2 FMA (sm_103a). ptxas never emits this from C++.
__device__ __forceinline__ u64 f2fma(u64 a, u64 b, u64 c) {
    u64 d;
    asm("fma.rn.f32x2 %0, %1, %2, %3;" : "=l"(d) : "l"(a), "l"(b), "l"(c));
    return d;
}
__device__ __forceinline__ float2 upk(u64 v) {
    float2 r;
    asm("mov.b64 {%0, %1}, %2;" : "=f"(r.x), "=f"(r.y) : "l"(v));
    return r;
}
__device__ __forceinline__ u64 dup2(float x) {
    u64 r;
    asm("mov.b64 %0, {%1, %1};" : "=l"(r) : "f"(x));
    return r;
}

// bf16 mma.sync (baseline PTX, compiles under compute_103, runs on HMMA)
__device__ __forceinline__ void mma_bf16(float* d, const unsigned* a,
                                         const unsigned* b) {
    asm volatile(
        "mma.sync.aligned.m16n8k16.row.col.f32.bf16.bf16.f32 "
        "{%0,%1,%2,%3}, {%4,%5,%6,%7}, {%8,%9}, {%0,%1,%2,%3};"
        : "+f"(d[0]), "+f"(d[1]), "+f"(d[2]), "+f"(d[3])
        : "r"(a[0]), "r"(a[1]), "r"(a[2]), "r"(a[3]), "r"(b[0]), "r"(b[1]));
}
__device__ __forceinline__ unsigned pack_bf16x2(float a, float b) {
    unsigned short ha = __bfloat16_as_ushort(__float2bfloat16(a));
    unsigned short hb = __bfloat16_as_ushort(__float2bfloat16(b));
    return (unsigned)ha | ((unsigned)hb << 16);
}

// Scratch (device globals — allocation-free)
__device__ float g_q  [BHq * Nq * HDq];     // [bh][n][d]
__device__ float g_k  [BHq * Nq * HDq];
__device__ float g_v  [BHq * Nq * HDq];
__device__ float g_aoP[4 * Mq * Cq];        // 4 k-split partials of attn-out
__device__ float g_ypP[4 * Mq * Cq];        // 4 k-split partials of proj-out

// ---------------------------------------------------------------------------
// Kernel 1: QKV GEMM. x[4096,512] @ Wqkv[512,1536] + bqkv -> scatter q/k/v
// 128x128x8 tiles, 256 threads, 8x8/thread, double-buffered, FFMA2 inner.
// ---------------------------------------------------------------------------
__global__ __launch_bounds__(256) void k_qkv(const float* __restrict__ A,
                                             const float* __restrict__ Bm,
                                             const float* __restrict__ bias) {
    const int K = 512, Nn = 1536;
    __shared__ float As[2][8][128];
    __shared__ float Bs[2][8][128];
    int tid = threadIdx.x;
    int bx = blockIdx.x, by = blockIdx.y;
    int aRow = tid >> 1, aCol = (tid & 1) << 2;
    int bRow = tid >> 5, bCol = (tid & 31) << 2;
    int ty = tid >> 4, tx = tid & 15;

    u64 acc[8][4];
#pragma unroll
    for (int i = 0; i < 8; i++)
#pragma unroll
        for (int j = 0; j < 4; j++) acc[i][j] = 0ULL;

    const float* Ap = A + (size_t)(by * 128 + aRow) * K + aCol;
    const float* Bp = Bm + (size_t)bRow * Nn + bx * 128 + bCol;

    {
        float4 av = *(const float4*)(Ap);
        As[0][aCol + 0][aRow] = av.x;
        As[0][aCol + 1][aRow] = av.y;
        As[0][aCol + 2][aRow] = av.z;
        As[0][aCol + 3][aRow] = av.w;
        *(float4*)&Bs[0][bRow][bCol] = *(const float4*)(Bp);
    }
    __syncthreads();

    for (int k0 = 0; k0 < K; k0 += 8) {
        int buf = (k0 >> 3) & 1;
        float4 av, bv;
        bool more = (k0 + 8) < K;
        if (more) {
            av = *(const float4*)(Ap + k0 + 8);
            bv = *(const float4*)(Bp + (size_t)(k0 + 8) * Nn);
        }
#pragma unroll
        for (int k = 0; k < 8; k++) {
            float a[8];
            *(float4*)&a[0] = *(const float4*)&As[buf][k][ty * 8];
            *(float4*)&a[4] = *(const float4*)&As[buf][k][ty * 8 + 4];
            u64x2 b0 = *(const u64x2*)&Bs[buf][k][tx * 8];
            u64x2 b1 = *(const u64x2*)&Bs[buf][k][tx * 8 + 4];
            u64 bp[4] = {b0.x, b0.y, b1.x, b1.y};
#pragma unroll
            for (int i = 0; i < 8; i++) {
                u64 ad = dup2(a[i]);
#pragma unroll
                for (int j = 0; j < 4; j++) acc[i][j] = f2fma(ad, bp[j], acc[i][j]);
            }
        }
        if (more) {
            int nb = buf ^ 1;
            As[nb][aCol + 0][aRow] = av.x;
            As[nb][aCol + 1][aRow] = av.y;
            As[nb][aCol + 2][aRow] = av.z;
            As[nb][aCol + 3][aRow] = av.w;
            *(float4*)&Bs[nb][bRow][bCol] = bv;
        }
        __syncthreads();
    }

#pragma unroll
    for (int i = 0; i < 8; i++) {
        int r = by * 128 + ty * 8 + i;
        int bb = r >> 10, n = r & 1023;
#pragma unroll
        for (int jp = 0; jp < 4; jp++) {
            float2 v2 = upk(acc[i][jp]);
            float vv[2] = {v2.x, v2.y};
#pragma unroll
            for (int l = 0; l < 2; l++) {
                int c = bx * 128 + tx * 8 + jp * 2 + l;
                float v = vv[l] + bias[c];
                int sel = c >> 9;
                int rem = c & 511;
                int h = rem >> 6, d = rem & 63;
                float* dst = (sel == 0) ? g_q : ((sel == 1) ? g_k : g_v);
                dst[((bb * 8 + h) * 1024 + n) * 64 + d] = v;
            }
        }
    }
}

// ---------------------------------------------------------------------------
// Kernel 2: scores via tensor cores (mma.sync bf16x3 split precision).
// 128x128 tile per block per bh, 256 threads (8 warps, each 32x64 outputs).
// D = Qh*Kh^T + Ql*Kh^T + Qh*Kl^T in fp32; epilogue scale+poly -> attn.
// ---------------------------------------------------------------------------
#define SST 72   // bf16 elements per smem row (144 B, conflict-free)
__global__ __launch_bounds__(256) void k_scores(const float* __restrict__ ow_in,
                                                float* __restrict__ attn) {
    extern __shared__ char smc[];
    unsigned short* Qh = (unsigned short*)smc;
    unsigned short* Ql = Qh + 128 * SST;
    unsigned short* Kh = Ql + 128 * SST;
    unsigned short* Kl = Kh + 128 * SST;

    int bh = blockIdx.z;
    int mb = blockIdx.y * 128;
    int nb = blockIdx.x * 128;
    int tid = threadIdx.x;

    // stage Q,K as hi/lo bf16 pairs
    const float* qbase = g_q + (size_t)(bh * 1024 + mb) * 64;
    const float* kbase = g_k + (size_t)(bh * 1024 + nb) * 64;
#pragma unroll
    for (int i = 0; i < 16; i++) {
        int p = tid + i * 256;       // 0..4095 pair index
        int row = p >> 5;            // 32 pairs per row
        int col = (p & 31) << 1;
        float2 qv = *(const float2*)(qbase + row * 64 + col);
        float2 kv = *(const float2*)(kbase + row * 64 + col);
        float qhx = __bfloat162float(__float2bfloat16(qv.x));
        float qhy = __bfloat162float(__float2bfloat16(qv.y));
        float khx = __bfloat162float(__float2bfloat16(kv.x));
        float khy = __bfloat162float(__float2bfloat16(kv.y));
        int off = row * SST + col;
        *(unsigned*)(Qh + off) = pack_bf16x2(qhx, qhy);
        *(unsigned*)(Ql + off) = pack_bf16x2(qv.x - qhx, qv.y - qhy);
        *(unsigned*)(Kh + off) = pack_bf16x2(khx, khy);
        *(unsigned*)(Kl + off) = pack_bf16x2(kv.x - khx, kv.y - khy);
    }
    __syncthreads();

    int w = tid >> 5, lane = tid & 31;
    int wm = (w >> 1) * 32;          // warp row base within tile
    int wn = (w & 1) * 64;           // warp col base within tile
    int lr = lane >> 2;              // 0..7
    int lc = (lane & 3) << 1;        // 0,2,4,6

    float d[2][8][4];
#pragma unroll
    for (int mt = 0; mt < 2; mt++)
#pragma unroll
        for (int nt = 0; nt < 8; nt++)
#pragma unroll
            for (int j = 0; j < 4; j++) d[mt][nt][j] = 0.f;

#pragma unroll
    for (int k0 = 0; k0 < 64; k0 += 16) {
        unsigned ah[2][4], al[2][4], bb[8][2];
#pragma unroll
        for (int mt = 0; mt < 2; mt++) {
            int r0 = (wm + mt * 16 + lr) * SST + k0 + lc;
            int r1 = (wm + mt * 16 + lr + 8) * SST + k0 + lc;
            ah[mt][0] = *(const unsigned*)(Qh + r0);
            ah[mt][1] = *(const unsigned*)(Qh + r1);
            ah[mt][2] = *(const unsigned*)(Qh + r0 + 8);
            ah[mt][3] = *(const unsigned*)(Qh + r1 + 8);
            al[mt][0] = *(const unsigned*)(Ql + r0);
            al[mt][1] = *(const unsigned*)(Ql + r1);
            al[mt][2] = *(const unsigned*)(Ql + r0 + 8);
            al[mt][3] = *(const unsigned*)(Ql + r1 + 8);
        }
        // B = Kh fragments: hh + lh passes
#pragma unroll
        for (int nt = 0; nt < 8; nt++) {
            int rn = (wn + nt * 8 + lr) * SST + k0 + lc;
            bb[nt][0] = *(const unsigned*)(Kh + rn);
            bb[nt][1] = *(const unsigned*)(Kh + rn + 8);
        }
#pragma unroll
        for (int mt = 0; mt < 2; mt++)
#pragma unroll
            for (int nt = 0; nt < 8; nt++) mma_bf16(d[mt][nt], ah[mt], bb[nt]);
#pragma unroll
        for (int mt = 0; mt < 2; mt++)
#pragma unroll
            for (int nt = 0; nt < 8; nt++) mma_bf16(d[mt][nt], al[mt], bb[nt]);
        // B = Kl fragments: hl pass
#pragma unroll
        for (int nt = 0; nt < 8; nt++) {
            int rn = (wn + nt * 8 + lr) * SST + k0 + lc;
            bb[nt][0] = *(const unsigned*)(Kl + rn);
            bb[nt][1] = *(const unsigned*)(Kl + rn + 8);
        }
#pragma unroll
        for (int mt = 0; mt < 2; mt++)
#pragma unroll
            for (int nt = 0; nt < 8; nt++) mma_bf16(d[mt][nt], ah[mt], bb[nt]);
    }

    // order-weight softmax
    float w0 = ow_in[0], w1 = ow_in[1], w2 = ow_in[2];
    float mw = fmaxf(w0, fmaxf(w1, w2));
    float e0 = __expf(w0 - mw), e1 = __expf(w1 - mw), e2 = __expf(w2 - mw);
    float inv = 1.f / (e0 + e1 + e2);
    w0 = e0 * inv; w1 = e1 * inv; w2 = e2 * inv;

    // epilogue: scale + poly + store (float2 per row per tile)
#pragma unroll
    for (int mt = 0; mt < 2; mt++) {
        int r0 = bh * 1024 + mb + wm + mt * 16 + lr;
#pragma unroll
        for (int nt = 0; nt < 8; nt++) {
            int col = nb + wn + nt * 8 + lc;
            float s, p0, p1;
            s = d[mt][nt][0] * SCALEq; p0 = s * (w0 + s * (w1 + s * w2));
            s = d[mt][nt][1] * SCALEq; p1 = s * (w0 + s * (w1 + s * w2));
            float2 o0 = {p0, p1};
            *(float2*)(attn + (size_t)r0 * 1024 + col) = o0;
            s = d[mt][nt][2] * SCALEq; p0 = s * (w0 + s * (w1 + s * w2));
            s = d[mt][nt][3] * SCALEq; p1 = s * (w0 + s * (w1 + s * w2));
            float2 o1 = {p0, p1};
            *(float2*)(attn + (size_t)(r0 + 8) * 1024 + col) = o1;
        }
    }
}

// ---------------------------------------------------------------------------
// Kernel 3: row softmax in place on attn [32768 rows x 1024].
// ---------------------------------------------------------------------------
__global__ __launch_bounds__(256) void k_softmax(float* __restrict__ attn) {
    __shared__ float red[8];
    int row = blockIdx.x;
    int tid = threadIdx.x;
    float* p = attn + (size_t)row * 1024;
    float4 v = *(const float4*)(p + tid * 4);

    float m = fmaxf(fmaxf(v.x, v.y), fmaxf(v.z, v.w));
#pragma unroll
    for (int o = 16; o; o >>= 1) m = fmaxf(m, __shfl_xor_sync(0xffffffffu, m, o));
    int wid = tid >> 5, lane = tid & 31;
    if (lane == 0) red[wid] = m;
    __syncthreads();
    if (tid == 0) {
        float mm = red[0];
#pragma unroll
        for (int i = 1; i < 8; i++) mm = fmaxf(mm, red[i]);
        red[0] = mm;
    }
    __syncthreads();
    m = red[0];
    __syncthreads();

    float4 e;
    e.x = __expf(v.x - m); e.y = __expf(v.y - m);
    e.z = __expf(v.z - m); e.w = __expf(v.w - m);
    float s = e.x + e.y + e.z + e.w;
#pragma unroll
    for (int o = 16; o; o >>= 1) s += __shfl_xor_sync(0xffffffffu, s, o);
    if (lane == 0) red[wid] = s;
    __syncthreads();
    if (tid == 0) {
        float ss = 0.f;
#pragma unroll
        for (int i = 0; i < 8; i++) ss += red[i];
        red[0] = ss;
    }
    __syncthreads();
    float invs = 1.f / red[0];

    e.x *= invs; e.y *= invs; e.z *= invs; e.w *= invs;
    *(float4*)(p + tid * 4) = e;
}

// ---------------------------------------------------------------------------
// Kernel 4: partial AV. Per (b,h,z): [128,256]@[256,64] -> g_aoP[z].
// 256 threads, 128x64 tile, FFMA2 with free row-pairs from transposed tile.
// ---------------------------------------------------------------------------
#define ATSTR 132
#define VSTR2 68
__global__ __launch_bounds__(256) void k_av(const float* __restrict__ attn) {
    extern __shared__ float sm[];
    float* At = sm;                 // [k 0..63][row 0..127] transposed
    float* Vs = sm + 64 * ATSTR;    // [k][d]
    int mb = blockIdx.x * 128;
    int bh = blockIdx.y;
    int kz = blockIdx.z << 8;       // z * 256
    int tid = threadIdx.x;
    int ty = tid >> 4, tx = tid & 15;

    u64 acc[4][4];
#pragma unroll
    for (int i = 0; i < 4; i++)
#pragma unroll
        for (int j = 0; j < 4; j++) acc[i][j] = 0ULL;

    for (int k0 = 0; k0 < 256; k0 += 64) {
        {   // fill At transposed: At[k][row]
            int row = tid >> 1;
            int c0 = (tid & 1) << 5;
            const float* ap = attn + (size_t)(bh * 1024 + mb + row) * 1024 + kz + k0 + c0;
#pragma unroll
            for (int m = 0; m < 8; m++) {
                float4 av = *(const float4*)(ap + m * 4);
                int kk = c0 + m * 4;
                At[(kk + 0) * ATSTR + row] = av.x;
                At[(kk + 1) * ATSTR + row] = av.y;
                At[(kk + 2) * ATSTR + row] = av.z;
                At[(kk + 3) * ATSTR + row] = av.w;
            }
        }
        {   // fill Vs natural: Vs[k][d]
            int vr = tid >> 2;
            int d0 = (tid & 3) << 4;
            const float* vp = g_v + (size_t)(bh * 1024 + kz + k0 + vr) * 64 + d0;
            float* vd = Vs + vr * VSTR2 + d0;
#pragma unroll
            for (int m = 0; m < 4; m++)
                *(float4*)(vd + m * 4) = *(const float4*)(vp + m * 4);
        }
        __syncthreads();

#pragma unroll 8
        for (int kk = 0; kk < 64; kk++) {
            u64x2 a01 = *(const u64x2*)(At + kk * ATSTR + ty * 8);      // rows 0-3
            u64x2 a23 = *(const u64x2*)(At + kk * ATSTR + ty * 8 + 4);  // rows 4-7
            float4 bf = *(const float4*)(Vs + kk * VSTR2 + tx * 4);
            u64 ap4[4] = {a01.x, a01.y, a23.x, a23.y};
            u64 bp4[4] = {dup2(bf.x), dup2(bf.y), dup2(bf.z), dup2(bf.w)};
#pragma unroll
            for (int i = 0; i < 4; i++)
#pragma unroll
                for (int j = 0; j < 4; j++) acc[i][j] = f2fma(ap4[i], bp4[j], acc[i][j]);
        }
        __syncthreads();
    }

    int b = bh >> 3, h = bh & 7;
    float* base = g_aoP + (size_t)blockIdx.z * (Mq * Cq);
#pragma unroll
    for (int p = 0; p < 4; p++) {
        float2 v0 = upk(acc[p][0]);
        float2 v1 = upk(acc[p][1]);
        float2 v2 = upk(acc[p][2]);
        float2 v3 = upk(acc[p][3]);
        float4 lo = {v0.x, v1.x, v2.x, v3.x};   // row 2p
        float4 hi = {v0.y, v1.y, v2.y, v3.y};   // row 2p+1
        int n0 = mb + ty * 8 + 2 * p;
        *(float4*)(base + (size_t)(b * 1024 + n0) * 512 + h * 64 + tx * 4) = lo;
        *(float4*)(base + (size_t)(b * 1024 + n0 + 1) * 512 + h * 64 + tx * 4) = hi;
    }
}

// ---------------------------------------------------------------------------
// Kernel 5: proj GEMM, K-split 4 -> g_ypP[z] partials. Grid (4,32,4).
// ---------------------------------------------------------------------------
__global__ __launch_bounds__(256) void k_proj(const float* __restrict__ Bm) {
    const int K4 = 128, Nn = 512;
    const int P = Mq * Cq;
    __shared__ float As[2][8][128];
    __shared__ float Bs[2][8][128];
    int tid = threadIdx.x;
    int bx = blockIdx.x, by = blockIdx.y, bz = blockIdx.z;
    int aRow = tid >> 1, aCol = (tid & 1) << 2;
    int bRow = tid >> 5, bCol = (tid & 31) << 2;
    int ty = tid >> 4, tx = tid & 15;

    u64 acc[8][4];
#pragma unroll
    for (int i = 0; i < 8; i++)
#pragma unroll
        for (int j = 0; j < 4; j++) acc[i][j] = 0ULL;

    const float* Ap = g_aoP + (size_t)(by * 128 + aRow) * 512 + bz * 128 + aCol;
    const float* Bp = Bm + (size_t)(bz * 128 + bRow) * Nn + bx * 128 + bCol;

    {
        float4 a0 = *(const float4*)(Ap);
        float4 a1 = *(const float4*)(Ap + P);
        float4 a2 = *(const float4*)(Ap + 2 * P);
        float4 a3 = *(const float4*)(Ap + 3 * P);
        float4 av = {a0.x + a1.x + a2.x + a3.x, a0.y + a1.y + a2.y + a3.y,
                     a0.z + a1.z + a2.z + a3.z, a0.w + a1.w + a2.w + a3.w};
        As[0][aCol + 0][aRow] = av.x;
        As[0][aCol + 1][aRow] = av.y;
        As[0][aCol + 2][aRow] = av.z;
        As[0][aCol + 3][aRow] = av.w;
        *(float4*)&Bs[0][bRow][bCol] = *(const float4*)(Bp);
    }
    __syncthreads();

    for (int k0 = 0; k0 < K4; k0 += 8) {
        int buf = (k0 >> 3) & 1;
        float4 av, bv;
        bool more = (k0 + 8) < K4;
        if (more) {
            float4 a0 = *(const float4*)(Ap + k0 + 8);
            float4 a1 = *(const float4*)(Ap + P + k0 + 8);
            float4 a2 = *(const float4*)(Ap + 2 * P + k0 + 8);
            float4 a3 = *(const float4*)(Ap + 3 * P + k0 + 8);
            av.x = a0.x + a1.x + a2.x + a3.x;
            av.y = a0.y + a1.y + a2.y + a3.y;
            av.z = a0.z + a1.z + a2.z + a3.z;
            av.w = a0.w + a1.w + a2.w + a3.w;
            bv = *(const float4*)(Bp + (size_t)(k0 + 8) * Nn);
        }
#pragma unroll
        for (int k = 0; k < 8; k++) {
            float a[8];
            *(float4*)&a[0] = *(const float4*)&As[buf][k][ty * 8];
            *(float4*)&a[4] = *(const float4*)&As[buf][k][ty * 8 + 4];
            u64x2 b0 = *(const u64x2*)&Bs[buf][k][tx * 8];
            u64x2 b1 = *(const u64x2*)&Bs[buf][k][tx * 8 + 4];
            u64 bp[4] = {b0.x, b0.y, b1.x, b1.y};
#pragma unroll
            for (int i = 0; i < 8; i++) {
                u64 ad = dup2(a[i]);
#pragma unroll
                for (int j = 0; j < 4; j++) acc[i][j] = f2fma(ad, bp[j], acc[i][j]);
            }
        }
        if (more) {
            int nb2 = buf ^ 1;
            As[nb2][aCol + 0][aRow] = av.x;
            As[nb2][aCol + 1][aRow] = av.y;
            As[nb2][aCol + 2][aRow] = av.z;
            As[nb2][aCol + 3][aRow] = av.w;
            *(float4*)&Bs[nb2][bRow][bCol] = bv;
        }
        __syncthreads();
    }

    float* yp = g_ypP + (size_t)bz * P;
#pragma unroll
    for (int i = 0; i < 8; i++) {
        int r = by * 128 + ty * 8 + i;
#pragma unroll
        for (int jp = 0; jp < 4; jp++) {
            float2 v2 = upk(acc[i][jp]);
            int c = bx * 128 + tx * 8 + jp * 2;
            yp[(size_t)r * 512 + c]     = v2.x;
            yp[(size_t)r * 512 + c + 1] = v2.y;
        }
    }
}

// ---------------------------------------------------------------------------
// Kernel 6: LayerNorm. y_pre = sum of 4 proj partials + bias + x, then LN.
// ---------------------------------------------------------------------------
__global__ __launch_bounds__(128) void k_ln(const float* __restrict__ gamma,
                                            const float* __restrict__ beta,
                                            const float* __restrict__ bias,
                                            const float* __restrict__ x,
                                            float* __restrict__ y) {
    const int P = Mq * Cq;
    __shared__ float s1[4], s2[4];
    int row = blockIdx.x;
    int tid = threadIdx.x;
    int c = tid * 4;
    const float* p = g_ypP + (size_t)row * 512 + c;
    float4 v0 = *(const float4*)(p);
    float4 v1 = *(const float4*)(p + P);
    float4 v2 = *(const float4*)(p + 2 * P);
    float4 v3 = *(const float4*)(p + 3 * P);
    float4 bb = *(const float4*)(bias + c);
    float4 xx = *(const float4*)(x + (size_t)row * 512 + c);
    float4 v;
    v.x = v0.x + v1.x + v2.x + v3.x + bb.x + xx.x;
    v.y = v0.y + v1.y + v2.y + v3.y + bb.y + xx.y;
    v.z = v0.z + v1.z + v2.z + v3.z + bb.z + xx.z;
    v.w = v0.w + v1.w + v2.w + v3.w + bb.w + xx.w;

    float s = v.x + v.y + v.z + v.w;
    float ss = v.x * v.x + v.y * v.y + v.z * v.z + v.w * v.w;
#pragma unroll
    for (int o = 16; o; o >>= 1) {
        s += __shfl_xor_sync(0xffffffffu, s, o);
        ss += __shfl_xor_sync(0xffffffffu, ss, o);
    }
    int wid = tid >> 5, lane = tid & 31;
    if (lane == 0) { s1[wid] = s; s2[wid] = ss; }
    __syncthreads();
    if (tid == 0) {
        s1[0] = s1[0] + s1[1] + s1[2] + s1[3];
        s2[0] = s2[0] + s2[1] + s2[2] + s2[3];
    }
    __syncthreads();
    float mu = s1[0] * (1.f / 512.f);
    float var = s2[0] * (1.f / 512.f) - mu * mu;
    float rstd = rsqrtf(var + LN_EPSq);

    float4 g = *(const float4*)(gamma + c);
    float4 be = *(const float4*)(beta + c);
    float4 o;
    o.x = (v.x - mu) * rstd * g.x + be.x;
    o.y = (v.y - mu) * rstd * g.y + be.y;
    o.z = (v.z - mu) * rstd * g.z + be.z;
    o.w = (v.w - mu) * rstd * g.w + be.w;
    *(float4*)(y + (size_t)row * 512 + c) = o;
}

// ---------------------------------------------------------------------------
extern "C" void kernel_launch(void* const* d_in, const int* in_sizes, int n_in,
                              void* d_out, int out_size) {
    (void)in_sizes; (void)n_in; (void)out_size;
    const float* x     = (const float*)d_in[0];
    const float* Wqkv  = (const float*)d_in[1];
    const float* bqkv  = (const float*)d_in[2];
    const float* ow    = (const float*)d_in[3];
    const float* Wproj = (const float*)d_in[4];
    const float* bproj = (const float*)d_in[5];
    const float* gamma = (const float*)d_in[6];
    const float* beta  = (const float*)d_in[7];

    float* out      = (float*)d_out;
    float* y_out    = out;                         // [4,1024,512]
    float* attn_out = out + (size_t)Bq * Nq * Cq;  // [4,8,1024,1024]

    int scores_smem = 4 * 128 * SST * 2;                               // 73728 B
    int av_smem     = (64 * ATSTR + 64 * VSTR2) * (int)sizeof(float);  // 51200 B
    cudaFuncSetAttribute(k_scores, cudaFuncAttributeMaxDynamicSharedMemorySize,
                         scores_smem);
    cudaFuncSetAttribute(k_av, cudaFuncAttributeMaxDynamicSharedMemorySize,
                         av_smem);

    k_qkv    <<<dim3(12, 32), 256>>>(x, Wqkv, bqkv);
    k_scores <<<dim3(8, 8, 32), 256, scores_smem>>>(ow, attn_out);
    k_softmax<<<32768, 256>>>(attn_out);
    k_av     <<<dim3(8, 32, 4), 256, av_smem>>>(attn_out);
    k_proj   <<<dim3(4, 32, 4), 256>>>(Wproj);
    k_ln     <<<4096, 128>>>(gamma, beta, bproj, x, y_out);
}

// round 12
// speedup vs baseline: 1.4273x; 1.0752x over previous
#include <cuda_runtime.h>
#include <cuda_bf16.h>
#include <math.h>

// Problem constants
#define Bq   4
#define Nq   1024
#define Cq   512
#define Hq   8
#define HDq  64
#define BHq  32
#define Mq   4096
#define SCALEq 0.125f
#define LN_EPSq 1e-5f

typedef unsigned long long u64;
typedef ulonglong2 u64x2;

// packed fp32x2 FMA (sm_103a)
__device__ __forceinline__ u64 f2fma(u64 a, u64 b, u64 c) {
    u64 d;
    asm("fma.rn.f32x2 %0, %1, %2, %3;" : "=l"(d) : "l"(a), "l"(b), "l"(c));
    return d;
}
__device__ __forceinline__ float2 upk(u64 v) {
    float2 r;
    asm("mov.b64 {%0, %1}, %2;" : "=f"(r.x), "=f"(r.y) : "l"(v));
    return r;
}
__device__ __forceinline__ u64 dup2(float x) {
    u64 r;
    asm("mov.b64 %0, {%1, %1};" : "=l"(r) : "f"(x));
    return r;
}

// bf16 mma.sync (baseline PTX, compiles under compute_103, runs on HMMA)
__device__ __forceinline__ void mma_bf16(float* d, const unsigned* a,
                                         const unsigned* b) {
    asm volatile(
        "mma.sync.aligned.m16n8k16.row.col.f32.bf16.bf16.f32 "
        "{%0,%1,%2,%3}, {%4,%5,%6,%7}, {%8,%9}, {%0,%1,%2,%3};"
        : "+f"(d[0]), "+f"(d[1]), "+f"(d[2]), "+f"(d[3])
        : "r"(a[0]), "r"(a[1]), "r"(a[2]), "r"(a[3]), "r"(b[0]), "r"(b[1]));
}
__device__ __forceinline__ unsigned pack_bf16x2(float a, float b) {
    unsigned short ha = __bfloat16_as_ushort(__float2bfloat16(a));
    unsigned short hb = __bfloat16_as_ushort(__float2bfloat16(b));
    return (unsigned)ha | ((unsigned)hb << 16);
}

// Scratch (device globals — allocation-free)
__device__ float g_q  [BHq * Nq * HDq];     // [bh][n][d]
__device__ float g_k  [BHq * Nq * HDq];
__device__ float g_vt [BHq * HDq * Nq];     // [bh][d][n]  (transposed V)
__device__ float g_ao [Mq * Cq];            // attention output [b*n][h*64+d]
__device__ float g_ypP[4 * Mq * Cq];        // 4 k-split partials of proj-out

// ---------------------------------------------------------------------------
// Kernel 1: QKV GEMM. x[4096,512] @ Wqkv[512,1536] + bqkv -> scatter q/k/vt
// 128x128x8 tiles, 256 threads, 8x8/thread, double-buffered, FFMA2 inner.
// ---------------------------------------------------------------------------
__global__ __launch_bounds__(256) void k_qkv(const float* __restrict__ A,
                                             const float* __restrict__ Bm,
                                             const float* __restrict__ bias) {
    const int K = 512, Nn = 1536;
    __shared__ float As[2][8][128];
    __shared__ float Bs[2][8][128];
    int tid = threadIdx.x;
    int bx = blockIdx.x, by = blockIdx.y;
    int aRow = tid >> 1, aCol = (tid & 1) << 2;
    int bRow = tid >> 5, bCol = (tid & 31) << 2;
    int ty = tid >> 4, tx = tid & 15;

    u64 acc[8][4];
#pragma unroll
    for (int i = 0; i < 8; i++)
#pragma unroll
        for (int j = 0; j < 4; j++) acc[i][j] = 0ULL;

    const float* Ap = A + (size_t)(by * 128 + aRow) * K + aCol;
    const float* Bp = Bm + (size_t)bRow * Nn + bx * 128 + bCol;

    {
        float4 av = *(const float4*)(Ap);
        As[0][aCol + 0][aRow] = av.x;
        As[0][aCol + 1][aRow] = av.y;
        As[0][aCol + 2][aRow] = av.z;
        As[0][aCol + 3][aRow] = av.w;
        *(float4*)&Bs[0][bRow][bCol] = *(const float4*)(Bp);
    }
    __syncthreads();

    for (int k0 = 0; k0 < K; k0 += 8) {
        int buf = (k0 >> 3) & 1;
        float4 av, bv;
        bool more = (k0 + 8) < K;
        if (more) {
            av = *(const float4*)(Ap + k0 + 8);
            bv = *(const float4*)(Bp + (size_t)(k0 + 8) * Nn);
        }
#pragma unroll
        for (int k = 0; k < 8; k++) {
            float a[8];
            *(float4*)&a[0] = *(const float4*)&As[buf][k][ty * 8];
            *(float4*)&a[4] = *(const float4*)&As[buf][k][ty * 8 + 4];
            u64x2 b0 = *(const u64x2*)&Bs[buf][k][tx * 8];
            u64x2 b1 = *(const u64x2*)&Bs[buf][k][tx * 8 + 4];
            u64 bp[4] = {b0.x, b0.y, b1.x, b1.y};
#pragma unroll
            for (int i = 0; i < 8; i++) {
                u64 ad = dup2(a[i]);
#pragma unroll
                for (int j = 0; j < 4; j++) acc[i][j] = f2fma(ad, bp[j], acc[i][j]);
            }
        }
        if (more) {
            int nb = buf ^ 1;
            As[nb][aCol + 0][aRow] = av.x;
            As[nb][aCol + 1][aRow] = av.y;
            As[nb][aCol + 2][aRow] = av.z;
            As[nb][aCol + 3][aRow] = av.w;
            *(float4*)&Bs[nb][bRow][bCol] = bv;
        }
        __syncthreads();
    }

#pragma unroll
    for (int i = 0; i < 8; i++) {
        int r = by * 128 + ty * 8 + i;
        int bb = r >> 10, n = r & 1023;
#pragma unroll
        for (int jp = 0; jp < 4; jp++) {
            float2 v2 = upk(acc[i][jp]);
            float vv[2] = {v2.x, v2.y};
#pragma unroll
            for (int l = 0; l < 2; l++) {
                int c = bx * 128 + tx * 8 + jp * 2 + l;
                float v = vv[l] + bias[c];
                int sel = c >> 9;
                int rem = c & 511;
                int h = rem >> 6, d = rem & 63;
                int bh = bb * 8 + h;
                if (sel == 0)      g_q [((size_t)bh * 1024 + n) * 64 + d] = v;
                else if (sel == 1) g_k [((size_t)bh * 1024 + n) * 64 + d] = v;
                else               g_vt[((size_t)bh * 64 + d) * 1024 + n] = v;
            }
        }
    }
}

// ---------------------------------------------------------------------------
// Kernel 2: scores via tensor cores (mma.sync bf16x3 split precision).
// 128x128 tile per block per bh, 256 threads (8 warps, each 32x64 outputs).
// ---------------------------------------------------------------------------
#define SST 72   // bf16 elements per smem row (144 B, conflict-free)
__global__ __launch_bounds__(256) void k_scores(const float* __restrict__ ow_in,
                                                float* __restrict__ attn) {
    extern __shared__ char smc[];
    unsigned short* Qh = (unsigned short*)smc;
    unsigned short* Ql = Qh + 128 * SST;
    unsigned short* Kh = Ql + 128 * SST;
    unsigned short* Kl = Kh + 128 * SST;

    int bh = blockIdx.z;
    int mb = blockIdx.y * 128;
    int nb = blockIdx.x * 128;
    int tid = threadIdx.x;

    const float* qbase = g_q + (size_t)(bh * 1024 + mb) * 64;
    const float* kbase = g_k + (size_t)(bh * 1024 + nb) * 64;
#pragma unroll
    for (int i = 0; i < 16; i++) {
        int p = tid + i * 256;
        int row = p >> 5;
        int col = (p & 31) << 1;
        float2 qv = *(const float2*)(qbase + row * 64 + col);
        float2 kv = *(const float2*)(kbase + row * 64 + col);
        float qhx = __bfloat162float(__float2bfloat16(qv.x));
        float qhy = __bfloat162float(__float2bfloat16(qv.y));
        float khx = __bfloat162float(__float2bfloat16(kv.x));
        float khy = __bfloat162float(__float2bfloat16(kv.y));
        int off = row * SST + col;
        *(unsigned*)(Qh + off) = pack_bf16x2(qhx, qhy);
        *(unsigned*)(Ql + off) = pack_bf16x2(qv.x - qhx, qv.y - qhy);
        *(unsigned*)(Kh + off) = pack_bf16x2(khx, khy);
        *(unsigned*)(Kl + off) = pack_bf16x2(kv.x - khx, kv.y - khy);
    }
    __syncthreads();

    int w = tid >> 5, lane = tid & 31;
    int wm = (w >> 1) * 32;
    int wn = (w & 1) * 64;
    int lr = lane >> 2;
    int lc = (lane & 3) << 1;

    float d[2][8][4];
#pragma unroll
    for (int mt = 0; mt < 2; mt++)
#pragma unroll
        for (int nt = 0; nt < 8; nt++)
#pragma unroll
            for (int j = 0; j < 4; j++) d[mt][nt][j] = 0.f;

#pragma unroll
    for (int k0 = 0; k0 < 64; k0 += 16) {
        unsigned ah[2][4], al[2][4], bb[8][2];
#pragma unroll
        for (int mt = 0; mt < 2; mt++) {
            int r0 = (wm + mt * 16 + lr) * SST + k0 + lc;
            int r1 = (wm + mt * 16 + lr + 8) * SST + k0 + lc;
            ah[mt][0] = *(const unsigned*)(Qh + r0);
            ah[mt][1] = *(const unsigned*)(Qh + r1);
            ah[mt][2] = *(const unsigned*)(Qh + r0 + 8);
            ah[mt][3] = *(const unsigned*)(Qh + r1 + 8);
            al[mt][0] = *(const unsigned*)(Ql + r0);
            al[mt][1] = *(const unsigned*)(Ql + r1);
            al[mt][2] = *(const unsigned*)(Ql + r0 + 8);
            al[mt][3] = *(const unsigned*)(Ql + r1 + 8);
        }
#pragma unroll
        for (int nt = 0; nt < 8; nt++) {
            int rn = (wn + nt * 8 + lr) * SST + k0 + lc;
            bb[nt][0] = *(const unsigned*)(Kh + rn);
            bb[nt][1] = *(const unsigned*)(Kh + rn + 8);
        }
#pragma unroll
        for (int mt = 0; mt < 2; mt++)
#pragma unroll
            for (int nt = 0; nt < 8; nt++) mma_bf16(d[mt][nt], ah[mt], bb[nt]);
#pragma unroll
        for (int mt = 0; mt < 2; mt++)
#pragma unroll
            for (int nt = 0; nt < 8; nt++) mma_bf16(d[mt][nt], al[mt], bb[nt]);
#pragma unroll
        for (int nt = 0; nt < 8; nt++) {
            int rn = (wn + nt * 8 + lr) * SST + k0 + lc;
            bb[nt][0] = *(const unsigned*)(Kl + rn);
            bb[nt][1] = *(const unsigned*)(Kl + rn + 8);
        }
#pragma unroll
        for (int mt = 0; mt < 2; mt++)
#pragma unroll
            for (int nt = 0; nt < 8; nt++) mma_bf16(d[mt][nt], ah[mt], bb[nt]);
    }

    float w0 = ow_in[0], w1 = ow_in[1], w2 = ow_in[2];
    float mw = fmaxf(w0, fmaxf(w1, w2));
    float e0 = __expf(w0 - mw), e1 = __expf(w1 - mw), e2 = __expf(w2 - mw);
    float inv = 1.f / (e0 + e1 + e2);
    w0 = e0 * inv; w1 = e1 * inv; w2 = e2 * inv;

#pragma unroll
    for (int mt = 0; mt < 2; mt++) {
        int r0 = bh * 1024 + mb + wm + mt * 16 + lr;
#pragma unroll
        for (int nt = 0; nt < 8; nt++) {
            int col = nb + wn + nt * 8 + lc;
            float s, p0, p1;
            s = d[mt][nt][0] * SCALEq; p0 = s * (w0 + s * (w1 + s * w2));
            s = d[mt][nt][1] * SCALEq; p1 = s * (w0 + s * (w1 + s * w2));
            float2 o0 = {p0, p1};
            *(float2*)(attn + (size_t)r0 * 1024 + col) = o0;
            s = d[mt][nt][2] * SCALEq; p0 = s * (w0 + s * (w1 + s * w2));
            s = d[mt][nt][3] * SCALEq; p1 = s * (w0 + s * (w1 + s * w2));
            float2 o1 = {p0, p1};
            *(float2*)(attn + (size_t)(r0 + 8) * 1024 + col) = o1;
        }
    }
}

// ---------------------------------------------------------------------------
// Kernel 3: row softmax in place on attn [32768 rows x 1024].
// ---------------------------------------------------------------------------
__global__ __launch_bounds__(256) void k_softmax(float* __restrict__ attn) {
    __shared__ float red[8];
    int row = blockIdx.x;
    int tid = threadIdx.x;
    float* p = attn + (size_t)row * 1024;
    float4 v = *(const float4*)(p + tid * 4);

    float m = fmaxf(fmaxf(v.x, v.y), fmaxf(v.z, v.w));
#pragma unroll
    for (int o = 16; o; o >>= 1) m = fmaxf(m, __shfl_xor_sync(0xffffffffu, m, o));
    int wid = tid >> 5, lane = tid & 31;
    if (lane == 0) red[wid] = m;
    __syncthreads();
    if (tid == 0) {
        float mm = red[0];
#pragma unroll
        for (int i = 1; i < 8; i++) mm = fmaxf(mm, red[i]);
        red[0] = mm;
    }
    __syncthreads();
    m = red[0];
    __syncthreads();

    float4 e;
    e.x = __expf(v.x - m); e.y = __expf(v.y - m);
    e.z = __expf(v.z - m); e.w = __expf(v.w - m);
    float s = e.x + e.y + e.z + e.w;
#pragma unroll
    for (int o = 16; o; o >>= 1) s += __shfl_xor_sync(0xffffffffu, s, o);
    if (lane == 0) red[wid] = s;
    __syncthreads();
    if (tid == 0) {
        float ss = 0.f;
#pragma unroll
        for (int i = 0; i < 8; i++) ss += red[i];
        red[0] = ss;
    }
    __syncthreads();
    float invs = 1.f / red[0];

    e.x *= invs; e.y *= invs; e.z *= invs; e.w *= invs;
    *(float4*)(p + tid * 4) = e;
}

// ---------------------------------------------------------------------------
// Kernel 4: AV via tensor cores (mma.sync bf16x3). Per (bh, mtile):
// O[128,64] = attn[128,1024] @ V[1024,64]; B operand from g_vt [d][n].
// 256 threads = 8 warps, each warp 16 rows x 64 cols. k-loop: 16 chunks of 64.
// ---------------------------------------------------------------------------
__global__ __launch_bounds__(256) void k_av(const float* __restrict__ attn) {
    extern __shared__ char smc[];
    unsigned short* Ahh = (unsigned short*)smc;          // [128][SST]
    unsigned short* All = Ahh + 128 * SST;
    unsigned short* Bhh = All + 128 * SST;               // [64][SST]
    unsigned short* Bll = Bhh + 64 * SST;

    int mb = blockIdx.x * 128;
    int bh = blockIdx.y;
    int tid = threadIdx.x;
    int w = tid >> 5, lane = tid & 31;
    int wm = w * 16;
    int lr = lane >> 2;
    int lc = (lane & 3) << 1;

    float d[8][4];
#pragma unroll
    for (int nt = 0; nt < 8; nt++)
#pragma unroll
        for (int j = 0; j < 4; j++) d[nt][j] = 0.f;

    const float* abase = attn + (size_t)(bh * 1024 + mb) * 1024;
    const float* bbase = g_vt + (size_t)bh * 64 * 1024;

    for (int ch = 0; ch < 16; ch++) {
        // stage A: attn rows [0,128) x k [ch*64, ch*64+64) as hi/lo bf16
#pragma unroll
        for (int i = 0; i < 16; i++) {
            int p = tid + i * 256;
            int row = p >> 5;
            int col = (p & 31) << 1;
            float2 av = *(const float2*)(abase + (size_t)row * 1024 + ch * 64 + col);
            float ahx = __bfloat162float(__float2bfloat16(av.x));
            float ahy = __bfloat162float(__float2bfloat16(av.y));
            int off = row * SST + col;
            *(unsigned*)(Ahh + off) = pack_bf16x2(ahx, ahy);
            *(unsigned*)(All + off) = pack_bf16x2(av.x - ahx, av.y - ahy);
        }
        // stage B: Vt rows d [0,64) x k [ch*64, +64)
#pragma unroll
        for (int i = 0; i < 8; i++) {
            int p = tid + i * 256;
            int row = p >> 5;
            int col = (p & 31) << 1;
            float2 bv = *(const float2*)(bbase + (size_t)row * 1024 + ch * 64 + col);
            float bhx = __bfloat162float(__float2bfloat16(bv.x));
            float bhy = __bfloat162float(__float2bfloat16(bv.y));
            int off = row * SST + col;
            *(unsigned*)(Bhh + off) = pack_bf16x2(bhx, bhy);
            *(unsigned*)(Bll + off) = pack_bf16x2(bv.x - bhx, bv.y - bhy);
        }
        __syncthreads();

#pragma unroll
        for (int k0 = 0; k0 < 64; k0 += 16) {
            unsigned ah[4], al[4], bb[8][2];
            int r0 = (wm + lr) * SST + k0 + lc;
            int r1 = (wm + lr + 8) * SST + k0 + lc;
            ah[0] = *(const unsigned*)(Ahh + r0);
            ah[1] = *(const unsigned*)(Ahh + r1);
            ah[2] = *(const unsigned*)(Ahh + r0 + 8);
            ah[3] = *(const unsigned*)(Ahh + r1 + 8);
            al[0] = *(const unsigned*)(All + r0);
            al[1] = *(const unsigned*)(All + r1);
            al[2] = *(const unsigned*)(All + r0 + 8);
            al[3] = *(const unsigned*)(All + r1 + 8);
#pragma unroll
            for (int nt = 0; nt < 8; nt++) {
                int rn = (nt * 8 + lr) * SST + k0 + lc;
                bb[nt][0] = *(const unsigned*)(Bhh + rn);
                bb[nt][1] = *(const unsigned*)(Bhh + rn + 8);
            }
#pragma unroll
            for (int nt = 0; nt < 8; nt++) mma_bf16(d[nt], ah, bb[nt]);
#pragma unroll
            for (int nt = 0; nt < 8; nt++) mma_bf16(d[nt], al, bb[nt]);
#pragma unroll
            for (int nt = 0; nt < 8; nt++) {
                int rn = (nt * 8 + lr) * SST + k0 + lc;
                bb[nt][0] = *(const unsigned*)(Bll + rn);
                bb[nt][1] = *(const unsigned*)(Bll + rn + 8);
            }
#pragma unroll
            for (int nt = 0; nt < 8; nt++) mma_bf16(d[nt], ah, bb[nt]);
        }
        __syncthreads();
    }

    int b = bh >> 3, h = bh & 7;
    int n0 = mb + wm + lr;
#pragma unroll
    for (int nt = 0; nt < 8; nt++) {
        int col = h * 64 + nt * 8 + lc;
        float2 o0 = {d[nt][0], d[nt][1]};
        float2 o1 = {d[nt][2], d[nt][3]};
        *(float2*)(g_ao + (size_t)(b * 1024 + n0) * 512 + col) = o0;
        *(float2*)(g_ao + (size_t)(b * 1024 + n0 + 8) * 512 + col) = o1;
    }
}

// ---------------------------------------------------------------------------
// Kernel 5: proj GEMM, K-split 4 -> g_ypP[z] partials. Grid (4,32,4).
// ---------------------------------------------------------------------------
__global__ __launch_bounds__(256) void k_proj(const float* __restrict__ Bm) {
    const int K4 = 128, Nn = 512;
    const int P = Mq * Cq;
    __shared__ float As[2][8][128];
    __shared__ float Bs[2][8][128];
    int tid = threadIdx.x;
    int bx = blockIdx.x, by = blockIdx.y, bz = blockIdx.z;
    int aRow = tid >> 1, aCol = (tid & 1) << 2;
    int bRow = tid >> 5, bCol = (tid & 31) << 2;
    int ty = tid >> 4, tx = tid & 15;

    u64 acc[8][4];
#pragma unroll
    for (int i = 0; i < 8; i++)
#pragma unroll
        for (int j = 0; j < 4; j++) acc[i][j] = 0ULL;

    const float* Ap = g_ao + (size_t)(by * 128 + aRow) * 512 + bz * 128 + aCol;
    const float* Bp = Bm + (size_t)(bz * 128 + bRow) * Nn + bx * 128 + bCol;

    {
        float4 av = *(const float4*)(Ap);
        As[0][aCol + 0][aRow] = av.x;
        As[0][aCol + 1][aRow] = av.y;
        As[0][aCol + 2][aRow] = av.z;
        As[0][aCol + 3][aRow] = av.w;
        *(float4*)&Bs[0][bRow][bCol] = *(const float4*)(Bp);
    }
    __syncthreads();

    for (int k0 = 0; k0 < K4; k0 += 8) {
        int buf = (k0 >> 3) & 1;
        float4 av, bv;
        bool more = (k0 + 8) < K4;
        if (more) {
            av = *(const float4*)(Ap + k0 + 8);
            bv = *(const float4*)(Bp + (size_t)(k0 + 8) * Nn);
        }
#pragma unroll
        for (int k = 0; k < 8; k++) {
            float a[8];
            *(float4*)&a[0] = *(const float4*)&As[buf][k][ty * 8];
            *(float4*)&a[4] = *(const float4*)&As[buf][k][ty * 8 + 4];
            u64x2 b0 = *(const u64x2*)&Bs[buf][k][tx * 8];
            u64x2 b1 = *(const u64x2*)&Bs[buf][k][tx * 8 + 4];
            u64 bp[4] = {b0.x, b0.y, b1.x, b1.y};
#pragma unroll
            for (int i = 0; i < 8; i++) {
                u64 ad = dup2(a[i]);
#pragma unroll
                for (int j = 0; j < 4; j++) acc[i][j] = f2fma(ad, bp[j], acc[i][j]);
            }
        }
        if (more) {
            int nb2 = buf ^ 1;
            As[nb2][aCol + 0][aRow] = av.x;
            As[nb2][aCol + 1][aRow] = av.y;
            As[nb2][aCol + 2][aRow] = av.z;
            As[nb2][aCol + 3][aRow] = av.w;
            *(float4*)&Bs[nb2][bRow][bCol] = bv;
        }
        __syncthreads();
    }

    float* yp = g_ypP + (size_t)bz * P;
#pragma unroll
    for (int i = 0; i < 8; i++) {
        int r = by * 128 + ty * 8 + i;
#pragma unroll
        for (int jp = 0; jp < 4; jp++) {
            float2 v2 = upk(acc[i][jp]);
            int c = bx * 128 + tx * 8 + jp * 2;
            yp[(size_t)r * 512 + c]     = v2.x;
            yp[(size_t)r * 512 + c + 1] = v2.y;
        }
    }
}

// ---------------------------------------------------------------------------
// Kernel 6: LayerNorm. y_pre = sum of 4 proj partials + bias + x, then LN.
// ---------------------------------------------------------------------------
__global__ __launch_bounds__(128) void k_ln(const float* __restrict__ gamma,
                                            const float* __restrict__ beta,
                                            const float* __restrict__ bias,
                                            const float* __restrict__ x,
                                            float* __restrict__ y) {
    const int P = Mq * Cq;
    __shared__ float s1[4], s2[4];
    int row = blockIdx.x;
    int tid = threadIdx.x;
    int c = tid * 4;
    const float* p = g_ypP + (size_t)row * 512 + c;
    float4 v0 = *(const float4*)(p);
    float4 v1 = *(const float4*)(p + P);
    float4 v2 = *(const float4*)(p + 2 * P);
    float4 v3 = *(const float4*)(p + 3 * P);
    float4 bb = *(const float4*)(bias + c);
    float4 xx = *(const float4*)(x + (size_t)row * 512 + c);
    float4 v;
    v.x = v0.x + v1.x + v2.x + v3.x + bb.x + xx.x;
    v.y = v0.y + v1.y + v2.y + v3.y + bb.y + xx.y;
    v.z = v0.z + v1.z + v2.z + v3.z + bb.z + xx.z;
    v.w = v0.w + v1.w + v2.w + v3.w + bb.w + xx.w;

    float s = v.x + v.y + v.z + v.w;
    float ss = v.x * v.x + v.y * v.y + v.z * v.z + v.w * v.w;
#pragma unroll
    for (int o = 16; o; o >>= 1) {
        s += __shfl_xor_sync(0xffffffffu, s, o);
        ss += __shfl_xor_sync(0xffffffffu, ss, o);
    }
    int wid = tid >> 5, lane = tid & 31;
    if (lane == 0) { s1[wid] = s; s2[wid] = ss; }
    __syncthreads();
    if (tid == 0) {
        s1[0] = s1[0] + s1[1] + s1[2] + s1[3];
        s2[0] = s2[0] + s2[1] + s2[2] + s2[3];
    }
    __syncthreads();
    float mu = s1[0] * (1.f / 512.f);
    float var = s2[0] * (1.f / 512.f) - mu * mu;
    float rstd = rsqrtf(var + LN_EPSq);

    float4 g = *(const float4*)(gamma + c);
    float4 be = *(const float4*)(beta + c);
    float4 o;
    o.x = (v.x - mu) * rstd * g.x + be.x;
    o.y = (v.y - mu) * rstd * g.y + be.y;
    o.z = (v.z - mu) * rstd * g.z + be.z;
    o.w = (v.w - mu) * rstd * g.w + be.w;
    *(float4*)(y + (size_t)row * 512 + c) = o;
}

// ---------------------------------------------------------------------------
extern "C" void kernel_launch(void* const* d_in, const int* in_sizes, int n_in,
                              void* d_out, int out_size) {
    (void)in_sizes; (void)n_in; (void)out_size;
    const float* x     = (const float*)d_in[0];
    const float* Wqkv  = (const float*)d_in[1];
    const float* bqkv  = (const float*)d_in[2];
    const float* ow    = (const float*)d_in[3];
    const float* Wproj = (const float*)d_in[4];
    const float* bproj = (const float*)d_in[5];
    const float* gamma = (const float*)d_in[6];
    const float* beta  = (const float*)d_in[7];

    float* out      = (float*)d_out;
    float* y_out    = out;                         // [4,1024,512]
    float* attn_out = out + (size_t)Bq * Nq * Cq;  // [4,8,1024,1024]

    int scores_smem = 4 * 128 * SST * 2;                     // 73728 B
    int av_smem     = (2 * 128 * SST + 2 * 64 * SST) * 2;    // 55296 B
    cudaFuncSetAttribute(k_scores, cudaFuncAttributeMaxDynamicSharedMemorySize,
                         scores_smem);
    cudaFuncSetAttribute(k_av, cudaFuncAttributeMaxDynamicSharedMemorySize,
                         av_smem);

    k_qkv    <<<dim3(12, 32), 256>>>(x, Wqkv, bqkv);
    k_scores <<<dim3(8, 8, 32), 256, scores_smem>>>(ow, attn_out);
    k_softmax<<<32768, 256>>>(attn_out);
    k_av     <<<dim3(8, 32), 256, av_smem>>>(attn_out);
    k_proj   <<<dim3(4, 32, 4), 256>>>(Wproj);
    k_ln     <<<4096, 128>>>(gamma, beta, bproj, x, y_out);
}

// round 13
// speedup vs baseline: 1.5094x; 1.0575x over previous
#include <cuda_runtime.h>
#include <cuda_bf16.h>
#include <math.h>

// Problem constants
#define Bq   4
#define Nq   1024
#define Cq   512
#define Hq   8
#define HDq  64
#define BHq  32
#define Mq   4096
#define SCALEq 0.125f
#define LN_EPSq 1e-5f

typedef unsigned long long u64;
typedef ulonglong2 u64x2;

// packed fp32x2 FMA (sm_103a)
__device__ __forceinline__ u64 f2fma(u64 a, u64 b, u64 c) {
    u64 d;
    asm("fma.rn.f32x2 %0, %1, %2, %3;" : "=l"(d) : "l"(a), "l"(b), "l"(c));
    return d;
}
__device__ __forceinline__ float2 upk(u64 v) {
    float2 r;
    asm("mov.b64 {%0, %1}, %2;" : "=f"(r.x), "=f"(r.y) : "l"(v));
    return r;
}
__device__ __forceinline__ u64 dup2(float x) {
    u64 r;
    asm("mov.b64 %0, {%1, %1};" : "=l"(r) : "f"(x));
    return r;
}

// bf16 mma.sync (baseline PTX, compiles under compute_103, runs on HMMA)
__device__ __forceinline__ void mma_bf16(float* d, const unsigned* a,
                                         const unsigned* b) {
    asm volatile(
        "mma.sync.aligned.m16n8k16.row.col.f32.bf16.bf16.f32 "
        "{%0,%1,%2,%3}, {%4,%5,%6,%7}, {%8,%9}, {%0,%1,%2,%3};"
        : "+f"(d[0]), "+f"(d[1]), "+f"(d[2]), "+f"(d[3])
        : "r"(a[0]), "r"(a[1]), "r"(a[2]), "r"(a[3]), "r"(b[0]), "r"(b[1]));
}
__device__ __forceinline__ unsigned pack_bf16x2(float a, float b) {
    unsigned short ha = __bfloat16_as_ushort(__float2bfloat16(a));
    unsigned short hb = __bfloat16_as_ushort(__float2bfloat16(b));
    return (unsigned)ha | ((unsigned)hb << 16);
}

// Scratch (device globals — allocation-free)
__device__ float g_q  [BHq * Nq * HDq];     // [bh][n][d]
__device__ float g_k  [BHq * Nq * HDq];
__device__ float g_vt [BHq * HDq * Nq];     // [bh][d][n]  (transposed V)
__device__ float g_ao [Mq * Cq];            // attention output [b*n][h*64+d]
__device__ float g_ypP[4 * Mq * Cq];        // 4 k-split partials of proj-out

#define SST 72   // bf16 elements per smem row (144 B, conflict-free frags)

// ---------------------------------------------------------------------------
// Kernel 1: QKV GEMM via tensor cores (mma.sync bf16x3).
// x[4096,512] @ Wqkv[512,1536] + bqkv -> scatter q/k/vt.
// 128x128 tile per block, 256 threads (8 warps: 2 mtiles x 8 ntiles each).
// B (Wqkv) staged TRANSPOSED to [n][k] for the col-major B fragment.
// ---------------------------------------------------------------------------
__global__ __launch_bounds__(256) void k_qkv(const float* __restrict__ A,
                                             const float* __restrict__ Bm,
                                             const float* __restrict__ bias) {
    extern __shared__ char smc[];
    unsigned short* Ah = (unsigned short*)smc;      // [128][SST]
    unsigned short* Al = Ah + 128 * SST;
    unsigned short* Bh = Al + 128 * SST;            // [128][SST] (n-major)
    unsigned short* Bl = Bh + 128 * SST;

    const int K = 512, Nn = 1536;
    int bx = blockIdx.x, by = blockIdx.y;
    int tid = threadIdx.x;
    int w = tid >> 5, lane = tid & 31;
    int wm = (w >> 1) * 32;
    int wn = (w & 1) * 64;
    int lr = lane >> 2;
    int lc = (lane & 3) << 1;

    float d[2][8][4];
#pragma unroll
    for (int mt = 0; mt < 2; mt++)
#pragma unroll
        for (int nt = 0; nt < 8; nt++)
#pragma unroll
            for (int j = 0; j < 4; j++) d[mt][nt][j] = 0.f;

    for (int ch = 0; ch < 8; ch++) {
        // stage A: x rows [by*128, +128) x k [ch*64, +64), hi/lo bf16
#pragma unroll
        for (int i = 0; i < 16; i++) {
            int p = tid + i * 256;
            int row = p >> 5;
            int col = (p & 31) << 1;
            float2 av = *(const float2*)(A + (size_t)(by * 128 + row) * K + ch * 64 + col);
            float ahx = __bfloat162float(__float2bfloat16(av.x));
            float ahy = __bfloat162float(__float2bfloat16(av.y));
            int off = row * SST + col;
            *(unsigned*)(Ah + off) = pack_bf16x2(ahx, ahy);
            *(unsigned*)(Al + off) = pack_bf16x2(av.x - ahx, av.y - ahy);
        }
        // stage B transposed: Wqkv[k][n] -> Bh/Bl[n][k]
#pragma unroll
        for (int i = 0; i < 16; i++) {
            int p = tid + i * 256;           // 0..4095
            int kk = p >> 6;                 // 0..63
            int nn = (p & 63) << 1;          // 0..126 even
            float2 bv = *(const float2*)(Bm + (size_t)(ch * 64 + kk) * Nn + bx * 128 + nn);
            float bhx = __bfloat162float(__float2bfloat16(bv.x));
            float bhy = __bfloat162float(__float2bfloat16(bv.y));
            Bh[nn * SST + kk]       = __bfloat16_as_ushort(__float2bfloat16(bhx));
            Bh[(nn + 1) * SST + kk] = __bfloat16_as_ushort(__float2bfloat16(bhy));
            Bl[nn * SST + kk]       = __bfloat16_as_ushort(__float2bfloat16(bv.x - bhx));
            Bl[(nn + 1) * SST + kk] = __bfloat16_as_ushort(__float2bfloat16(bv.y - bhy));
        }
        __syncthreads();

#pragma unroll
        for (int k0 = 0; k0 < 64; k0 += 16) {
            unsigned ah[2][4], al[2][4], bb[8][2];
#pragma unroll
            for (int mt = 0; mt < 2; mt++) {
                int r0 = (wm + mt * 16 + lr) * SST + k0 + lc;
                int r1 = (wm + mt * 16 + lr + 8) * SST + k0 + lc;
                ah[mt][0] = *(const unsigned*)(Ah + r0);
                ah[mt][1] = *(const unsigned*)(Ah + r1);
                ah[mt][2] = *(const unsigned*)(Ah + r0 + 8);
                ah[mt][3] = *(const unsigned*)(Ah + r1 + 8);
                al[mt][0] = *(const unsigned*)(Al + r0);
                al[mt][1] = *(const unsigned*)(Al + r1);
                al[mt][2] = *(const unsigned*)(Al + r0 + 8);
                al[mt][3] = *(const unsigned*)(Al + r1 + 8);
            }
#pragma unroll
            for (int nt = 0; nt < 8; nt++) {
                int rn = (wn + nt * 8 + lr) * SST + k0 + lc;
                bb[nt][0] = *(const unsigned*)(Bh + rn);
                bb[nt][1] = *(const unsigned*)(Bh + rn + 8);
            }
#pragma unroll
            for (int mt = 0; mt < 2; mt++)
#pragma unroll
                for (int nt = 0; nt < 8; nt++) mma_bf16(d[mt][nt], ah[mt], bb[nt]);
#pragma unroll
            for (int mt = 0; mt < 2; mt++)
#pragma unroll
                for (int nt = 0; nt < 8; nt++) mma_bf16(d[mt][nt], al[mt], bb[nt]);
#pragma unroll
            for (int nt = 0; nt < 8; nt++) {
                int rn = (wn + nt * 8 + lr) * SST + k0 + lc;
                bb[nt][0] = *(const unsigned*)(Bl + rn);
                bb[nt][1] = *(const unsigned*)(Bl + rn + 8);
            }
#pragma unroll
            for (int mt = 0; mt < 2; mt++)
#pragma unroll
                for (int nt = 0; nt < 8; nt++) mma_bf16(d[mt][nt], ah[mt], bb[nt]);
        }
        __syncthreads();
    }

    // epilogue: bias + scatter to q/k/vt
#pragma unroll
    for (int mt = 0; mt < 2; mt++) {
#pragma unroll
        for (int rr = 0; rr < 2; rr++) {
            int r = by * 128 + wm + mt * 16 + lr + rr * 8;
            int bb2 = r >> 10, n = r & 1023;
#pragma unroll
            for (int nt = 0; nt < 8; nt++) {
#pragma unroll
                for (int cc = 0; cc < 2; cc++) {
                    int c = bx * 128 + wn + nt * 8 + lc + cc;
                    float v = d[mt][nt][rr * 2 + cc] + bias[c];
                    int sel = c >> 9;
                    int rem = c & 511;
                    int h = rem >> 6, dd = rem & 63;
                    int bh = bb2 * 8 + h;
                    if (sel == 0)      g_q [((size_t)bh * 1024 + n) * 64 + dd] = v;
                    else if (sel == 1) g_k [((size_t)bh * 1024 + n) * 64 + dd] = v;
                    else               g_vt[((size_t)bh * 64 + dd) * 1024 + n] = v;
                }
            }
        }
    }
}

// ---------------------------------------------------------------------------
// Kernel 2: scores via tensor cores (mma.sync bf16x3 split precision).
// ---------------------------------------------------------------------------
__global__ __launch_bounds__(256) void k_scores(const float* __restrict__ ow_in,
                                                float* __restrict__ attn) {
    extern __shared__ char smc[];
    unsigned short* Qh = (unsigned short*)smc;
    unsigned short* Ql = Qh + 128 * SST;
    unsigned short* Kh = Ql + 128 * SST;
    unsigned short* Kl = Kh + 128 * SST;

    int bh = blockIdx.z;
    int mb = blockIdx.y * 128;
    int nb = blockIdx.x * 128;
    int tid = threadIdx.x;

    const float* qbase = g_q + (size_t)(bh * 1024 + mb) * 64;
    const float* kbase = g_k + (size_t)(bh * 1024 + nb) * 64;
#pragma unroll
    for (int i = 0; i < 16; i++) {
        int p = tid + i * 256;
        int row = p >> 5;
        int col = (p & 31) << 1;
        float2 qv = *(const float2*)(qbase + row * 64 + col);
        float2 kv = *(const float2*)(kbase + row * 64 + col);
        float qhx = __bfloat162float(__float2bfloat16(qv.x));
        float qhy = __bfloat162float(__float2bfloat16(qv.y));
        float khx = __bfloat162float(__float2bfloat16(kv.x));
        float khy = __bfloat162float(__float2bfloat16(kv.y));
        int off = row * SST + col;
        *(unsigned*)(Qh + off) = pack_bf16x2(qhx, qhy);
        *(unsigned*)(Ql + off) = pack_bf16x2(qv.x - qhx, qv.y - qhy);
        *(unsigned*)(Kh + off) = pack_bf16x2(khx, khy);
        *(unsigned*)(Kl + off) = pack_bf16x2(kv.x - khx, kv.y - khy);
    }
    __syncthreads();

    int w = tid >> 5, lane = tid & 31;
    int wm = (w >> 1) * 32;
    int wn = (w & 1) * 64;
    int lr = lane >> 2;
    int lc = (lane & 3) << 1;

    float d[2][8][4];
#pragma unroll
    for (int mt = 0; mt < 2; mt++)
#pragma unroll
        for (int nt = 0; nt < 8; nt++)
#pragma unroll
            for (int j = 0; j < 4; j++) d[mt][nt][j] = 0.f;

#pragma unroll
    for (int k0 = 0; k0 < 64; k0 += 16) {
        unsigned ah[2][4], al[2][4], bb[8][2];
#pragma unroll
        for (int mt = 0; mt < 2; mt++) {
            int r0 = (wm + mt * 16 + lr) * SST + k0 + lc;
            int r1 = (wm + mt * 16 + lr + 8) * SST + k0 + lc;
            ah[mt][0] = *(const unsigned*)(Qh + r0);
            ah[mt][1] = *(const unsigned*)(Qh + r1);
            ah[mt][2] = *(const unsigned*)(Qh + r0 + 8);
            ah[mt][3] = *(const unsigned*)(Qh + r1 + 8);
            al[mt][0] = *(const unsigned*)(Ql + r0);
            al[mt][1] = *(const unsigned*)(Ql + r1);
            al[mt][2] = *(const unsigned*)(Ql + r0 + 8);
            al[mt][3] = *(const unsigned*)(Ql + r1 + 8);
        }
#pragma unroll
        for (int nt = 0; nt < 8; nt++) {
            int rn = (wn + nt * 8 + lr) * SST + k0 + lc;
            bb[nt][0] = *(const unsigned*)(Kh + rn);
            bb[nt][1] = *(const unsigned*)(Kh + rn + 8);
        }
#pragma unroll
        for (int mt = 0; mt < 2; mt++)
#pragma unroll
            for (int nt = 0; nt < 8; nt++) mma_bf16(d[mt][nt], ah[mt], bb[nt]);
#pragma unroll
        for (int mt = 0; mt < 2; mt++)
#pragma unroll
            for (int nt = 0; nt < 8; nt++) mma_bf16(d[mt][nt], al[mt], bb[nt]);
#pragma unroll
        for (int nt = 0; nt < 8; nt++) {
            int rn = (wn + nt * 8 + lr) * SST + k0 + lc;
            bb[nt][0] = *(const unsigned*)(Kl + rn);
            bb[nt][1] = *(const unsigned*)(Kl + rn + 8);
        }
#pragma unroll
        for (int mt = 0; mt < 2; mt++)
#pragma unroll
            for (int nt = 0; nt < 8; nt++) mma_bf16(d[mt][nt], ah[mt], bb[nt]);
    }

    float w0 = ow_in[0], w1 = ow_in[1], w2 = ow_in[2];
    float mw = fmaxf(w0, fmaxf(w1, w2));
    float e0 = __expf(w0 - mw), e1 = __expf(w1 - mw), e2 = __expf(w2 - mw);
    float inv = 1.f / (e0 + e1 + e2);
    w0 = e0 * inv; w1 = e1 * inv; w2 = e2 * inv;

#pragma unroll
    for (int mt = 0; mt < 2; mt++) {
        int r0 = bh * 1024 + mb + wm + mt * 16 + lr;
#pragma unroll
        for (int nt = 0; nt < 8; nt++) {
            int col = nb + wn + nt * 8 + lc;
            float s, p0, p1;
            s = d[mt][nt][0] * SCALEq; p0 = s * (w0 + s * (w1 + s * w2));
            s = d[mt][nt][1] * SCALEq; p1 = s * (w0 + s * (w1 + s * w2));
            float2 o0 = {p0, p1};
            *(float2*)(attn + (size_t)r0 * 1024 + col) = o0;
            s = d[mt][nt][2] * SCALEq; p0 = s * (w0 + s * (w1 + s * w2));
            s = d[mt][nt][3] * SCALEq; p1 = s * (w0 + s * (w1 + s * w2));
            float2 o1 = {p0, p1};
            *(float2*)(attn + (size_t)(r0 + 8) * 1024 + col) = o1;
        }
    }
}

// ---------------------------------------------------------------------------
// Kernel 3: row softmax in place on attn [32768 rows x 1024].
// ---------------------------------------------------------------------------
__global__ __launch_bounds__(256) void k_softmax(float* __restrict__ attn) {
    __shared__ float red[8];
    int row = blockIdx.x;
    int tid = threadIdx.x;
    float* p = attn + (size_t)row * 1024;
    float4 v = *(const float4*)(p + tid * 4);

    float m = fmaxf(fmaxf(v.x, v.y), fmaxf(v.z, v.w));
#pragma unroll
    for (int o = 16; o; o >>= 1) m = fmaxf(m, __shfl_xor_sync(0xffffffffu, m, o));
    int wid = tid >> 5, lane = tid & 31;
    if (lane == 0) red[wid] = m;
    __syncthreads();
    if (tid == 0) {
        float mm = red[0];
#pragma unroll
        for (int i = 1; i < 8; i++) mm = fmaxf(mm, red[i]);
        red[0] = mm;
    }
    __syncthreads();
    m = red[0];
    __syncthreads();

    float4 e;
    e.x = __expf(v.x - m); e.y = __expf(v.y - m);
    e.z = __expf(v.z - m); e.w = __expf(v.w - m);
    float s = e.x + e.y + e.z + e.w;
#pragma unroll
    for (int o = 16; o; o >>= 1) s += __shfl_xor_sync(0xffffffffu, s, o);
    if (lane == 0) red[wid] = s;
    __syncthreads();
    if (tid == 0) {
        float ss = 0.f;
#pragma unroll
        for (int i = 0; i < 8; i++) ss += red[i];
        red[0] = ss;
    }
    __syncthreads();
    float invs = 1.f / red[0];

    e.x *= invs; e.y *= invs; e.z *= invs; e.w *= invs;
    *(float4*)(p + tid * 4) = e;
}

// ---------------------------------------------------------------------------
// Kernel 4: AV via tensor cores (mma.sync bf16x3).
// ---------------------------------------------------------------------------
__global__ __launch_bounds__(256) void k_av(const float* __restrict__ attn) {
    extern __shared__ char smc[];
    unsigned short* Ahh = (unsigned short*)smc;          // [128][SST]
    unsigned short* All = Ahh + 128 * SST;
    unsigned short* Bhh = All + 128 * SST;               // [64][SST]
    unsigned short* Bll = Bhh + 64 * SST;

    int mb = blockIdx.x * 128;
    int bh = blockIdx.y;
    int tid = threadIdx.x;
    int w = tid >> 5, lane = tid & 31;
    int wm = w * 16;
    int lr = lane >> 2;
    int lc = (lane & 3) << 1;

    float d[8][4];
#pragma unroll
    for (int nt = 0; nt < 8; nt++)
#pragma unroll
        for (int j = 0; j < 4; j++) d[nt][j] = 0.f;

    const float* abase = attn + (size_t)(bh * 1024 + mb) * 1024;
    const float* bbase = g_vt + (size_t)bh * 64 * 1024;

    for (int ch = 0; ch < 16; ch++) {
#pragma unroll
        for (int i = 0; i < 16; i++) {
            int p = tid + i * 256;
            int row = p >> 5;
            int col = (p & 31) << 1;
            float2 av = *(const float2*)(abase + (size_t)row * 1024 + ch * 64 + col);
            float ahx = __bfloat162float(__float2bfloat16(av.x));
            float ahy = __bfloat162float(__float2bfloat16(av.y));
            int off = row * SST + col;
            *(unsigned*)(Ahh + off) = pack_bf16x2(ahx, ahy);
            *(unsigned*)(All + off) = pack_bf16x2(av.x - ahx, av.y - ahy);
        }
#pragma unroll
        for (int i = 0; i < 8; i++) {
            int p = tid + i * 256;
            int row = p >> 5;
            int col = (p & 31) << 1;
            float2 bv = *(const float2*)(bbase + (size_t)row * 1024 + ch * 64 + col);
            float bhx = __bfloat162float(__float2bfloat16(bv.x));
            float bhy = __bfloat162float(__float2bfloat16(bv.y));
            int off = row * SST + col;
            *(unsigned*)(Bhh + off) = pack_bf16x2(bhx, bhy);
            *(unsigned*)(Bll + off) = pack_bf16x2(bv.x - bhx, bv.y - bhy);
        }
        __syncthreads();

#pragma unroll
        for (int k0 = 0; k0 < 64; k0 += 16) {
            unsigned ah[4], al[4], bb[8][2];
            int r0 = (wm + lr) * SST + k0 + lc;
            int r1 = (wm + lr + 8) * SST + k0 + lc;
            ah[0] = *(const unsigned*)(Ahh + r0);
            ah[1] = *(const unsigned*)(Ahh + r1);
            ah[2] = *(const unsigned*)(Ahh + r0 + 8);
            ah[3] = *(const unsigned*)(Ahh + r1 + 8);
            al[0] = *(const unsigned*)(All + r0);
            al[1] = *(const unsigned*)(All + r1);
            al[2] = *(const unsigned*)(All + r0 + 8);
            al[3] = *(const unsigned*)(All + r1 + 8);
#pragma unroll
            for (int nt = 0; nt < 8; nt++) {
                int rn = (nt * 8 + lr) * SST + k0 + lc;
                bb[nt][0] = *(const unsigned*)(Bhh + rn);
                bb[nt][1] = *(const unsigned*)(Bhh + rn + 8);
            }
#pragma unroll
            for (int nt = 0; nt < 8; nt++) mma_bf16(d[nt], ah, bb[nt]);
#pragma unroll
            for (int nt = 0; nt < 8; nt++) mma_bf16(d[nt], al, bb[nt]);
#pragma unroll
            for (int nt = 0; nt < 8; nt++) {
                int rn = (nt * 8 + lr) * SST + k0 + lc;
                bb[nt][0] = *(const unsigned*)(Bll + rn);
                bb[nt][1] = *(const unsigned*)(Bll + rn + 8);
            }
#pragma unroll
            for (int nt = 0; nt < 8; nt++) mma_bf16(d[nt], ah, bb[nt]);
        }
        __syncthreads();
    }

    int b = bh >> 3, h = bh & 7;
    int n0 = mb + wm + lr;
#pragma unroll
    for (int nt = 0; nt < 8; nt++) {
        int col = h * 64 + nt * 8 + lc;
        float2 o0 = {d[nt][0], d[nt][1]};
        float2 o1 = {d[nt][2], d[nt][3]};
        *(float2*)(g_ao + (size_t)(b * 1024 + n0) * 512 + col) = o0;
        *(float2*)(g_ao + (size_t)(b * 1024 + n0 + 8) * 512 + col) = o1;
    }
}

// ---------------------------------------------------------------------------
// Kernel 5: proj GEMM, K-split 4 -> g_ypP[z] partials. Grid (4,32,4). FFMA2.
// ---------------------------------------------------------------------------
__global__ __launch_bounds__(256) void k_proj(const float* __restrict__ Bm) {
    const int K4 = 128, Nn = 512;
    const int P = Mq * Cq;
    __shared__ float As[2][8][128];
    __shared__ float Bs[2][8][128];
    int tid = threadIdx.x;
    int bx = blockIdx.x, by = blockIdx.y, bz = blockIdx.z;
    int aRow = tid >> 1, aCol = (tid & 1) << 2;
    int bRow = tid >> 5, bCol = (tid & 31) << 2;
    int ty = tid >> 4, tx = tid & 15;

    u64 acc[8][4];
#pragma unroll
    for (int i = 0; i < 8; i++)
#pragma unroll
        for (int j = 0; j < 4; j++) acc[i][j] = 0ULL;

    const float* Ap = g_ao + (size_t)(by * 128 + aRow) * 512 + bz * 128 + aCol;
    const float* Bp = Bm + (size_t)(bz * 128 + bRow) * Nn + bx * 128 + bCol;

    {
        float4 av = *(const float4*)(Ap);
        As[0][aCol + 0][aRow] = av.x;
        As[0][aCol + 1][aRow] = av.y;
        As[0][aCol + 2][aRow] = av.z;
        As[0][aCol + 3][aRow] = av.w;
        *(float4*)&Bs[0][bRow][bCol] = *(const float4*)(Bp);
    }
    __syncthreads();

    for (int k0 = 0; k0 < K4; k0 += 8) {
        int buf = (k0 >> 3) & 1;
        float4 av, bv;
        bool more = (k0 + 8) < K4;
        if (more) {
            av = *(const float4*)(Ap + k0 + 8);
            bv = *(const float4*)(Bp + (size_t)(k0 + 8) * Nn);
        }
#pragma unroll
        for (int k = 0; k < 8; k++) {
            float a[8];
            *(float4*)&a[0] = *(const float4*)&As[buf][k][ty * 8];
            *(float4*)&a[4] = *(const float4*)&As[buf][k][ty * 8 + 4];
            u64x2 b0 = *(const u64x2*)&Bs[buf][k][tx * 8];
            u64x2 b1 = *(const u64x2*)&Bs[buf][k][tx * 8 + 4];
            u64 bp[4] = {b0.x, b0.y, b1.x, b1.y};
#pragma unroll
            for (int i = 0; i < 8; i++) {
                u64 ad = dup2(a[i]);
#pragma unroll
                for (int j = 0; j < 4; j++) acc[i][j] = f2fma(ad, bp[j], acc[i][j]);
            }
        }
        if (more) {
            int nb2 = buf ^ 1;
            As[nb2][aCol + 0][aRow] = av.x;
            As[nb2][aCol + 1][aRow] = av.y;
            As[nb2][aCol + 2][aRow] = av.z;
            As[nb2][aCol + 3][aRow] = av.w;
            *(float4*)&Bs[nb2][bRow][bCol] = bv;
        }
        __syncthreads();
    }

    float* yp = g_ypP + (size_t)bz * P;
#pragma unroll
    for (int i = 0; i < 8; i++) {
        int r = by * 128 + ty * 8 + i;
#pragma unroll
        for (int jp = 0; jp < 4; jp++) {
            float2 v2 = upk(acc[i][jp]);
            int c = bx * 128 + tx * 8 + jp * 2;
            yp[(size_t)r * 512 + c]     = v2.x;
            yp[(size_t)r * 512 + c + 1] = v2.y;
        }
    }
}

// ---------------------------------------------------------------------------
// Kernel 6: LayerNorm. y_pre = sum of 4 proj partials + bias + x, then LN.
// ---------------------------------------------------------------------------
__global__ __launch_bounds__(128) void k_ln(const float* __restrict__ gamma,
                                            const float* __restrict__ beta,
                                            const float* __restrict__ bias,
                                            const float* __restrict__ x,
                                            float* __restrict__ y) {
    const int P = Mq * Cq;
    __shared__ float s1[4], s2[4];
    int row = blockIdx.x;
    int tid = threadIdx.x;
    int c = tid * 4;
    const float* p = g_ypP + (size_t)row * 512 + c;
    float4 v0 = *(const float4*)(p);
    float4 v1 = *(const float4*)(p + P);
    float4 v2 = *(const float4*)(p + 2 * P);
    float4 v3 = *(const float4*)(p + 3 * P);
    float4 bb = *(const float4*)(bias + c);
    float4 xx = *(const float4*)(x + (size_t)row * 512 + c);
    float4 v;
    v.x = v0.x + v1.x + v2.x + v3.x + bb.x + xx.x;
    v.y = v0.y + v1.y + v2.y + v3.y + bb.y + xx.y;
    v.z = v0.z + v1.z + v2.z + v3.z + bb.z + xx.z;
    v.w = v0.w + v1.w + v2.w + v3.w + bb.w + xx.w;

    float s = v.x + v.y + v.z + v.w;
    float ss = v.x * v.x + v.y * v.y + v.z * v.z + v.w * v.w;
#pragma unroll
    for (int o = 16; o; o >>= 1) {
        s += __shfl_xor_sync(0xffffffffu, s, o);
        ss += __shfl_xor_sync(0xffffffffu, ss, o);
    }
    int wid = tid >> 5, lane = tid & 31;
    if (lane == 0) { s1[wid] = s; s2[wid] = ss; }
    __syncthreads();
    if (tid == 0) {
        s1[0] = s1[0] + s1[1] + s1[2] + s1[3];
        s2[0] = s2[0] + s2[1] + s2[2] + s2[3];
    }
    __syncthreads();
    float mu = s1[0] * (1.f / 512.f);
    float var = s2[0] * (1.f / 512.f) - mu * mu;
    float rstd = rsqrtf(var + LN_EPSq);

    float4 g = *(const float4*)(gamma + c);
    float4 be = *(const float4*)(beta + c);
    float4 o;
    o.x = (v.x - mu) * rstd * g.x + be.x;
    o.y = (v.y - mu) * rstd * g.y + be.y;
    o.z = (v.z - mu) * rstd * g.z + be.z;
    o.w = (v.w - mu) * rstd * g.w + be.w;
    *(float4*)(y + (size_t)row * 512 + c) = o;
}

// ---------------------------------------------------------------------------
extern "C" void kernel_launch(void* const* d_in, const int* in_sizes, int n_in,
                              void* d_out, int out_size) {
    (void)in_sizes; (void)n_in; (void)out_size;
    const float* x     = (const float*)d_in[0];
    const float* Wqkv  = (const float*)d_in[1];
    const float* bqkv  = (const float*)d_in[2];
    const float* ow    = (const float*)d_in[3];
    const float* Wproj = (const float*)d_in[4];
    const float* bproj = (const float*)d_in[5];
    const float* gamma = (const float*)d_in[6];
    const float* beta  = (const float*)d_in[7];

    float* out      = (float*)d_out;
    float* y_out    = out;                         // [4,1024,512]
    float* attn_out = out + (size_t)Bq * Nq * Cq;  // [4,8,1024,1024]

    int qkv_smem    = 4 * 128 * SST * 2;                     // 73728 B
    int scores_smem = 4 * 128 * SST * 2;                     // 73728 B
    int av_smem     = (2 * 128 * SST + 2 * 64 * SST) * 2;    // 55296 B
    cudaFuncSetAttribute(k_qkv, cudaFuncAttributeMaxDynamicSharedMemorySize,
                         qkv_smem);
    cudaFuncSetAttribute(k_scores, cudaFuncAttributeMaxDynamicSharedMemorySize,
                         scores_smem);
    cudaFuncSetAttribute(k_av, cudaFuncAttributeMaxDynamicSharedMemorySize,
                         av_smem);

    k_qkv    <<<dim3(12, 32), 256, qkv_smem>>>(x, Wqkv, bqkv);
    k_scores <<<dim3(8, 8, 32), 256, scores_smem>>>(ow, attn_out);
    k_softmax<<<32768, 256>>>(attn_out);
    k_av     <<<dim3(8, 32), 256, av_smem>>>(attn_out);
    k_proj   <<<dim3(4, 32, 4), 256>>>(Wproj);
    k_ln     <<<4096, 128>>>(gamma, beta, bproj, x, y_out);
}

// round 14
// speedup vs baseline: 1.6251x; 1.0766x over previous
#include <cuda_runtime.h>
#include <cuda_bf16.h>
#include <math.h>

// Problem constants
#define Bq   4
#define Nq   1024
#define Cq   512
#define Hq   8
#define HDq  64
#define BHq  32
#define Mq   4096
#define SCALEq 0.125f
#define LN_EPSq 1e-5f

typedef unsigned long long u64;
typedef ulonglong2 u64x2;

// packed fp32x2 FMA (sm_103a)
__device__ __forceinline__ u64 f2fma(u64 a, u64 b, u64 c) {
    u64 d;
    asm("fma.rn.f32x2 %0, %1, %2, %3;" : "=l"(d) : "l"(a), "l"(b), "l"(c));
    return d;
}
__device__ __forceinline__ float2 upk(u64 v) {
    float2 r;
    asm("mov.b64 {%0, %1}, %2;" : "=f"(r.x), "=f"(r.y) : "l"(v));
    return r;
}
__device__ __forceinline__ u64 dup2(float x) {
    u64 r;
    asm("mov.b64 %0, {%1, %1};" : "=l"(r) : "f"(x));
    return r;
}

// bf16 mma.sync (baseline PTX, compiles under compute_103, runs on HMMA)
__device__ __forceinline__ void mma_bf16(float* d, const unsigned* a,
                                         const unsigned* b) {
    asm volatile(
        "mma.sync.aligned.m16n8k16.row.col.f32.bf16.bf16.f32 "
        "{%0,%1,%2,%3}, {%4,%5,%6,%7}, {%8,%9}, {%0,%1,%2,%3};"
        : "+f"(d[0]), "+f"(d[1]), "+f"(d[2]), "+f"(d[3])
        : "r"(a[0]), "r"(a[1]), "r"(a[2]), "r"(a[3]), "r"(b[0]), "r"(b[1]));
}
__device__ __forceinline__ unsigned pack_bf16x2(float a, float b) {
    unsigned short ha = __bfloat16_as_ushort(__float2bfloat16(a));
    unsigned short hb = __bfloat16_as_ushort(__float2bfloat16(b));
    return (unsigned)ha | ((unsigned)hb << 16);
}

// Scratch (device globals — allocation-free)
__device__ float g_q  [BHq * Nq * HDq];     // [bh][n][d]
__device__ float g_k  [BHq * Nq * HDq];
__device__ float g_vt [BHq * HDq * Nq];     // [bh][d][n]  (transposed V)
__device__ float g_aoP[2 * Mq * Cq];        // 2 k-split partials of attn-out
__device__ float g_ypP[4 * Mq * Cq];        // 4 k-split partials of proj-out

#define SST 72   // bf16 elements per smem row (144 B, conflict-free frags)

// ---------------------------------------------------------------------------
// Kernel 1: QKV GEMM via tensor cores (mma.sync bf16x3).
// x[4096,512] @ Wqkv[512,1536] + bqkv -> scatter q/k/vt.
// ---------------------------------------------------------------------------
__global__ __launch_bounds__(256) void k_qkv(const float* __restrict__ A,
                                             const float* __restrict__ Bm,
                                             const float* __restrict__ bias) {
    extern __shared__ char smc[];
    unsigned short* Ah = (unsigned short*)smc;      // [128][SST]
    unsigned short* Al = Ah + 128 * SST;
    unsigned short* Bh = Al + 128 * SST;            // [128][SST] (n-major)
    unsigned short* Bl = Bh + 128 * SST;

    const int K = 512, Nn = 1536;
    int bx = blockIdx.x, by = blockIdx.y;
    int tid = threadIdx.x;
    int w = tid >> 5, lane = tid & 31;
    int wm = (w >> 1) * 32;
    int wn = (w & 1) * 64;
    int lr = lane >> 2;
    int lc = (lane & 3) << 1;

    float d[2][8][4];
#pragma unroll
    for (int mt = 0; mt < 2; mt++)
#pragma unroll
        for (int nt = 0; nt < 8; nt++)
#pragma unroll
            for (int j = 0; j < 4; j++) d[mt][nt][j] = 0.f;

    for (int ch = 0; ch < 8; ch++) {
#pragma unroll
        for (int i = 0; i < 16; i++) {
            int p = tid + i * 256;
            int row = p >> 5;
            int col = (p & 31) << 1;
            float2 av = *(const float2*)(A + (size_t)(by * 128 + row) * K + ch * 64 + col);
            float ahx = __bfloat162float(__float2bfloat16(av.x));
            float ahy = __bfloat162float(__float2bfloat16(av.y));
            int off = row * SST + col;
            *(unsigned*)(Ah + off) = pack_bf16x2(ahx, ahy);
            *(unsigned*)(Al + off) = pack_bf16x2(av.x - ahx, av.y - ahy);
        }
#pragma unroll
        for (int i = 0; i < 16; i++) {
            int p = tid + i * 256;
            int kk = p >> 6;
            int nn = (p & 63) << 1;
            float2 bv = *(const float2*)(Bm + (size_t)(ch * 64 + kk) * Nn + bx * 128 + nn);
            float bhx = __bfloat162float(__float2bfloat16(bv.x));
            float bhy = __bfloat162float(__float2bfloat16(bv.y));
            Bh[nn * SST + kk]       = __bfloat16_as_ushort(__float2bfloat16(bhx));
            Bh[(nn + 1) * SST + kk] = __bfloat16_as_ushort(__float2bfloat16(bhy));
            Bl[nn * SST + kk]       = __bfloat16_as_ushort(__float2bfloat16(bv.x - bhx));
            Bl[(nn + 1) * SST + kk] = __bfloat16_as_ushort(__float2bfloat16(bv.y - bhy));
        }
        __syncthreads();

#pragma unroll
        for (int k0 = 0; k0 < 64; k0 += 16) {
            unsigned ah[2][4], al[2][4], bb[8][2];
#pragma unroll
            for (int mt = 0; mt < 2; mt++) {
                int r0 = (wm + mt * 16 + lr) * SST + k0 + lc;
                int r1 = (wm + mt * 16 + lr + 8) * SST + k0 + lc;
                ah[mt][0] = *(const unsigned*)(Ah + r0);
                ah[mt][1] = *(const unsigned*)(Ah + r1);
                ah[mt][2] = *(const unsigned*)(Ah + r0 + 8);
                ah[mt][3] = *(const unsigned*)(Ah + r1 + 8);
                al[mt][0] = *(const unsigned*)(Al + r0);
                al[mt][1] = *(const unsigned*)(Al + r1);
                al[mt][2] = *(const unsigned*)(Al + r0 + 8);
                al[mt][3] = *(const unsigned*)(Al + r1 + 8);
            }
#pragma unroll
            for (int nt = 0; nt < 8; nt++) {
                int rn = (wn + nt * 8 + lr) * SST + k0 + lc;
                bb[nt][0] = *(const unsigned*)(Bh + rn);
                bb[nt][1] = *(const unsigned*)(Bh + rn + 8);
            }
#pragma unroll
            for (int mt = 0; mt < 2; mt++)
#pragma unroll
                for (int nt = 0; nt < 8; nt++) mma_bf16(d[mt][nt], ah[mt], bb[nt]);
#pragma unroll
            for (int mt = 0; mt < 2; mt++)
#pragma unroll
                for (int nt = 0; nt < 8; nt++) mma_bf16(d[mt][nt], al[mt], bb[nt]);
#pragma unroll
            for (int nt = 0; nt < 8; nt++) {
                int rn = (wn + nt * 8 + lr) * SST + k0 + lc;
                bb[nt][0] = *(const unsigned*)(Bl + rn);
                bb[nt][1] = *(const unsigned*)(Bl + rn + 8);
            }
#pragma unroll
            for (int mt = 0; mt < 2; mt++)
#pragma unroll
                for (int nt = 0; nt < 8; nt++) mma_bf16(d[mt][nt], ah[mt], bb[nt]);
        }
        __syncthreads();
    }

#pragma unroll
    for (int mt = 0; mt < 2; mt++) {
#pragma unroll
        for (int rr = 0; rr < 2; rr++) {
            int r = by * 128 + wm + mt * 16 + lr + rr * 8;
            int bb2 = r >> 10, n = r & 1023;
#pragma unroll
            for (int nt = 0; nt < 8; nt++) {
#pragma unroll
                for (int cc = 0; cc < 2; cc++) {
                    int c = bx * 128 + wn + nt * 8 + lc + cc;
                    float v = d[mt][nt][rr * 2 + cc] + bias[c];
                    int sel = c >> 9;
                    int rem = c & 511;
                    int h = rem >> 6, dd = rem & 63;
                    int bh = bb2 * 8 + h;
                    if (sel == 0)      g_q [((size_t)bh * 1024 + n) * 64 + dd] = v;
                    else if (sel == 1) g_k [((size_t)bh * 1024 + n) * 64 + dd] = v;
                    else               g_vt[((size_t)bh * 64 + dd) * 1024 + n] = v;
                }
            }
        }
    }
}

// ---------------------------------------------------------------------------
// Kernel 2: scores via tensor cores (mma.sync bf16x3 split precision).
// ---------------------------------------------------------------------------
__global__ __launch_bounds__(256) void k_scores(const float* __restrict__ ow_in,
                                                float* __restrict__ attn) {
    extern __shared__ char smc[];
    unsigned short* Qh = (unsigned short*)smc;
    unsigned short* Ql = Qh + 128 * SST;
    unsigned short* Kh = Ql + 128 * SST;
    unsigned short* Kl = Kh + 128 * SST;

    int bh = blockIdx.z;
    int mb = blockIdx.y * 128;
    int nb = blockIdx.x * 128;
    int tid = threadIdx.x;

    const float* qbase = g_q + (size_t)(bh * 1024 + mb) * 64;
    const float* kbase = g_k + (size_t)(bh * 1024 + nb) * 64;
#pragma unroll
    for (int i = 0; i < 16; i++) {
        int p = tid + i * 256;
        int row = p >> 5;
        int col = (p & 31) << 1;
        float2 qv = *(const float2*)(qbase + row * 64 + col);
        float2 kv = *(const float2*)(kbase + row * 64 + col);
        float qhx = __bfloat162float(__float2bfloat16(qv.x));
        float qhy = __bfloat162float(__float2bfloat16(qv.y));
        float khx = __bfloat162float(__float2bfloat16(kv.x));
        float khy = __bfloat162float(__float2bfloat16(kv.y));
        int off = row * SST + col;
        *(unsigned*)(Qh + off) = pack_bf16x2(qhx, qhy);
        *(unsigned*)(Ql + off) = pack_bf16x2(qv.x - qhx, qv.y - qhy);
        *(unsigned*)(Kh + off) = pack_bf16x2(khx, khy);
        *(unsigned*)(Kl + off) = pack_bf16x2(kv.x - khx, kv.y - khy);
    }
    __syncthreads();

    int w = tid >> 5, lane = tid & 31;
    int wm = (w >> 1) * 32;
    int wn = (w & 1) * 64;
    int lr = lane >> 2;
    int lc = (lane & 3) << 1;

    float d[2][8][4];
#pragma unroll
    for (int mt = 0; mt < 2; mt++)
#pragma unroll
        for (int nt = 0; nt < 8; nt++)
#pragma unroll
            for (int j = 0; j < 4; j++) d[mt][nt][j] = 0.f;

#pragma unroll
    for (int k0 = 0; k0 < 64; k0 += 16) {
        unsigned ah[2][4], al[2][4], bb[8][2];
#pragma unroll
        for (int mt = 0; mt < 2; mt++) {
            int r0 = (wm + mt * 16 + lr) * SST + k0 + lc;
            int r1 = (wm + mt * 16 + lr + 8) * SST + k0 + lc;
            ah[mt][0] = *(const unsigned*)(Qh + r0);
            ah[mt][1] = *(const unsigned*)(Qh + r1);
            ah[mt][2] = *(const unsigned*)(Qh + r0 + 8);
            ah[mt][3] = *(const unsigned*)(Qh + r1 + 8);
            al[mt][0] = *(const unsigned*)(Ql + r0);
            al[mt][1] = *(const unsigned*)(Ql + r1);
            al[mt][2] = *(const unsigned*)(Ql + r0 + 8);
            al[mt][3] = *(const unsigned*)(Ql + r1 + 8);
        }
#pragma unroll
        for (int nt = 0; nt < 8; nt++) {
            int rn = (wn + nt * 8 + lr) * SST + k0 + lc;
            bb[nt][0] = *(const unsigned*)(Kh + rn);
            bb[nt][1] = *(const unsigned*)(Kh + rn + 8);
        }
#pragma unroll
        for (int mt = 0; mt < 2; mt++)
#pragma unroll
            for (int nt = 0; nt < 8; nt++) mma_bf16(d[mt][nt], ah[mt], bb[nt]);
#pragma unroll
        for (int mt = 0; mt < 2; mt++)
#pragma unroll
            for (int nt = 0; nt < 8; nt++) mma_bf16(d[mt][nt], al[mt], bb[nt]);
#pragma unroll
        for (int nt = 0; nt < 8; nt++) {
            int rn = (wn + nt * 8 + lr) * SST + k0 + lc;
            bb[nt][0] = *(const unsigned*)(Kl + rn);
            bb[nt][1] = *(const unsigned*)(Kl + rn + 8);
        }
#pragma unroll
        for (int mt = 0; mt < 2; mt++)
#pragma unroll
            for (int nt = 0; nt < 8; nt++) mma_bf16(d[mt][nt], ah[mt], bb[nt]);
    }

    float w0 = ow_in[0], w1 = ow_in[1], w2 = ow_in[2];
    float mw = fmaxf(w0, fmaxf(w1, w2));
    float e0 = __expf(w0 - mw), e1 = __expf(w1 - mw), e2 = __expf(w2 - mw);
    float inv = 1.f / (e0 + e1 + e2);
    w0 = e0 * inv; w1 = e1 * inv; w2 = e2 * inv;

#pragma unroll
    for (int mt = 0; mt < 2; mt++) {
        int r0 = bh * 1024 + mb + wm + mt * 16 + lr;
#pragma unroll
        for (int nt = 0; nt < 8; nt++) {
            int col = nb + wn + nt * 8 + lc;
            float s, p0, p1;
            s = d[mt][nt][0] * SCALEq; p0 = s * (w0 + s * (w1 + s * w2));
            s = d[mt][nt][1] * SCALEq; p1 = s * (w0 + s * (w1 + s * w2));
            float2 o0 = {p0, p1};
            *(float2*)(attn + (size_t)r0 * 1024 + col) = o0;
            s = d[mt][nt][2] * SCALEq; p0 = s * (w0 + s * (w1 + s * w2));
            s = d[mt][nt][3] * SCALEq; p1 = s * (w0 + s * (w1 + s * w2));
            float2 o1 = {p0, p1};
            *(float2*)(attn + (size_t)(r0 + 8) * 1024 + col) = o1;
        }
    }
}

// ---------------------------------------------------------------------------
// Kernel 3: row softmax in place on attn [32768 rows x 1024].
// ---------------------------------------------------------------------------
__global__ __launch_bounds__(256) void k_softmax(float* __restrict__ attn) {
    __shared__ float red[8];
    int row = blockIdx.x;
    int tid = threadIdx.x;
    float* p = attn + (size_t)row * 1024;
    float4 v = *(const float4*)(p + tid * 4);

    float m = fmaxf(fmaxf(v.x, v.y), fmaxf(v.z, v.w));
#pragma unroll
    for (int o = 16; o; o >>= 1) m = fmaxf(m, __shfl_xor_sync(0xffffffffu, m, o));
    int wid = tid >> 5, lane = tid & 31;
    if (lane == 0) red[wid] = m;
    __syncthreads();
    if (tid == 0) {
        float mm = red[0];
#pragma unroll
        for (int i = 1; i < 8; i++) mm = fmaxf(mm, red[i]);
        red[0] = mm;
    }
    __syncthreads();
    m = red[0];
    __syncthreads();

    float4 e;
    e.x = __expf(v.x - m); e.y = __expf(v.y - m);
    e.z = __expf(v.z - m); e.w = __expf(v.w - m);
    float s = e.x + e.y + e.z + e.w;
#pragma unroll
    for (int o = 16; o; o >>= 1) s += __shfl_xor_sync(0xffffffffu, s, o);
    if (lane == 0) red[wid] = s;
    __syncthreads();
    if (tid == 0) {
        float ss = 0.f;
#pragma unroll
        for (int i = 0; i < 8; i++) ss += red[i];
        red[0] = ss;
    }
    __syncthreads();
    float invs = 1.f / red[0];

    e.x *= invs; e.y *= invs; e.z *= invs; e.w *= invs;
    *(float4*)(p + tid * 4) = e;
}

// ---------------------------------------------------------------------------
// Kernel 4: AV via tensor cores (mma.sync bf16x3), K-SPLIT 2.
// Block (mtile, bh, z): O_partial[128,64] over keys [z*512, z*512+512).
// Grid (8, 32, 2) = 512 blocks -> fixes grid starvation (was 256).
// ---------------------------------------------------------------------------
__global__ __launch_bounds__(256) void k_av(const float* __restrict__ attn) {
    extern __shared__ char smc[];
    unsigned short* Ahh = (unsigned short*)smc;          // [128][SST]
    unsigned short* All = Ahh + 128 * SST;
    unsigned short* Bhh = All + 128 * SST;               // [64][SST]
    unsigned short* Bll = Bhh + 64 * SST;

    int mb = blockIdx.x * 128;
    int bh = blockIdx.y;
    int zc = blockIdx.z * 8;     // chunk base: 8 chunks of 64 keys per block
    int tid = threadIdx.x;
    int w = tid >> 5, lane = tid & 31;
    int wm = w * 16;
    int lr = lane >> 2;
    int lc = (lane & 3) << 1;

    float d[8][4];
#pragma unroll
    for (int nt = 0; nt < 8; nt++)
#pragma unroll
        for (int j = 0; j < 4; j++) d[nt][j] = 0.f;

    const float* abase = attn + (size_t)(bh * 1024 + mb) * 1024;
    const float* bbase = g_vt + (size_t)bh * 64 * 1024;

    for (int c8 = 0; c8 < 8; c8++) {
        int ch = zc + c8;
#pragma unroll
        for (int i = 0; i < 16; i++) {
            int p = tid + i * 256;
            int row = p >> 5;
            int col = (p & 31) << 1;
            float2 av = *(const float2*)(abase + (size_t)row * 1024 + ch * 64 + col);
            float ahx = __bfloat162float(__float2bfloat16(av.x));
            float ahy = __bfloat162float(__float2bfloat16(av.y));
            int off = row * SST + col;
            *(unsigned*)(Ahh + off) = pack_bf16x2(ahx, ahy);
            *(unsigned*)(All + off) = pack_bf16x2(av.x - ahx, av.y - ahy);
        }
#pragma unroll
        for (int i = 0; i < 8; i++) {
            int p = tid + i * 256;
            int row = p >> 5;
            int col = (p & 31) << 1;
            float2 bv = *(const float2*)(bbase + (size_t)row * 1024 + ch * 64 + col);
            float bhx = __bfloat162float(__float2bfloat16(bv.x));
            float bhy = __bfloat162float(__float2bfloat16(bv.y));
            int off = row * SST + col;
            *(unsigned*)(Bhh + off) = pack_bf16x2(bhx, bhy);
            *(unsigned*)(Bll + off) = pack_bf16x2(bv.x - bhx, bv.y - bhy);
        }
        __syncthreads();

#pragma unroll
        for (int k0 = 0; k0 < 64; k0 += 16) {
            unsigned ah[4], al[4], bb[8][2];
            int r0 = (wm + lr) * SST + k0 + lc;
            int r1 = (wm + lr + 8) * SST + k0 + lc;
            ah[0] = *(const unsigned*)(Ahh + r0);
            ah[1] = *(const unsigned*)(Ahh + r1);
            ah[2] = *(const unsigned*)(Ahh + r0 + 8);
            ah[3] = *(const unsigned*)(Ahh + r1 + 8);
            al[0] = *(const unsigned*)(All + r0);
            al[1] = *(const unsigned*)(All + r1);
            al[2] = *(const unsigned*)(All + r0 + 8);
            al[3] = *(const unsigned*)(All + r1 + 8);
#pragma unroll
            for (int nt = 0; nt < 8; nt++) {
                int rn = (nt * 8 + lr) * SST + k0 + lc;
                bb[nt][0] = *(const unsigned*)(Bhh + rn);
                bb[nt][1] = *(const unsigned*)(Bhh + rn + 8);
            }
#pragma unroll
            for (int nt = 0; nt < 8; nt++) mma_bf16(d[nt], ah, bb[nt]);
#pragma unroll
            for (int nt = 0; nt < 8; nt++) mma_bf16(d[nt], al, bb[nt]);
#pragma unroll
            for (int nt = 0; nt < 8; nt++) {
                int rn = (nt * 8 + lr) * SST + k0 + lc;
                bb[nt][0] = *(const unsigned*)(Bll + rn);
                bb[nt][1] = *(const unsigned*)(Bll + rn + 8);
            }
#pragma unroll
            for (int nt = 0; nt < 8; nt++) mma_bf16(d[nt], ah, bb[nt]);
        }
        __syncthreads();
    }

    int b = bh >> 3, h = bh & 7;
    int n0 = mb + wm + lr;
    float* base = g_aoP + (size_t)blockIdx.z * (Mq * Cq);
#pragma unroll
    for (int nt = 0; nt < 8; nt++) {
        int col = h * 64 + nt * 8 + lc;
        float2 o0 = {d[nt][0], d[nt][1]};
        float2 o1 = {d[nt][2], d[nt][3]};
        *(float2*)(base + (size_t)(b * 1024 + n0) * 512 + col) = o0;
        *(float2*)(base + (size_t)(b * 1024 + n0 + 8) * 512 + col) = o1;
    }
}

// ---------------------------------------------------------------------------
// Kernel 5: proj GEMM, K-split 4 -> g_ypP[z]. A = sum of 2 g_aoP partials.
// ---------------------------------------------------------------------------
__global__ __launch_bounds__(256) void k_proj(const float* __restrict__ Bm) {
    const int K4 = 128, Nn = 512;
    const int P = Mq * Cq;
    __shared__ float As[2][8][128];
    __shared__ float Bs[2][8][128];
    int tid = threadIdx.x;
    int bx = blockIdx.x, by = blockIdx.y, bz = blockIdx.z;
    int aRow = tid >> 1, aCol = (tid & 1) << 2;
    int bRow = tid >> 5, bCol = (tid & 31) << 2;
    int ty = tid >> 4, tx = tid & 15;

    u64 acc[8][4];
#pragma unroll
    for (int i = 0; i < 8; i++)
#pragma unroll
        for (int j = 0; j < 4; j++) acc[i][j] = 0ULL;

    const float* Ap = g_aoP + (size_t)(by * 128 + aRow) * 512 + bz * 128 + aCol;
    const float* Bp = Bm + (size_t)(bz * 128 + bRow) * Nn + bx * 128 + bCol;

    {
        float4 a0 = *(const float4*)(Ap);
        float4 a1 = *(const float4*)(Ap + P);
        float4 av = {a0.x + a1.x, a0.y + a1.y, a0.z + a1.z, a0.w + a1.w};
        As[0][aCol + 0][aRow] = av.x;
        As[0][aCol + 1][aRow] = av.y;
        As[0][aCol + 2][aRow] = av.z;
        As[0][aCol + 3][aRow] = av.w;
        *(float4*)&Bs[0][bRow][bCol] = *(const float4*)(Bp);
    }
    __syncthreads();

    for (int k0 = 0; k0 < K4; k0 += 8) {
        int buf = (k0 >> 3) & 1;
        float4 av, bv;
        bool more = (k0 + 8) < K4;
        if (more) {
            float4 a0 = *(const float4*)(Ap + k0 + 8);
            float4 a1 = *(const float4*)(Ap + P + k0 + 8);
            av.x = a0.x + a1.x;
            av.y = a0.y + a1.y;
            av.z = a0.z + a1.z;
            av.w = a0.w + a1.w;
            bv = *(const float4*)(Bp + (size_t)(k0 + 8) * Nn);
        }
#pragma unroll
        for (int k = 0; k < 8; k++) {
            float a[8];
            *(float4*)&a[0] = *(const float4*)&As[buf][k][ty * 8];
            *(float4*)&a[4] = *(const float4*)&As[buf][k][ty * 8 + 4];
            u64x2 b0 = *(const u64x2*)&Bs[buf][k][tx * 8];
            u64x2 b1 = *(const u64x2*)&Bs[buf][k][tx * 8 + 4];
            u64 bp[4] = {b0.x, b0.y, b1.x, b1.y};
#pragma unroll
            for (int i = 0; i < 8; i++) {
                u64 ad = dup2(a[i]);
#pragma unroll
                for (int j = 0; j < 4; j++) acc[i][j] = f2fma(ad, bp[j], acc[i][j]);
            }
        }
        if (more) {
            int nb2 = buf ^ 1;
            As[nb2][aCol + 0][aRow] = av.x;
            As[nb2][aCol + 1][aRow] = av.y;
            As[nb2][aCol + 2][aRow] = av.z;
            As[nb2][aCol + 3][aRow] = av.w;
            *(float4*)&Bs[nb2][bRow][bCol] = bv;
        }
        __syncthreads();
    }

    float* yp = g_ypP + (size_t)bz * P;
#pragma unroll
    for (int i = 0; i < 8; i++) {
        int r = by * 128 + ty * 8 + i;
#pragma unroll
        for (int jp = 0; jp < 4; jp++) {
            float2 v2 = upk(acc[i][jp]);
            int c = bx * 128 + tx * 8 + jp * 2;
            yp[(size_t)r * 512 + c]     = v2.x;
            yp[(size_t)r * 512 + c + 1] = v2.y;
        }
    }
}

// ---------------------------------------------------------------------------
// Kernel 6: LayerNorm. y_pre = sum of 4 proj partials + bias + x, then LN.
// ---------------------------------------------------------------------------
__global__ __launch_bounds__(128) void k_ln(const float* __restrict__ gamma,
                                            const float* __restrict__ beta,
                                            const float* __restrict__ bias,
                                            const float* __restrict__ x,
                                            float* __restrict__ y) {
    const int P = Mq * Cq;
    __shared__ float s1[4], s2[4];
    int row = blockIdx.x;
    int tid = threadIdx.x;
    int c = tid * 4;
    const float* p = g_ypP + (size_t)row * 512 + c;
    float4 v0 = *(const float4*)(p);
    float4 v1 = *(const float4*)(p + P);
    float4 v2 = *(const float4*)(p + 2 * P);
    float4 v3 = *(const float4*)(p + 3 * P);
    float4 bb = *(const float4*)(bias + c);
    float4 xx = *(const float4*)(x + (size_t)row * 512 + c);
    float4 v;
    v.x = v0.x + v1.x + v2.x + v3.x + bb.x + xx.x;
    v.y = v0.y + v1.y + v2.y + v3.y + bb.y + xx.y;
    v.z = v0.z + v1.z + v2.z + v3.z + bb.z + xx.z;
    v.w = v0.w + v1.w + v2.w + v3.w + bb.w + xx.w;

    float s = v.x + v.y + v.z + v.w;
    float ss = v.x * v.x + v.y * v.y + v.z * v.z + v.w * v.w;
#pragma unroll
    for (int o = 16; o; o >>= 1) {
        s += __shfl_xor_sync(0xffffffffu, s, o);
        ss += __shfl_xor_sync(0xffffffffu, ss, o);
    }
    int wid = tid >> 5, lane = tid & 31;
    if (lane == 0) { s1[wid] = s; s2[wid] = ss; }
    __syncthreads();
    if (tid == 0) {
        s1[0] = s1[0] + s1[1] + s1[2] + s1[3];
        s2[0] = s2[0] + s2[1] + s2[2] + s2[3];
    }
    __syncthreads();
    float mu = s1[0] * (1.f / 512.f);
    float var = s2[0] * (1.f / 512.f) - mu * mu;
    float rstd = rsqrtf(var + LN_EPSq);

    float4 g = *(const float4*)(gamma + c);
    float4 be = *(const float4*)(beta + c);
    float4 o;
    o.x = (v.x - mu) * rstd * g.x + be.x;
    o.y = (v.y - mu) * rstd * g.y + be.y;
    o.z = (v.z - mu) * rstd * g.z + be.z;
    o.w = (v.w - mu) * rstd * g.w + be.w;
    *(float4*)(y + (size_t)row * 512 + c) = o;
}

// ---------------------------------------------------------------------------
extern "C" void kernel_launch(void* const* d_in, const int* in_sizes, int n_in,
                              void* d_out, int out_size) {
    (void)in_sizes; (void)n_in; (void)out_size;
    const float* x     = (const float*)d_in[0];
    const float* Wqkv  = (const float*)d_in[1];
    const float* bqkv  = (const float*)d_in[2];
    const float* ow    = (const float*)d_in[3];
    const float* Wproj = (const float*)d_in[4];
    const float* bproj = (const float*)d_in[5];
    const float* gamma = (const float*)d_in[6];
    const float* beta  = (const float*)d_in[7];

    float* out      = (float*)d_out;
    float* y_out    = out;                         // [4,1024,512]
    float* attn_out = out + (size_t)Bq * Nq * Cq;  // [4,8,1024,1024]

    int qkv_smem    = 4 * 128 * SST * 2;                     // 73728 B
    int scores_smem = 4 * 128 * SST * 2;                     // 73728 B
    int av_smem     = (2 * 128 * SST + 2 * 64 * SST) * 2;    // 55296 B
    cudaFuncSetAttribute(k_qkv, cudaFuncAttributeMaxDynamicSharedMemorySize,
                         qkv_smem);
    cudaFuncSetAttribute(k_scores, cudaFuncAttributeMaxDynamicSharedMemorySize,
                         scores_smem);
    cudaFuncSetAttribute(k_av, cudaFuncAttributeMaxDynamicSharedMemorySize,
                         av_smem);

    k_qkv    <<<dim3(12, 32), 256, qkv_smem>>>(x, Wqkv, bqkv);
    k_scores <<<dim3(8, 8, 32), 256, scores_smem>>>(ow, attn_out);
    k_softmax<<<32768, 256>>>(attn_out);
    k_av     <<<dim3(8, 32, 2), 256, av_smem>>>(attn_out);
    k_proj   <<<dim3(4, 32, 4), 256>>>(Wproj);
    k_ln     <<<4096, 128>>>(gamma, beta, bproj, x, y_out);
}

// round 15
// speedup vs baseline: 1.7978x; 1.1063x over previous
#include <cuda_runtime.h>
#include <cuda_bf16.h>
#include <math.h>

// Problem constants
#define Bq   4
#define Nq   1024
#define Cq   512
#define Hq   8
#define HDq  64
#define BHq  32
#define Mq   4096
#define SCALEq 0.125f
#define LN_EPSq 1e-5f

// bf16 mma.sync (baseline PTX, compiles under compute_103, runs on HMMA)
__device__ __forceinline__ void mma_bf16(float* d, const unsigned* a,
                                         const unsigned* b) {
    asm volatile(
        "mma.sync.aligned.m16n8k16.row.col.f32.bf16.bf16.f32 "
        "{%0,%1,%2,%3}, {%4,%5,%6,%7}, {%8,%9}, {%0,%1,%2,%3};"
        : "+f"(d[0]), "+f"(d[1]), "+f"(d[2]), "+f"(d[3])
        : "r"(a[0]), "r"(a[1]), "r"(a[2]), "r"(a[3]), "r"(b[0]), "r"(b[1]));
}
__device__ __forceinline__ unsigned pack_bf16x2(float a, float b) {
    unsigned short ha = __bfloat16_as_ushort(__float2bfloat16(a));
    unsigned short hb = __bfloat16_as_ushort(__float2bfloat16(b));
    return (unsigned)ha | ((unsigned)hb << 16);
}

// Scratch (device globals — allocation-free)
__device__ float g_q  [BHq * Nq * HDq];     // [bh][n][d]
__device__ float g_k  [BHq * Nq * HDq];
__device__ float g_vt [BHq * HDq * Nq];     // [bh][d][n]  (transposed V)
__device__ float g_aoP[2 * Mq * Cq];        // 2 k-split partials of attn-out
__device__ float g_ypP[2 * Mq * Cq];        // 2 k-split partials of proj-out

#define SST 72   // bf16 elements per smem row (144 B, conflict-free frags)

// ---------------------------------------------------------------------------
// Kernel 1: QKV GEMM via tensor cores (mma.sync bf16x3).
// x[4096,512] @ Wqkv[512,1536] + bqkv -> scatter q/k/vt.
// ---------------------------------------------------------------------------
__global__ __launch_bounds__(256) void k_qkv(const float* __restrict__ A,
                                             const float* __restrict__ Bm,
                                             const float* __restrict__ bias) {
    extern __shared__ char smc[];
    unsigned short* Ah = (unsigned short*)smc;      // [128][SST]
    unsigned short* Al = Ah + 128 * SST;
    unsigned short* Bh = Al + 128 * SST;            // [128][SST] (n-major)
    unsigned short* Bl = Bh + 128 * SST;

    const int K = 512, Nn = 1536;
    int bx = blockIdx.x, by = blockIdx.y;
    int tid = threadIdx.x;
    int w = tid >> 5, lane = tid & 31;
    int wm = (w >> 1) * 32;
    int wn = (w & 1) * 64;
    int lr = lane >> 2;
    int lc = (lane & 3) << 1;

    float d[2][8][4];
#pragma unroll
    for (int mt = 0; mt < 2; mt++)
#pragma unroll
        for (int nt = 0; nt < 8; nt++)
#pragma unroll
            for (int j = 0; j < 4; j++) d[mt][nt][j] = 0.f;

    for (int ch = 0; ch < 8; ch++) {
#pragma unroll
        for (int i = 0; i < 16; i++) {
            int p = tid + i * 256;
            int row = p >> 5;
            int col = (p & 31) << 1;
            float2 av = *(const float2*)(A + (size_t)(by * 128 + row) * K + ch * 64 + col);
            float ahx = __bfloat162float(__float2bfloat16(av.x));
            float ahy = __bfloat162float(__float2bfloat16(av.y));
            int off = row * SST + col;
            *(unsigned*)(Ah + off) = pack_bf16x2(ahx, ahy);
            *(unsigned*)(Al + off) = pack_bf16x2(av.x - ahx, av.y - ahy);
        }
#pragma unroll
        for (int i = 0; i < 16; i++) {
            int p = tid + i * 256;
            int kk = p >> 6;
            int nn = (p & 63) << 1;
            float2 bv = *(const float2*)(Bm + (size_t)(ch * 64 + kk) * Nn + bx * 128 + nn);
            float bhx = __bfloat162float(__float2bfloat16(bv.x));
            float bhy = __bfloat162float(__float2bfloat16(bv.y));
            Bh[nn * SST + kk]       = __bfloat16_as_ushort(__float2bfloat16(bhx));
            Bh[(nn + 1) * SST + kk] = __bfloat16_as_ushort(__float2bfloat16(bhy));
            Bl[nn * SST + kk]       = __bfloat16_as_ushort(__float2bfloat16(bv.x - bhx));
            Bl[(nn + 1) * SST + kk] = __bfloat16_as_ushort(__float2bfloat16(bv.y - bhy));
        }
        __syncthreads();

#pragma unroll
        for (int k0 = 0; k0 < 64; k0 += 16) {
            unsigned ah[2][4], al[2][4], bb[8][2];
#pragma unroll
            for (int mt = 0; mt < 2; mt++) {
                int r0 = (wm + mt * 16 + lr) * SST + k0 + lc;
                int r1 = (wm + mt * 16 + lr + 8) * SST + k0 + lc;
                ah[mt][0] = *(const unsigned*)(Ah + r0);
                ah[mt][1] = *(const unsigned*)(Ah + r1);
                ah[mt][2] = *(const unsigned*)(Ah + r0 + 8);
                ah[mt][3] = *(const unsigned*)(Ah + r1 + 8);
                al[mt][0] = *(const unsigned*)(Al + r0);
                al[mt][1] = *(const unsigned*)(Al + r1);
                al[mt][2] = *(const unsigned*)(Al + r0 + 8);
                al[mt][3] = *(const unsigned*)(Al + r1 + 8);
            }
#pragma unroll
            for (int nt = 0; nt < 8; nt++) {
                int rn = (wn + nt * 8 + lr) * SST + k0 + lc;
                bb[nt][0] = *(const unsigned*)(Bh + rn);
                bb[nt][1] = *(const unsigned*)(Bh + rn + 8);
            }
#pragma unroll
            for (int mt = 0; mt < 2; mt++)
#pragma unroll
                for (int nt = 0; nt < 8; nt++) mma_bf16(d[mt][nt], ah[mt], bb[nt]);
#pragma unroll
            for (int mt = 0; mt < 2; mt++)
#pragma unroll
                for (int nt = 0; nt < 8; nt++) mma_bf16(d[mt][nt], al[mt], bb[nt]);
#pragma unroll
            for (int nt = 0; nt < 8; nt++) {
                int rn = (wn + nt * 8 + lr) * SST + k0 + lc;
                bb[nt][0] = *(const unsigned*)(Bl + rn);
                bb[nt][1] = *(const unsigned*)(Bl + rn + 8);
            }
#pragma unroll
            for (int mt = 0; mt < 2; mt++)
#pragma unroll
                for (int nt = 0; nt < 8; nt++) mma_bf16(d[mt][nt], ah[mt], bb[nt]);
        }
        __syncthreads();
    }

#pragma unroll
    for (int mt = 0; mt < 2; mt++) {
#pragma unroll
        for (int rr = 0; rr < 2; rr++) {
            int r = by * 128 + wm + mt * 16 + lr + rr * 8;
            int bb2 = r >> 10, n = r & 1023;
#pragma unroll
            for (int nt = 0; nt < 8; nt++) {
#pragma unroll
                for (int cc = 0; cc < 2; cc++) {
                    int c = bx * 128 + wn + nt * 8 + lc + cc;
                    float v = d[mt][nt][rr * 2 + cc] + bias[c];
                    int sel = c >> 9;
                    int rem = c & 511;
                    int h = rem >> 6, dd = rem & 63;
                    int bh = bb2 * 8 + h;
                    if (sel == 0)      g_q [((size_t)bh * 1024 + n) * 64 + dd] = v;
                    else if (sel == 1) g_k [((size_t)bh * 1024 + n) * 64 + dd] = v;
                    else               g_vt[((size_t)bh * 64 + dd) * 1024 + n] = v;
                }
            }
        }
    }
}

// ---------------------------------------------------------------------------
// Kernel 2: scores via tensor cores (mma.sync bf16x3 split precision).
// ---------------------------------------------------------------------------
__global__ __launch_bounds__(256) void k_scores(const float* __restrict__ ow_in,
                                                float* __restrict__ attn) {
    extern __shared__ char smc[];
    unsigned short* Qh = (unsigned short*)smc;
    unsigned short* Ql = Qh + 128 * SST;
    unsigned short* Kh = Ql + 128 * SST;
    unsigned short* Kl = Kh + 128 * SST;

    int bh = blockIdx.z;
    int mb = blockIdx.y * 128;
    int nb = blockIdx.x * 128;
    int tid = threadIdx.x;

    const float* qbase = g_q + (size_t)(bh * 1024 + mb) * 64;
    const float* kbase = g_k + (size_t)(bh * 1024 + nb) * 64;
#pragma unroll
    for (int i = 0; i < 16; i++) {
        int p = tid + i * 256;
        int row = p >> 5;
        int col = (p & 31) << 1;
        float2 qv = *(const float2*)(qbase + row * 64 + col);
        float2 kv = *(const float2*)(kbase + row * 64 + col);
        float qhx = __bfloat162float(__float2bfloat16(qv.x));
        float qhy = __bfloat162float(__float2bfloat16(qv.y));
        float khx = __bfloat162float(__float2bfloat16(kv.x));
        float khy = __bfloat162float(__float2bfloat16(kv.y));
        int off = row * SST + col;
        *(unsigned*)(Qh + off) = pack_bf16x2(qhx, qhy);
        *(unsigned*)(Ql + off) = pack_bf16x2(qv.x - qhx, qv.y - qhy);
        *(unsigned*)(Kh + off) = pack_bf16x2(khx, khy);
        *(unsigned*)(Kl + off) = pack_bf16x2(kv.x - khx, kv.y - khy);
    }
    __syncthreads();

    int w = tid >> 5, lane = tid & 31;
    int wm = (w >> 1) * 32;
    int wn = (w & 1) * 64;
    int lr = lane >> 2;
    int lc = (lane & 3) << 1;

    float d[2][8][4];
#pragma unroll
    for (int mt = 0; mt < 2; mt++)
#pragma unroll
        for (int nt = 0; nt < 8; nt++)
#pragma unroll
            for (int j = 0; j < 4; j++) d[mt][nt][j] = 0.f;

#pragma unroll
    for (int k0 = 0; k0 < 64; k0 += 16) {
        unsigned ah[2][4], al[2][4], bb[8][2];
#pragma unroll
        for (int mt = 0; mt < 2; mt++) {
            int r0 = (wm + mt * 16 + lr) * SST + k0 + lc;
            int r1 = (wm + mt * 16 + lr + 8) * SST + k0 + lc;
            ah[mt][0] = *(const unsigned*)(Qh + r0);
            ah[mt][1] = *(const unsigned*)(Qh + r1);
            ah[mt][2] = *(const unsigned*)(Qh + r0 + 8);
            ah[mt][3] = *(const unsigned*)(Qh + r1 + 8);
            al[mt][0] = *(const unsigned*)(Ql + r0);
            al[mt][1] = *(const unsigned*)(Ql + r1);
            al[mt][2] = *(const unsigned*)(Ql + r0 + 8);
            al[mt][3] = *(const unsigned*)(Ql + r1 + 8);
        }
#pragma unroll
        for (int nt = 0; nt < 8; nt++) {
            int rn = (wn + nt * 8 + lr) * SST + k0 + lc;
            bb[nt][0] = *(const unsigned*)(Kh + rn);
            bb[nt][1] = *(const unsigned*)(Kh + rn + 8);
        }
#pragma unroll
        for (int mt = 0; mt < 2; mt++)
#pragma unroll
            for (int nt = 0; nt < 8; nt++) mma_bf16(d[mt][nt], ah[mt], bb[nt]);
#pragma unroll
        for (int mt = 0; mt < 2; mt++)
#pragma unroll
            for (int nt = 0; nt < 8; nt++) mma_bf16(d[mt][nt], al[mt], bb[nt]);
#pragma unroll
        for (int nt = 0; nt < 8; nt++) {
            int rn = (wn + nt * 8 + lr) * SST + k0 + lc;
            bb[nt][0] = *(const unsigned*)(Kl + rn);
            bb[nt][1] = *(const unsigned*)(Kl + rn + 8);
        }
#pragma unroll
        for (int mt = 0; mt < 2; mt++)
#pragma unroll
            for (int nt = 0; nt < 8; nt++) mma_bf16(d[mt][nt], ah[mt], bb[nt]);
    }

    float w0 = ow_in[0], w1 = ow_in[1], w2 = ow_in[2];
    float mw = fmaxf(w0, fmaxf(w1, w2));
    float e0 = __expf(w0 - mw), e1 = __expf(w1 - mw), e2 = __expf(w2 - mw);
    float inv = 1.f / (e0 + e1 + e2);
    w0 = e0 * inv; w1 = e1 * inv; w2 = e2 * inv;

#pragma unroll
    for (int mt = 0; mt < 2; mt++) {
        int r0 = bh * 1024 + mb + wm + mt * 16 + lr;
#pragma unroll
        for (int nt = 0; nt < 8; nt++) {
            int col = nb + wn + nt * 8 + lc;
            float s, p0, p1;
            s = d[mt][nt][0] * SCALEq; p0 = s * (w0 + s * (w1 + s * w2));
            s = d[mt][nt][1] * SCALEq; p1 = s * (w0 + s * (w1 + s * w2));
            float2 o0 = {p0, p1};
            *(float2*)(attn + (size_t)r0 * 1024 + col) = o0;
            s = d[mt][nt][2] * SCALEq; p0 = s * (w0 + s * (w1 + s * w2));
            s = d[mt][nt][3] * SCALEq; p1 = s * (w0 + s * (w1 + s * w2));
            float2 o1 = {p0, p1};
            *(float2*)(attn + (size_t)(r0 + 8) * 1024 + col) = o1;
        }
    }
}

// ---------------------------------------------------------------------------
// Kernel 3: row softmax in place on attn [32768 rows x 1024].
// ---------------------------------------------------------------------------
__global__ __launch_bounds__(256) void k_softmax(float* __restrict__ attn) {
    __shared__ float red[8];
    int row = blockIdx.x;
    int tid = threadIdx.x;
    float* p = attn + (size_t)row * 1024;
    float4 v = *(const float4*)(p + tid * 4);

    float m = fmaxf(fmaxf(v.x, v.y), fmaxf(v.z, v.w));
#pragma unroll
    for (int o = 16; o; o >>= 1) m = fmaxf(m, __shfl_xor_sync(0xffffffffu, m, o));
    int wid = tid >> 5, lane = tid & 31;
    if (lane == 0) red[wid] = m;
    __syncthreads();
    if (tid == 0) {
        float mm = red[0];
#pragma unroll
        for (int i = 1; i < 8; i++) mm = fmaxf(mm, red[i]);
        red[0] = mm;
    }
    __syncthreads();
    m = red[0];
    __syncthreads();

    float4 e;
    e.x = __expf(v.x - m); e.y = __expf(v.y - m);
    e.z = __expf(v.z - m); e.w = __expf(v.w - m);
    float s = e.x + e.y + e.z + e.w;
#pragma unroll
    for (int o = 16; o; o >>= 1) s += __shfl_xor_sync(0xffffffffu, s, o);
    if (lane == 0) red[wid] = s;
    __syncthreads();
    if (tid == 0) {
        float ss = 0.f;
#pragma unroll
        for (int i = 0; i < 8; i++) ss += red[i];
        red[0] = ss;
    }
    __syncthreads();
    float invs = 1.f / red[0];

    e.x *= invs; e.y *= invs; e.z *= invs; e.w *= invs;
    *(float4*)(p + tid * 4) = e;
}

// ---------------------------------------------------------------------------
// Kernel 4: AV via tensor cores (mma.sync bf16x3), K-SPLIT 2.
// ---------------------------------------------------------------------------
__global__ __launch_bounds__(256) void k_av(const float* __restrict__ attn) {
    extern __shared__ char smc[];
    unsigned short* Ahh = (unsigned short*)smc;          // [128][SST]
    unsigned short* All = Ahh + 128 * SST;
    unsigned short* Bhh = All + 128 * SST;               // [64][SST]
    unsigned short* Bll = Bhh + 64 * SST;

    int mb = blockIdx.x * 128;
    int bh = blockIdx.y;
    int zc = blockIdx.z * 8;
    int tid = threadIdx.x;
    int w = tid >> 5, lane = tid & 31;
    int wm = w * 16;
    int lr = lane >> 2;
    int lc = (lane & 3) << 1;

    float d[8][4];
#pragma unroll
    for (int nt = 0; nt < 8; nt++)
#pragma unroll
        for (int j = 0; j < 4; j++) d[nt][j] = 0.f;

    const float* abase = attn + (size_t)(bh * 1024 + mb) * 1024;
    const float* bbase = g_vt + (size_t)bh * 64 * 1024;

    for (int c8 = 0; c8 < 8; c8++) {
        int ch = zc + c8;
#pragma unroll
        for (int i = 0; i < 16; i++) {
            int p = tid + i * 256;
            int row = p >> 5;
            int col = (p & 31) << 1;
            float2 av = *(const float2*)(abase + (size_t)row * 1024 + ch * 64 + col);
            float ahx = __bfloat162float(__float2bfloat16(av.x));
            float ahy = __bfloat162float(__float2bfloat16(av.y));
            int off = row * SST + col;
            *(unsigned*)(Ahh + off) = pack_bf16x2(ahx, ahy);
            *(unsigned*)(All + off) = pack_bf16x2(av.x - ahx, av.y - ahy);
        }
#pragma unroll
        for (int i = 0; i < 8; i++) {
            int p = tid + i * 256;
            int row = p >> 5;
            int col = (p & 31) << 1;
            float2 bv = *(const float2*)(bbase + (size_t)row * 1024 + ch * 64 + col);
            float bhx = __bfloat162float(__float2bfloat16(bv.x));
            float bhy = __bfloat162float(__float2bfloat16(bv.y));
            int off = row * SST + col;
            *(unsigned*)(Bhh + off) = pack_bf16x2(bhx, bhy);
            *(unsigned*)(Bll + off) = pack_bf16x2(bv.x - bhx, bv.y - bhy);
        }
        __syncthreads();

#pragma unroll
        for (int k0 = 0; k0 < 64; k0 += 16) {
            unsigned ah[4], al[4], bb[8][2];
            int r0 = (wm + lr) * SST + k0 + lc;
            int r1 = (wm + lr + 8) * SST + k0 + lc;
            ah[0] = *(const unsigned*)(Ahh + r0);
            ah[1] = *(const unsigned*)(Ahh + r1);
            ah[2] = *(const unsigned*)(Ahh + r0 + 8);
            ah[3] = *(const unsigned*)(Ahh + r1 + 8);
            al[0] = *(const unsigned*)(All + r0);
            al[1] = *(const unsigned*)(All + r1);
            al[2] = *(const unsigned*)(All + r0 + 8);
            al[3] = *(const unsigned*)(All + r1 + 8);
#pragma unroll
            for (int nt = 0; nt < 8; nt++) {
                int rn = (nt * 8 + lr) * SST + k0 + lc;
                bb[nt][0] = *(const unsigned*)(Bhh + rn);
                bb[nt][1] = *(const unsigned*)(Bhh + rn + 8);
            }
#pragma unroll
            for (int nt = 0; nt < 8; nt++) mma_bf16(d[nt], ah, bb[nt]);
#pragma unroll
            for (int nt = 0; nt < 8; nt++) mma_bf16(d[nt], al, bb[nt]);
#pragma unroll
            for (int nt = 0; nt < 8; nt++) {
                int rn = (nt * 8 + lr) * SST + k0 + lc;
                bb[nt][0] = *(const unsigned*)(Bll + rn);
                bb[nt][1] = *(const unsigned*)(Bll + rn + 8);
            }
#pragma unroll
            for (int nt = 0; nt < 8; nt++) mma_bf16(d[nt], ah, bb[nt]);
        }
        __syncthreads();
    }

    int b = bh >> 3, h = bh & 7;
    int n0 = mb + wm + lr;
    float* base = g_aoP + (size_t)blockIdx.z * (Mq * Cq);
#pragma unroll
    for (int nt = 0; nt < 8; nt++) {
        int col = h * 64 + nt * 8 + lc;
        float2 o0 = {d[nt][0], d[nt][1]};
        float2 o1 = {d[nt][2], d[nt][3]};
        *(float2*)(base + (size_t)(b * 1024 + n0) * 512 + col) = o0;
        *(float2*)(base + (size_t)(b * 1024 + n0 + 8) * 512 + col) = o1;
    }
}

// ---------------------------------------------------------------------------
// Kernel 5: proj GEMM via tensor cores (mma.sync bf16x3), K-SPLIT 2.
// A = sum of 2 g_aoP partials [4096,512]; B = Wproj[512,512] staged transposed.
// Block (bx, by, z): 128x128 tile over K half [z*256, z*256+256) -> g_ypP[z].
// Grid (4, 32, 2) = 256 blocks.
// ---------------------------------------------------------------------------
__global__ __launch_bounds__(256) void k_proj(const float* __restrict__ Bm) {
    extern __shared__ char smc[];
    unsigned short* Ah = (unsigned short*)smc;      // [128][SST]
    unsigned short* Al = Ah + 128 * SST;
    unsigned short* Bh = Al + 128 * SST;            // [128][SST] (n-major)
    unsigned short* Bl = Bh + 128 * SST;

    const int Nn = 512;
    const int P = Mq * Cq;
    int bx = blockIdx.x, by = blockIdx.y, bz = blockIdx.z;
    int tid = threadIdx.x;
    int w = tid >> 5, lane = tid & 31;
    int wm = (w >> 1) * 32;
    int wn = (w & 1) * 64;
    int lr = lane >> 2;
    int lc = (lane & 3) << 1;

    float d[2][8][4];
#pragma unroll
    for (int mt = 0; mt < 2; mt++)
#pragma unroll
        for (int nt = 0; nt < 8; nt++)
#pragma unroll
            for (int j = 0; j < 4; j++) d[mt][nt][j] = 0.f;

    for (int c4 = 0; c4 < 4; c4++) {
        int ch = bz * 4 + c4;
        // stage A: (aoP0 + aoP1) rows [by*128,+128) x k [ch*64,+64)
#pragma unroll
        for (int i = 0; i < 16; i++) {
            int p = tid + i * 256;
            int row = p >> 5;
            int col = (p & 31) << 1;
            const float* ap = g_aoP + (size_t)(by * 128 + row) * 512 + ch * 64 + col;
            float2 a0 = *(const float2*)(ap);
            float2 a1 = *(const float2*)(ap + P);
            float vx = a0.x + a1.x;
            float vy = a0.y + a1.y;
            float ahx = __bfloat162float(__float2bfloat16(vx));
            float ahy = __bfloat162float(__float2bfloat16(vy));
            int off = row * SST + col;
            *(unsigned*)(Ah + off) = pack_bf16x2(ahx, ahy);
            *(unsigned*)(Al + off) = pack_bf16x2(vx - ahx, vy - ahy);
        }
        // stage B transposed: Wproj[k][n] -> Bh/Bl[n][k]
#pragma unroll
        for (int i = 0; i < 16; i++) {
            int p = tid + i * 256;
            int kk = p >> 6;
            int nn = (p & 63) << 1;
            float2 bv = *(const float2*)(Bm + (size_t)(ch * 64 + kk) * Nn + bx * 128 + nn);
            float bhx = __bfloat162float(__float2bfloat16(bv.x));
            float bhy = __bfloat162float(__float2bfloat16(bv.y));
            Bh[nn * SST + kk]       = __bfloat16_as_ushort(__float2bfloat16(bhx));
            Bh[(nn + 1) * SST + kk] = __bfloat16_as_ushort(__float2bfloat16(bhy));
            Bl[nn * SST + kk]       = __bfloat16_as_ushort(__float2bfloat16(bv.x - bhx));
            Bl[(nn + 1) * SST + kk] = __bfloat16_as_ushort(__float2bfloat16(bv.y - bhy));
        }
        __syncthreads();

#pragma unroll
        for (int k0 = 0; k0 < 64; k0 += 16) {
            unsigned ah[2][4], al[2][4], bb[8][2];
#pragma unroll
            for (int mt = 0; mt < 2; mt++) {
                int r0 = (wm + mt * 16 + lr) * SST + k0 + lc;
                int r1 = (wm + mt * 16 + lr + 8) * SST + k0 + lc;
                ah[mt][0] = *(const unsigned*)(Ah + r0);
                ah[mt][1] = *(const unsigned*)(Ah + r1);
                ah[mt][2] = *(const unsigned*)(Ah + r0 + 8);
                ah[mt][3] = *(const unsigned*)(Ah + r1 + 8);
                al[mt][0] = *(const unsigned*)(Al + r0);
                al[mt][1] = *(const unsigned*)(Al + r1);
                al[mt][2] = *(const unsigned*)(Al + r0 + 8);
                al[mt][3] = *(const unsigned*)(Al + r1 + 8);
            }
#pragma unroll
            for (int nt = 0; nt < 8; nt++) {
                int rn = (wn + nt * 8 + lr) * SST + k0 + lc;
                bb[nt][0] = *(const unsigned*)(Bh + rn);
                bb[nt][1] = *(const unsigned*)(Bh + rn + 8);
            }
#pragma unroll
            for (int mt = 0; mt < 2; mt++)
#pragma unroll
                for (int nt = 0; nt < 8; nt++) mma_bf16(d[mt][nt], ah[mt], bb[nt]);
#pragma unroll
            for (int mt = 0; mt < 2; mt++)
#pragma unroll
                for (int nt = 0; nt < 8; nt++) mma_bf16(d[mt][nt], al[mt], bb[nt]);
#pragma unroll
            for (int nt = 0; nt < 8; nt++) {
                int rn = (wn + nt * 8 + lr) * SST + k0 + lc;
                bb[nt][0] = *(const unsigned*)(Bl + rn);
                bb[nt][1] = *(const unsigned*)(Bl + rn + 8);
            }
#pragma unroll
            for (int mt = 0; mt < 2; mt++)
#pragma unroll
                for (int nt = 0; nt < 8; nt++) mma_bf16(d[mt][nt], ah[mt], bb[nt]);
        }
        __syncthreads();
    }

    float* yp = g_ypP + (size_t)bz * P;
#pragma unroll
    for (int mt = 0; mt < 2; mt++) {
#pragma unroll
        for (int rr = 0; rr < 2; rr++) {
            int r = by * 128 + wm + mt * 16 + lr + rr * 8;
#pragma unroll
            for (int nt = 0; nt < 8; nt++) {
                int c = bx * 128 + wn + nt * 8 + lc;
                float2 o = {d[mt][nt][rr * 2], d[mt][nt][rr * 2 + 1]};
                *(float2*)(yp + (size_t)r * 512 + c) = o;
            }
        }
    }
}

// ---------------------------------------------------------------------------
// Kernel 6: LayerNorm. y_pre = sum of 2 proj partials + bias + x, then LN.
// ---------------------------------------------------------------------------
__global__ __launch_bounds__(128) void k_ln(const float* __restrict__ gamma,
                                            const float* __restrict__ beta,
                                            const float* __restrict__ bias,
                                            const float* __restrict__ x,
                                            float* __restrict__ y) {
    const int P = Mq * Cq;
    __shared__ float s1[4], s2[4];
    int row = blockIdx.x;
    int tid = threadIdx.x;
    int c = tid * 4;
    const float* p = g_ypP + (size_t)row * 512 + c;
    float4 v0 = *(const float4*)(p);
    float4 v1 = *(const float4*)(p + P);
    float4 bb = *(const float4*)(bias + c);
    float4 xx = *(const float4*)(x + (size_t)row * 512 + c);
    float4 v;
    v.x = v0.x + v1.x + bb.x + xx.x;
    v.y = v0.y + v1.y + bb.y + xx.y;
    v.z = v0.z + v1.z + bb.z + xx.z;
    v.w = v0.w + v1.w + bb.w + xx.w;

    float s = v.x + v.y + v.z + v.w;
    float ss = v.x * v.x + v.y * v.y + v.z * v.z + v.w * v.w;
#pragma unroll
    for (int o = 16; o; o >>= 1) {
        s += __shfl_xor_sync(0xffffffffu, s, o);
        ss += __shfl_xor_sync(0xffffffffu, ss, o);
    }
    int wid = tid >> 5, lane = tid & 31;
    if (lane == 0) { s1[wid] = s; s2[wid] = ss; }
    __syncthreads();
    if (tid == 0) {
        s1[0] = s1[0] + s1[1] + s1[2] + s1[3];
        s2[0] = s2[0] + s2[1] + s2[2] + s2[3];
    }
    __syncthreads();
    float mu = s1[0] * (1.f / 512.f);
    float var = s2[0] * (1.f / 512.f) - mu * mu;
    float rstd = rsqrtf(var + LN_EPSq);

    float4 g = *(const float4*)(gamma + c);
    float4 be = *(const float4*)(beta + c);
    float4 o;
    o.x = (v.x - mu) * rstd * g.x + be.x;
    o.y = (v.y - mu) * rstd * g.y + be.y;
    o.z = (v.z - mu) * rstd * g.z + be.z;
    o.w = (v.w - mu) * rstd * g.w + be.w;
    *(float4*)(y + (size_t)row * 512 + c) = o;
}

// ---------------------------------------------------------------------------
extern "C" void kernel_launch(void* const* d_in, const int* in_sizes, int n_in,
                              void* d_out, int out_size) {
    (void)in_sizes; (void)n_in; (void)out_size;
    const float* x     = (const float*)d_in[0];
    const float* Wqkv  = (const float*)d_in[1];
    const float* bqkv  = (const float*)d_in[2];
    const float* ow    = (const float*)d_in[3];
    const float* Wproj = (const float*)d_in[4];
    const float* bproj = (const float*)d_in[5];
    const float* gamma = (const float*)d_in[6];
    const float* beta  = (const float*)d_in[7];

    float* out      = (float*)d_out;
    float* y_out    = out;                         // [4,1024,512]
    float* attn_out = out + (size_t)Bq * Nq * Cq;  // [4,8,1024,1024]

    int big_smem = 4 * 128 * SST * 2;                     // 73728 B
    int av_smem  = (2 * 128 * SST + 2 * 64 * SST) * 2;    // 55296 B
    cudaFuncSetAttribute(k_qkv, cudaFuncAttributeMaxDynamicSharedMemorySize,
                         big_smem);
    cudaFuncSetAttribute(k_scores, cudaFuncAttributeMaxDynamicSharedMemorySize,
                         big_smem);
    cudaFuncSetAttribute(k_av, cudaFuncAttributeMaxDynamicSharedMemorySize,
                         av_smem);
    cudaFuncSetAttribute(k_proj, cudaFuncAttributeMaxDynamicSharedMemorySize,
                         big_smem);

    k_qkv    <<<dim3(12, 32), 256, big_smem>>>(x, Wqkv, bqkv);
    k_scores <<<dim3(8, 8, 32), 256, big_smem>>>(ow, attn_out);
    k_softmax<<<32768, 256>>>(attn_out);
    k_av     <<<dim3(8, 32, 2), 256, av_smem>>>(attn_out);
    k_proj   <<<dim3(4, 32, 2), 256, big_smem>>>(Wproj);
    k_ln     <<<4096, 128>>>(gamma, beta, bproj, x, y_out);
}